// round 3
// baseline (speedup 1.0000x reference)
#include <cuda_runtime.h>
#include <math.h>

#define T 512
#define M 5
#define H 128
#define KTOP 3
#define DK 64
#define DV 64
#define DC 32
#define NELEM 6     // 5 modalities + null
#define GH 512      // 4*H

// Scratch (no allocations allowed)
__device__ float g_keys[T * NELEM * DK];
__device__ float g_vals[T * NELEM * DV];
__device__ float g_hidden[T * M * H];

// ---------------------------------------------------------------------------
// Kernel 1: modality projections (fp32). One block per t, 768 threads,
// one output per thread: o = mod*128 + half*64 + dk.
// ---------------------------------------------------------------------------
__global__ void __launch_bounds__(768) proj_kernel(
    const float* __restrict__ bert,       // [T,768]
    const int*   __restrict__ umls_idx,   // [T]
    const int*   __restrict__ pos_idx,    // [T]
    const float* __restrict__ disg,       // [T,2]
    const float* __restrict__ udisg,      // [T,2]
    const float* __restrict__ umls_table, // [500000,50]
    const float* __restrict__ pos_table,  // [50,20]
    const float* __restrict__ Wk0, const float* __restrict__ Wv0,
    const float* __restrict__ Wk1, const float* __restrict__ Wv1,
    const float* __restrict__ Wk2, const float* __restrict__ Wv2,
    const float* __restrict__ Wk3, const float* __restrict__ Wv3,
    const float* __restrict__ Wk4, const float* __restrict__ Wv4)
{
    __shared__ float x[768 + 50 + 20 + 2 + 2];   // 842
    const int t = blockIdx.x;
    const int tid = threadIdx.x;

    x[tid] = bert[t * 768 + tid];
    {
        const long ui = (long)umls_idx[t];
        const int  pi = pos_idx[t];
        if (tid < 50) x[768 + tid] = umls_table[ui * 50 + tid];
        else if (tid < 70) x[818 + (tid - 50)] = pos_table[pi * 20 + (tid - 50)];
        else if (tid < 72) x[838 + (tid - 70)] = disg[t * 2 + (tid - 70)];
        else if (tid < 74) x[840 + (tid - 72)] = udisg[t * 2 + (tid - 72)];
    }
    __syncthreads();

    const float* Wks[5] = {Wk0, Wk1, Wk2, Wk3, Wk4};
    const float* Wvs[5] = {Wv0, Wv1, Wv2, Wv3, Wv4};
    const int dims[5] = {768, 50, 20, 2, 2};
    const int offs[5] = {0, 768, 818, 838, 840};

    const int o    = tid;
    const int mod  = o >> 7;               // 0..5
    const int half = (o >> 6) & 1;         // 0=key, 1=val
    const int dk   = o & 63;
    float acc = 0.f;
    if (mod < 5) {
        const float* W  = half ? Wvs[mod] : Wks[mod];
        const float* xx = x + offs[mod];
        const int d = dims[mod];
        for (int i = 0; i < d; i++) acc += xx[i] * W[i * 64 + dk];
    }
    if (half == 0) g_keys[t * NELEM * DK + mod * DK + dk] = acc;
    else           g_vals[t * NELEM * DV + mod * DV + dk] = acc;
}

// ---------------------------------------------------------------------------
// Kernel 2: sequential MI-RIM scan in FP64. Single block, 640 threads.
// One thread per (m, hh); gates computed inline (no gate buffer).
// ---------------------------------------------------------------------------
__global__ void __launch_bounds__(640, 1) scan_kernel(
    const float* __restrict__ Wq,    // [M,H,DK]
    const float* __restrict__ Wih,   // [M,DV,4H]
    const float* __restrict__ Whh,   // [M,H,4H]
    const float* __restrict__ blstm, // [M,4H]
    const float* __restrict__ Wqc,   // [M,H,DC]
    const float* __restrict__ Wkc,   // [M,H,DC]
    const float* __restrict__ Wvc)   // [M,H,H]
{
    __shared__ double sh[M * H], sc[M * H], sh1[M * H];
    __shared__ float  skt[NELEM * DK], svt[NELEM * DV];
    __shared__ double sq[M * DK];
    __shared__ double sattn[M * 8];
    __shared__ double sinp[M * DV];
    __shared__ double sqc[M * DC], skc[M * DC], svc[M * H];
    __shared__ double scat[M * 8];
    __shared__ double smask[M];

    const int tid = threadIdx.x;
    const int m  = tid >> 7;        // 0..4
    const int hh = tid & 127;       // 0..127
    sh[tid] = 0.0; sc[tid] = 0.0;
    __syncthreads();

    for (int t = 0; t < T; ++t) {
        // --- A: load this step's keys/vals ---
        if (tid < NELEM * DK) {
            skt[tid] = g_keys[t * NELEM * DK + tid];
            svt[tid] = g_vals[t * NELEM * DV + tid];
        }
        __syncthreads();

        // --- B: q[m,dk] = h[m,:] . Wq[m,:,dk] ---
        if (tid < M * DK) {
            const int qm = tid >> 6, dk = tid & 63;
            const float*  w  = Wq + (qm * H) * DK + dk;
            const double* hp = sh + qm * H;
            double acc = 0.0;
            for (int i = 0; i < H; i++) acc += hp[i] * (double)w[i * DK];
            sq[tid] = acc;
        }
        __syncthreads();

        // --- C: attention logits over 6 elems ---
        if (tid < M * NELEM) {
            const int am = tid / NELEM, j = tid - am * NELEM;
            const double* qq = sq + am * DK;
            const float*  kk = skt + j * DK;
            double acc = 0.0;
            for (int i = 0; i < DK; i++) acc += qq[i] * (double)kk[i];
            sattn[am * 8 + j] = acc * 0.125;
        }
        __syncthreads();

        // --- D: softmax per module ---
        if (tid < M) {
            const int sm = tid;
            double mx = sattn[sm * 8];
            for (int j = 1; j < NELEM; j++) mx = fmax(mx, sattn[sm * 8 + j]);
            double s = 0.0;
            for (int j = 0; j < NELEM; j++) {
                double e = exp(sattn[sm * 8 + j] - mx);
                sattn[sm * 8 + j] = e; s += e;
            }
            const double inv = 1.0 / s;
            for (int j = 0; j < NELEM; j++) sattn[sm * 8 + j] *= inv;
        }
        __syncthreads();

        // --- D2: stable top-3 of smallest null attention ---
        if (tid == 0) {
            double nl[M]; bool used[M];
            for (int i = 0; i < M; i++) {
                nl[i] = sattn[i * 8 + (NELEM - 1)];
                used[i] = false;
                smask[i] = 0.0;
            }
            for (int r = 0; r < KTOP; r++) {
                int best = -1; double bv = 0.0;
                for (int i = 0; i < M; i++)
                    if (!used[i] && (best < 0 || nl[i] < bv)) { bv = nl[i]; best = i; }
                used[best] = true;
                smask[best] = 1.0;
            }
        }
        __syncthreads();

        // --- E: inp[m,dv] = attn[m,:] @ vals ---
        if (tid < M * DV) {
            const int em = tid >> 6, dv = tid & 63;
            const double* a = sattn + em * 8;
            double acc = 0.0;
            #pragma unroll
            for (int j = 0; j < NELEM; j++) acc += a[j] * (double)svt[j * DV + dv];
            sinp[tid] = acc;
        }
        __syncthreads();

        // --- F+G: gates for this (m,hh) + LSTM update + masked blend ---
        {
            const float* wih = Wih + m * DV * GH;   // [64][512]
            const float* whh = Whh + m * H  * GH;   // [128][512]
            const float* bb  = blstm + m * GH;
            double gi = (double)bb[hh];
            double gf = (double)bb[H   + hh];
            double gg = (double)bb[2*H + hh];
            double go = (double)bb[3*H + hh];
            const double* inp = sinp + m * DV;
            for (int v = 0; v < DV; v++) {
                const double s = inp[v];
                const float* wr = wih + v * GH;
                gi += s * (double)wr[hh];
                gf += s * (double)wr[H   + hh];
                gg += s * (double)wr[2*H + hh];
                go += s * (double)wr[3*H + hh];
            }
            const double* hp = sh + m * H;
            for (int v = 0; v < H; v++) {
                const double s = hp[v];
                const float* wr = whh + v * GH;
                gi += s * (double)wr[hh];
                gf += s * (double)wr[H   + hh];
                gg += s * (double)wr[2*H + hh];
                go += s * (double)wr[3*H + hh];
            }
            const double ig = 1.0 / (1.0 + exp(-gi));
            const double fg = 1.0 / (1.0 + exp(-gf));
            const double gt = tanh(gg);
            const double og = 1.0 / (1.0 + exp(-go));
            const double cn = fg * sc[tid] + ig * gt;
            const double hn = og * tanh(cn);
            const double mk = smask[m];
            sh1[tid] = mk * hn + (1.0 - mk) * sh[tid];
            sc[tid]  = mk * cn + (1.0 - mk) * sc[tid];
        }
        __syncthreads();

        // --- H1: qc/kc projections ---
        if (tid < M * DC) {
            const int pm = tid >> 5, dc = tid & 31;
            const float*  w  = Wqc + pm * H * DC + dc;
            const double* hp = sh1 + pm * H;
            double acc = 0.0;
            for (int i = 0; i < H; i++) acc += hp[i] * (double)w[i * DC];
            sqc[tid] = acc;
        } else if (tid < 2 * M * DC) {
            const int o2 = tid - M * DC;
            const int pm = o2 >> 5, dc = o2 & 31;
            const float*  w  = Wkc + pm * H * DC + dc;
            const double* hp = sh1 + pm * H;
            double acc = 0.0;
            for (int i = 0; i < H; i++) acc += hp[i] * (double)w[i * DC];
            skc[o2] = acc;
        }
        __syncthreads();

        // --- H2: vc projection ---
        {
            const float*  w  = Wvc + m * H * H + hh;
            const double* hp = sh1 + m * H;
            double acc = 0.0;
            for (int i = 0; i < H; i++) acc += hp[i] * (double)w[i * H];
            svc[tid] = acc;
        }
        __syncthreads();

        // --- I: cattn logits [M,M] ---
        if (tid < M * M) {
            const int im = tid / M, j = tid - im * M;
            const double* a = sqc + im * DC;
            const double* b = skc + j * DC;
            double acc = 0.0;
            for (int i = 0; i < DC; i++) acc += a[i] * b[i];
            scat[im * 8 + j] = acc * 0.17677669529663688;  // 1/sqrt(32)
        }
        __syncthreads();

        // --- I2: softmax over modules ---
        if (tid < M) {
            const int sm = tid;
            double mx = scat[sm * 8];
            for (int j = 1; j < M; j++) mx = fmax(mx, scat[sm * 8 + j]);
            double s = 0.0;
            for (int j = 0; j < M; j++) {
                double e = exp(scat[sm * 8 + j] - mx);
                scat[sm * 8 + j] = e; s += e;
            }
            const double inv = 1.0 / s;
            for (int j = 0; j < M; j++) scat[sm * 8 + j] *= inv;
        }
        __syncthreads();

        // --- J: h2 = h1 + mask * (cattn @ vc); emit hidden, carry h ---
        {
            double s = 0.0;
            #pragma unroll
            for (int j = 0; j < M; j++) s += scat[m * 8 + j] * svc[j * H + hh];
            const double h2 = sh1[tid] + smask[m] * s;
            sh[tid] = h2;
            g_hidden[t * (M * H) + tid] = (float)h2;
        }
        __syncthreads();
    }
}

// ---------------------------------------------------------------------------
// Kernel 3: logits = hidden @ Wcls + bcls. One warp per (t, class).
// ---------------------------------------------------------------------------
__global__ void cls_kernel(const float* __restrict__ Wcls,
                           const float* __restrict__ bcls,
                           float* __restrict__ out)
{
    const int warp = (blockIdx.x * blockDim.x + threadIdx.x) >> 5;
    const int lane = threadIdx.x & 31;
    if (warp >= T * 2) return;
    const int t = warp >> 1, c = warp & 1;
    const float* h = g_hidden + t * (M * H);
    float acc = 0.f;
    for (int i = lane; i < M * H; i += 32) acc += h[i] * Wcls[i * 2 + c];
    #pragma unroll
    for (int off = 16; off; off >>= 1) acc += __shfl_down_sync(0xffffffffu, acc, off);
    if (lane == 0) out[t * 2 + c] = acc + bcls[c];
}

// ---------------------------------------------------------------------------
extern "C" void kernel_launch(void* const* d_in, const int* in_sizes, int n_in,
                              void* d_out, int out_size)
{
    const float* bert  = (const float*)d_in[0];
    const int*   ui    = (const int*)  d_in[1];
    const int*   pi    = (const int*)  d_in[2];
    const float* disg  = (const float*)d_in[3];
    const float* udisg = (const float*)d_in[4];
    const float* utab  = (const float*)d_in[5];
    const float* ptab  = (const float*)d_in[6];
    const float* Wk0 = (const float*)d_in[7],  *Wv0 = (const float*)d_in[8];
    const float* Wk1 = (const float*)d_in[9],  *Wv1 = (const float*)d_in[10];
    const float* Wk2 = (const float*)d_in[11], *Wv2 = (const float*)d_in[12];
    const float* Wk3 = (const float*)d_in[13], *Wv3 = (const float*)d_in[14];
    const float* Wk4 = (const float*)d_in[15], *Wv4 = (const float*)d_in[16];
    const float* Wq    = (const float*)d_in[17];
    const float* Wih   = (const float*)d_in[18];
    const float* Whh   = (const float*)d_in[19];
    const float* blstm = (const float*)d_in[20];
    const float* Wqc   = (const float*)d_in[21];
    const float* Wkc   = (const float*)d_in[22];
    const float* Wvc   = (const float*)d_in[23];
    const float* Wcls  = (const float*)d_in[24];
    const float* bcls  = (const float*)d_in[25];

    proj_kernel<<<T, 768>>>(bert, ui, pi, disg, udisg, utab, ptab,
                            Wk0, Wv0, Wk1, Wv1, Wk2, Wv2, Wk3, Wv3, Wk4, Wv4);
    scan_kernel<<<1, 640>>>(Wq, Wih, Whh, blstm, Wqc, Wkc, Wvc);
    cls_kernel<<<32, 1024>>>(Wcls, bcls, (float*)d_out);
}

// round 4
// speedup vs baseline: 6.9843x; 6.9843x over previous
#include <cuda_runtime.h>
#include <math.h>

#define T 512
#define M 5
#define H 128
#define KTOP 3
#define DK 64
#define DV 64
#define DC 32
#define NELEM 6     // 5 modalities + null
#define GH 512      // 4*H

// Scratch (no allocations allowed)
__device__ float g_keys[T * NELEM * DK];
__device__ float g_vals[T * NELEM * DV];
__device__ float g_hidden[T * M * H];

// ===========================================================================
// Double-float (DF) primitives — all fp32 pipe, effective precision ~1e-14.
// ===========================================================================
struct DF { float h, l; };

__device__ __forceinline__ DF qts(float a, float b) {           // |a| >= |b|
    float s = a + b; float e = b - (s - a); return {s, e};
}
__device__ __forceinline__ DF tsum(float a, float b) {          // Knuth 2Sum
    float s = a + b; float bb = s - a;
    float e = (a - (s - bb)) + (b - bb);
    return {s, e};
}
__device__ __forceinline__ DF tprod(float a, float b) {         // 2Prod via FMA
    float p = a * b; float e = fmaf(a, b, -p); return {p, e};
}
__device__ __forceinline__ DF df_add(DF a, DF b) {
    DF s = tsum(a.h, b.h);
    return qts(s.h, s.l + (a.l + b.l));
}
__device__ __forceinline__ DF df_add_f(DF a, float b) {
    DF s = tsum(a.h, b);
    return qts(s.h, s.l + a.l);
}
__device__ __forceinline__ DF df_sub(DF a, DF b) { return df_add(a, {-b.h, -b.l}); }
__device__ __forceinline__ DF df_mul(DF a, DF b) {
    DF p = tprod(a.h, b.h);
    float l = p.l + (a.h * b.l + a.l * b.h);
    return qts(p.h, l);
}
__device__ __forceinline__ DF df_recip(DF d) {
    float y0 = __frcp_rn(d.h);
    DF p = tprod(d.h, y0);
    float e = (1.0f - p.h) - p.l;
    e = fmaf(-d.l, y0, e);
    return qts(y0, y0 * e);
}
__device__ __forceinline__ bool df_lt(DF a, DF b) {
    return (a.h < b.h) || (a.h == b.h && a.l < b.l);
}

// Compensated accumulate: (s,c) += (xh+xl) * w   (w plain float)
__device__ __forceinline__ void cacc(float& s, float& c, float xh, float xl, float w) {
    float p = xh * w;
    float e = fmaf(xh, w, -p);
    e = fmaf(xl, w, e);
    float t = s + p;
    float bb = t - s;
    c += ((s - (t - bb)) + (p - bb)) + e;
    s = t;
}
// Compensated accumulate: (s,c) += a * b   (both DF)
__device__ __forceinline__ void cacc_df(float& s, float& c, DF a, DF b) {
    float p = a.h * b.h;
    float e = fmaf(a.h, b.h, -p);
    e = fmaf(a.h, b.l, e);
    e = fmaf(a.l, b.h, e);
    float t = s + p;
    float bb = t - s;
    c += ((s - (t - bb)) + (p - bb)) + e;
    s = t;
}

// exp(x) for DF x, |x| clamped to 30; rel err ~1e-11.
__device__ __forceinline__ DF df_exp(DF x) {
    if (x.h > 30.f)  { x.h = 30.f;  x.l = 0.f; }
    if (x.h < -30.f) { x.h = -30.f; x.l = 0.f; }
    const float kf = rintf(x.h * 1.4426950408889634f);
    // range reduce: ln2_hi has 14-bit mantissa -> kf*ln2_hi exact; Sterbenz sub exact
    const float th = fmaf(-kf, 0.693145751953125f, x.h);
    const float tl = fmaf(-kf, 1.4286068203094172e-6f, x.l);
    // tail poly (plain fp32): B = 1/24 + th/120 + ... + th^5/362880
    float B = 2.7557319e-6f;
    B = fmaf(B, th, 2.4801587e-5f);
    B = fmaf(B, th, 1.9841270e-4f);
    B = fmaf(B, th, 1.3888889e-3f);
    B = fmaf(B, th, 8.3333333e-3f);
    B = fmaf(B, th, 4.1666667e-2f);
    DF t2 = tprod(th, th);
    DF t3 = tprod(t2.h, th);
    t3.l = fmaf(t2.l, th, t3.l);
    // t3/6 in DF (1/6 = c6h + c6l)
    DF q = tprod(t3.h, 0.16666667f);
    q.l = fmaf(t3.h, -4.9670537e-9f, q.l);
    q.l = fmaf(t3.l, 0.16666667f, q.l);
    const float f4 = t2.h * t2.h * B;
    DF S = qts(1.0f, th);
    S = df_add(S, {t2.h * 0.5f, t2.l * 0.5f});
    S = df_add(S, q);
    S.l += f4;
    S.l = fmaf(S.h, tl, S.l);        // * (1 + tl)
    S = qts(S.h, S.l);
    const float sc = __int_as_float(((int)kf + 127) << 23);   // exact 2^k
    S.h *= sc; S.l *= sc;
    return S;
}
__device__ __forceinline__ DF df_sigmoid(DF x) {
    DF E = df_exp({-x.h, -x.l});
    return df_recip(df_add_f(E, 1.0f));
}
__device__ __forceinline__ DF df_tanh(DF x) {
    const float sgn = (x.h < 0.f) ? -1.f : 1.f;
    DF a = {sgn * x.h, sgn * x.l};
    DF E = df_exp({2.f * a.h, 2.f * a.l});
    DF r = df_recip(df_add_f(E, 1.0f));
    DF res = tsum(1.0f, -2.f * r.h);
    DF o = qts(res.h, res.l - 2.f * r.l);
    return {sgn * o.h, sgn * o.l};
}

// ---------------------------------------------------------------------------
// Kernel 1: modality projections (fp32) — unchanged from passing R3.
// ---------------------------------------------------------------------------
__global__ void __launch_bounds__(768) proj_kernel(
    const float* __restrict__ bert,
    const int*   __restrict__ umls_idx,
    const int*   __restrict__ pos_idx,
    const float* __restrict__ disg,
    const float* __restrict__ udisg,
    const float* __restrict__ umls_table,
    const float* __restrict__ pos_table,
    const float* __restrict__ Wk0, const float* __restrict__ Wv0,
    const float* __restrict__ Wk1, const float* __restrict__ Wv1,
    const float* __restrict__ Wk2, const float* __restrict__ Wv2,
    const float* __restrict__ Wk3, const float* __restrict__ Wv3,
    const float* __restrict__ Wk4, const float* __restrict__ Wv4)
{
    __shared__ float x[768 + 50 + 20 + 2 + 2];
    const int t = blockIdx.x;
    const int tid = threadIdx.x;

    x[tid] = bert[t * 768 + tid];
    {
        const long ui = (long)umls_idx[t];
        const int  pi = pos_idx[t];
        if (tid < 50) x[768 + tid] = umls_table[ui * 50 + tid];
        else if (tid < 70) x[818 + (tid - 50)] = pos_table[pi * 20 + (tid - 50)];
        else if (tid < 72) x[838 + (tid - 70)] = disg[t * 2 + (tid - 70)];
        else if (tid < 74) x[840 + (tid - 72)] = udisg[t * 2 + (tid - 72)];
    }
    __syncthreads();

    const float* Wks[5] = {Wk0, Wk1, Wk2, Wk3, Wk4};
    const float* Wvs[5] = {Wv0, Wv1, Wv2, Wv3, Wv4};
    const int dims[5] = {768, 50, 20, 2, 2};
    const int offs[5] = {0, 768, 818, 838, 840};

    const int o    = tid;
    const int mod  = o >> 7;
    const int half = (o >> 6) & 1;
    const int dk   = o & 63;
    float acc = 0.f;
    if (mod < 5) {
        const float* W  = half ? Wvs[mod] : Wks[mod];
        const float* xx = x + offs[mod];
        const int d = dims[mod];
        for (int i = 0; i < d; i++) acc += xx[i] * W[i * 64 + dk];
    }
    if (half == 0) g_keys[t * NELEM * DK + mod * DK + dk] = acc;
    else           g_vals[t * NELEM * DV + mod * DV + dk] = acc;
}

// ---------------------------------------------------------------------------
// Kernel 2: sequential MI-RIM scan in compensated fp32 (double-float).
// Single block, 640 threads. Thread = (m = tid>>7, hh = tid&127).
// ---------------------------------------------------------------------------
__global__ void __launch_bounds__(640, 1) scan_kernel(
    const float* __restrict__ Wq,    // [M,H,DK]
    const float* __restrict__ Wih,   // [M,DV,4H]
    const float* __restrict__ Whh,   // [M,H,4H]
    const float* __restrict__ blstm, // [M,4H]
    const float* __restrict__ Wqc,   // [M,H,DC]
    const float* __restrict__ Wkc,   // [M,H,DC]
    const float* __restrict__ Wvc)   // [M,H,H]
{
    // Persistent DF state
    __shared__ float sh_h[M * H], sh_l[M * H];
    __shared__ float sc_h[M * H], sc_l[M * H];
    __shared__ float s1_h[M * H], s1_l[M * H];
    __shared__ float sinp_h[M * DV], sinp_l[M * DV];
    __shared__ float smask[8];
    // Union arena (20 KB), phase-disjoint:
    __shared__ float XU[5120];
    // Phase A-E view:
    float* skt   = XU;           // 384
    float* svt   = XU + 384;     // 384
    float* sq_h  = XU + 768;     // 320
    float* sq_l  = XU + 1088;    // 320
    float* sat_h = XU + 1408;    // 40 (stride 8 per module)
    float* sat_l = XU + 1448;    // 40
    // Phase F-G view:
    float* sg_h  = XU;           // 2560
    float* sg_l  = XU + 2560;    // 2560
    // Phase H-J view:
    float* sqc_h = XU;           // 160
    float* sqc_l = XU + 160;
    float* skc_h = XU + 320;
    float* skc_l = XU + 480;
    float* svc_h = XU + 640;     // 640
    float* svc_l = XU + 1280;    // 640
    float* sct_h = XU + 1920;    // 40
    float* sct_l = XU + 1960;    // 40

    const int tid = threadIdx.x;
    const int m  = tid >> 7;
    const int hh = tid & 127;
    sh_h[tid] = 0.f; sh_l[tid] = 0.f;
    sc_h[tid] = 0.f; sc_l[tid] = 0.f;
    __syncthreads();

    for (int t = 0; t < T; ++t) {
        // --- A: load this step's keys/vals ---
        if (tid < NELEM * DK) {
            skt[tid] = g_keys[t * NELEM * DK + tid];
            svt[tid] = g_vals[t * NELEM * DV + tid];
        }
        __syncthreads();

        // --- B: q[m,dk] = h[m,:] . Wq[m,:,dk]  (compensated) ---
        if (tid < M * DK) {
            const int qm = tid >> 6, dk = tid & 63;
            const float* w = Wq + (qm * H) * DK + dk;
            const float* hph = sh_h + qm * H;
            const float* hpl = sh_l + qm * H;
            float s = 0.f, c = 0.f;
            #pragma unroll 4
            for (int i = 0; i < H; i++) cacc(s, c, hph[i], hpl[i], w[i * DK]);
            DF r = qts(s, c);
            sq_h[tid] = r.h; sq_l[tid] = r.l;
        }
        __syncthreads();

        // --- C: attention logits over 6 elems ---
        if (tid < M * NELEM) {
            const int am = tid / NELEM, j = tid - am * NELEM;
            const float* kk = skt + j * DK;
            const float* qh = sq_h + am * DK;
            const float* ql = sq_l + am * DK;
            float s = 0.f, c = 0.f;
            #pragma unroll 4
            for (int i = 0; i < DK; i++) cacc(s, c, qh[i], ql[i], kk[i]);
            DF r = qts(s, c);
            sat_h[am * 8 + j] = r.h * 0.125f;     // exact scale
            sat_l[am * 8 + j] = r.l * 0.125f;
        }
        __syncthreads();

        // --- D: softmax per module (DF) ---
        if (tid < M) {
            const int sm = tid;
            DF v[NELEM];
            for (int j = 0; j < NELEM; j++) v[j] = {sat_h[sm * 8 + j], sat_l[sm * 8 + j]};
            DF mx = v[0];
            for (int j = 1; j < NELEM; j++) if (df_lt(mx, v[j])) mx = v[j];
            DF sum = {0.f, 0.f};
            for (int j = 0; j < NELEM; j++) {
                v[j] = df_exp(df_sub(v[j], mx));
                sum = df_add(sum, v[j]);
            }
            DF inv = df_recip(sum);
            for (int j = 0; j < NELEM; j++) {
                DF a = df_mul(v[j], inv);
                sat_h[sm * 8 + j] = a.h; sat_l[sm * 8 + j] = a.l;
            }
        }
        __syncthreads();

        // --- D2: stable top-3 of smallest null attention ---
        if (tid == 0) {
            DF nl[M]; bool used[M];
            for (int i = 0; i < M; i++) {
                nl[i] = {sat_h[i * 8 + (NELEM - 1)], sat_l[i * 8 + (NELEM - 1)]};
                used[i] = false;
                smask[i] = 0.f;
            }
            for (int r = 0; r < KTOP; r++) {
                int best = -1; DF bv = {0.f, 0.f};
                for (int i = 0; i < M; i++)
                    if (!used[i] && (best < 0 || df_lt(nl[i], bv))) { bv = nl[i]; best = i; }
                used[best] = true;
                smask[best] = 1.f;
            }
        }
        __syncthreads();

        // --- E: inp[m,dv] = attn[m,:] @ vals ---
        if (tid < M * DV) {
            const int em = tid >> 6, dv = tid & 63;
            float s = 0.f, c = 0.f;
            #pragma unroll
            for (int j = 0; j < NELEM; j++)
                cacc(s, c, sat_h[em * 8 + j], sat_l[em * 8 + j], svt[j * DV + dv]);
            DF r = qts(s, c);
            sinp_h[tid] = r.h; sinp_l[tid] = r.l;
        }
        __syncthreads();

        // --- F: gates GEMV (dominant). Thread -> 4 consecutive gate columns. ---
        {
            const int q4 = hh;                 // 0..127
            const int gb = q4 * 4;             // column base within 512
            const float4* wih4 = (const float4*)(Wih + (m * DV) * GH + gb);
            const float4* whh4 = (const float4*)(Whh + (m * H) * GH + gb);
            const float4 b4 = *(const float4*)(blstm + m * GH + gb);
            float s0 = b4.x, s1v = b4.y, s2 = b4.z, s3 = b4.w;
            float c0 = 0.f, c1 = 0.f, c2 = 0.f, c3 = 0.f;
            const float* ih = sinp_h + m * DV;
            const float* il = sinp_l + m * DV;
            #pragma unroll 4
            for (int v = 0; v < DV; v++) {
                const float xh = ih[v], xl = il[v];
                const float4 w = wih4[v * (GH / 4)];
                cacc(s0, c0, xh, xl, w.x);
                cacc(s1v, c1, xh, xl, w.y);
                cacc(s2, c2, xh, xl, w.z);
                cacc(s3, c3, xh, xl, w.w);
            }
            const float* hph = sh_h + m * H;
            const float* hpl = sh_l + m * H;
            #pragma unroll 4
            for (int v = 0; v < H; v++) {
                const float xh = hph[v], xl = hpl[v];
                const float4 w = whh4[v * (GH / 4)];
                cacc(s0, c0, xh, xl, w.x);
                cacc(s1v, c1, xh, xl, w.y);
                cacc(s2, c2, xh, xl, w.z);
                cacc(s3, c3, xh, xl, w.w);
            }
            *(float4*)(sg_h + m * GH + gb) = {s0, s1v, s2, s3};
            *(float4*)(sg_l + m * GH + gb) = {c0, c1, c2, c3};
        }
        __syncthreads();

        // --- G: LSTM update + exact masked select ---
        {
            const float* gh = sg_h + m * GH;
            const float* gl = sg_l + m * GH;
            DF gi = qts(gh[hh],         gl[hh]);
            DF gf = qts(gh[H + hh],     gl[H + hh]);
            DF gg = qts(gh[2 * H + hh], gl[2 * H + hh]);
            DF go = qts(gh[3 * H + hh], gl[3 * H + hh]);
            DF ig = df_sigmoid(gi);
            DF fg = df_sigmoid(gf);
            DF gt = df_tanh(gg);
            DF og = df_sigmoid(go);
            DF cold = {sc_h[tid], sc_l[tid]};
            DF cn = df_add(df_mul(fg, cold), df_mul(ig, gt));
            DF hn = df_mul(og, df_tanh(cn));
            const bool on = smask[m] > 0.5f;
            DF hold = {sh_h[tid], sh_l[tid]};
            DF h1 = on ? hn : hold;
            DF c1 = on ? cn : cold;
            s1_h[tid] = h1.h; s1_l[tid] = h1.l;
            sc_h[tid] = c1.h; sc_l[tid] = c1.l;
        }
        __syncthreads();

        // --- H1: qc/kc projections ---
        if (tid < M * DC) {
            const int pm = tid >> 5, dc = tid & 31;
            const float* w = Wqc + pm * H * DC + dc;
            const float* hph = s1_h + pm * H;
            const float* hpl = s1_l + pm * H;
            float s = 0.f, c = 0.f;
            #pragma unroll 4
            for (int i = 0; i < H; i++) cacc(s, c, hph[i], hpl[i], w[i * DC]);
            DF r = qts(s, c);
            sqc_h[tid] = r.h; sqc_l[tid] = r.l;
        } else if (tid < 2 * M * DC) {
            const int o2 = tid - M * DC;
            const int pm = o2 >> 5, dc = o2 & 31;
            const float* w = Wkc + pm * H * DC + dc;
            const float* hph = s1_h + pm * H;
            const float* hpl = s1_l + pm * H;
            float s = 0.f, c = 0.f;
            #pragma unroll 4
            for (int i = 0; i < H; i++) cacc(s, c, hph[i], hpl[i], w[i * DC]);
            DF r = qts(s, c);
            skc_h[o2] = r.h; skc_l[o2] = r.l;
        }
        __syncthreads();

        // --- H2: vc projection ---
        {
            const float* w = Wvc + m * H * H + hh;
            const float* hph = s1_h + m * H;
            const float* hpl = s1_l + m * H;
            float s = 0.f, c = 0.f;
            #pragma unroll 4
            for (int i = 0; i < H; i++) cacc(s, c, hph[i], hpl[i], w[i * H]);
            DF r = qts(s, c);
            svc_h[tid] = r.h; svc_l[tid] = r.l;
        }
        __syncthreads();

        // --- I: cattn logits [M,M] (DF x DF), scale by 1/sqrt(32) in DF ---
        if (tid < M * M) {
            const int im = tid / M, j = tid - im * M;
            float s = 0.f, c = 0.f;
            #pragma unroll 4
            for (int i = 0; i < DC; i++)
                cacc_df(s, c, {sqc_h[im * DC + i], sqc_l[im * DC + i]},
                              {skc_h[j * DC + i],  skc_l[j * DC + i]});
            DF r = qts(s, c);
            // 1/sqrt(32) = float(sqrt2)/8 + residual/8 (exact decomposition)
            DF sc = df_mul(r, {0.17677669227123260f, 3.0254043e-9f});
            sct_h[im * 8 + j] = sc.h; sct_l[im * 8 + j] = sc.l;
        }
        __syncthreads();

        // --- I2: softmax over modules ---
        if (tid < M) {
            const int sm = tid;
            DF v[M];
            for (int j = 0; j < M; j++) v[j] = {sct_h[sm * 8 + j], sct_l[sm * 8 + j]};
            DF mx = v[0];
            for (int j = 1; j < M; j++) if (df_lt(mx, v[j])) mx = v[j];
            DF sum = {0.f, 0.f};
            for (int j = 0; j < M; j++) {
                v[j] = df_exp(df_sub(v[j], mx));
                sum = df_add(sum, v[j]);
            }
            DF inv = df_recip(sum);
            for (int j = 0; j < M; j++) {
                DF a = df_mul(v[j], inv);
                sct_h[sm * 8 + j] = a.h; sct_l[sm * 8 + j] = a.l;
            }
        }
        __syncthreads();

        // --- J: h2 = h1 + mask * (cattn @ vc); emit hidden, carry h ---
        {
            float s = 0.f, c = 0.f;
            #pragma unroll
            for (int j = 0; j < M; j++)
                cacc_df(s, c, {sct_h[m * 8 + j], sct_l[m * 8 + j]},
                              {svc_h[j * H + hh], svc_l[j * H + hh]});
            DF dot = qts(s, c);
            DF h1 = {s1_h[tid], s1_l[tid]};
            const bool on = smask[m] > 0.5f;
            DF h2 = on ? df_add(h1, dot) : h1;
            sh_h[tid] = h2.h; sh_l[tid] = h2.l;
            g_hidden[t * (M * H) + tid] = h2.h + h2.l;
        }
        __syncthreads();
    }
}

// ---------------------------------------------------------------------------
// Kernel 3: logits = hidden @ Wcls + bcls. One warp per (t, class).
// ---------------------------------------------------------------------------
__global__ void cls_kernel(const float* __restrict__ Wcls,
                           const float* __restrict__ bcls,
                           float* __restrict__ out)
{
    const int warp = (blockIdx.x * blockDim.x + threadIdx.x) >> 5;
    const int lane = threadIdx.x & 31;
    if (warp >= T * 2) return;
    const int t = warp >> 1, c = warp & 1;
    const float* h = g_hidden + t * (M * H);
    float acc = 0.f;
    for (int i = lane; i < M * H; i += 32) acc += h[i] * Wcls[i * 2 + c];
    #pragma unroll
    for (int off = 16; off; off >>= 1) acc += __shfl_down_sync(0xffffffffu, acc, off);
    if (lane == 0) out[t * 2 + c] = acc + bcls[c];
}

// ---------------------------------------------------------------------------
extern "C" void kernel_launch(void* const* d_in, const int* in_sizes, int n_in,
                              void* d_out, int out_size)
{
    const float* bert  = (const float*)d_in[0];
    const int*   ui    = (const int*)  d_in[1];
    const int*   pi    = (const int*)  d_in[2];
    const float* disg  = (const float*)d_in[3];
    const float* udisg = (const float*)d_in[4];
    const float* utab  = (const float*)d_in[5];
    const float* ptab  = (const float*)d_in[6];
    const float* Wk0 = (const float*)d_in[7],  *Wv0 = (const float*)d_in[8];
    const float* Wk1 = (const float*)d_in[9],  *Wv1 = (const float*)d_in[10];
    const float* Wk2 = (const float*)d_in[11], *Wv2 = (const float*)d_in[12];
    const float* Wk3 = (const float*)d_in[13], *Wv3 = (const float*)d_in[14];
    const float* Wk4 = (const float*)d_in[15], *Wv4 = (const float*)d_in[16];
    const float* Wq    = (const float*)d_in[17];
    const float* Wih   = (const float*)d_in[18];
    const float* Whh   = (const float*)d_in[19];
    const float* blstm = (const float*)d_in[20];
    const float* Wqc   = (const float*)d_in[21];
    const float* Wkc   = (const float*)d_in[22];
    const float* Wvc   = (const float*)d_in[23];
    const float* Wcls  = (const float*)d_in[24];
    const float* bcls  = (const float*)d_in[25];

    proj_kernel<<<T, 768>>>(bert, ui, pi, disg, udisg, utab, ptab,
                            Wk0, Wv0, Wk1, Wv1, Wk2, Wv2, Wk3, Wv3, Wk4, Wv4);
    scan_kernel<<<1, 640>>>(Wq, Wih, Whh, blstm, Wqc, Wkc, Wvc);
    cls_kernel<<<32, 1024>>>(Wcls, bcls, (float*)d_out);
}

// round 5
// speedup vs baseline: 14.6705x; 2.1005x over previous
#include <cuda_runtime.h>
#include <math.h>
#include <stdint.h>

#define T 512
#define M 5
#define H 128
#define KTOP 3
#define DK 64
#define DV 64
#define DC 32
#define NELEM 6
#define GH 512
#define NCTA 4      // cluster size
#define HSL 32      // hh slice per CTA

__device__ float g_keys[T * NELEM * DK];
__device__ float g_vals[T * NELEM * DV];
__device__ float g_hidden[T * M * H];

// ===========================================================================
// Double-float primitives (proven in R4)
// ===========================================================================
struct DF { float h, l; };

__device__ __forceinline__ DF qts(float a, float b) {
    float s = a + b; float e = b - (s - a); return {s, e};
}
__device__ __forceinline__ DF tsum(float a, float b) {
    float s = a + b; float bb = s - a;
    float e = (a - (s - bb)) + (b - bb);
    return {s, e};
}
__device__ __forceinline__ DF tprod(float a, float b) {
    float p = a * b; float e = fmaf(a, b, -p); return {p, e};
}
__device__ __forceinline__ DF df_add(DF a, DF b) {
    DF s = tsum(a.h, b.h);
    return qts(s.h, s.l + (a.l + b.l));
}
__device__ __forceinline__ DF df_add_f(DF a, float b) {
    DF s = tsum(a.h, b);
    return qts(s.h, s.l + a.l);
}
__device__ __forceinline__ DF df_sub(DF a, DF b) { return df_add(a, {-b.h, -b.l}); }
__device__ __forceinline__ DF df_mul(DF a, DF b) {
    DF p = tprod(a.h, b.h);
    float l = p.l + (a.h * b.l + a.l * b.h);
    return qts(p.h, l);
}
__device__ __forceinline__ DF df_recip(DF d) {
    float y0 = __frcp_rn(d.h);
    DF p = tprod(d.h, y0);
    float e = (1.0f - p.h) - p.l;
    e = fmaf(-d.l, y0, e);
    return qts(y0, y0 * e);
}
__device__ __forceinline__ bool df_lt(DF a, DF b) {
    return (a.h < b.h) || (a.h == b.h && a.l < b.l);
}
__device__ __forceinline__ void cacc(float& s, float& c, float xh, float xl, float w) {
    float p = xh * w;
    float e = fmaf(xh, w, -p);
    e = fmaf(xl, w, e);
    float t = s + p;
    float bb = t - s;
    c += ((s - (t - bb)) + (p - bb)) + e;
    s = t;
}
__device__ __forceinline__ void cacc_df(float& s, float& c, DF a, DF b) {
    float p = a.h * b.h;
    float e = fmaf(a.h, b.h, -p);
    e = fmaf(a.h, b.l, e);
    e = fmaf(a.l, b.h, e);
    float t = s + p;
    float bb = t - s;
    c += ((s - (t - bb)) + (p - bb)) + e;
    s = t;
}
__device__ __forceinline__ DF df_exp(DF x) {
    if (x.h > 30.f)  { x.h = 30.f;  x.l = 0.f; }
    if (x.h < -30.f) { x.h = -30.f; x.l = 0.f; }
    const float kf = rintf(x.h * 1.4426950408889634f);
    const float th = fmaf(-kf, 0.693145751953125f, x.h);
    const float tl = fmaf(-kf, 1.4286068203094172e-6f, x.l);
    float B = 2.7557319e-6f;
    B = fmaf(B, th, 2.4801587e-5f);
    B = fmaf(B, th, 1.9841270e-4f);
    B = fmaf(B, th, 1.3888889e-3f);
    B = fmaf(B, th, 8.3333333e-3f);
    B = fmaf(B, th, 4.1666667e-2f);
    DF t2 = tprod(th, th);
    DF t3 = tprod(t2.h, th);
    t3.l = fmaf(t2.l, th, t3.l);
    DF q = tprod(t3.h, 0.16666667f);
    q.l = fmaf(t3.h, -4.9670537e-9f, q.l);
    q.l = fmaf(t3.l, 0.16666667f, q.l);
    const float f4 = t2.h * t2.h * B;
    DF S = qts(1.0f, th);
    S = df_add(S, {t2.h * 0.5f, t2.l * 0.5f});
    S = df_add(S, q);
    S.l += f4;
    S.l = fmaf(S.h, tl, S.l);
    S = qts(S.h, S.l);
    const float sc = __int_as_float(((int)kf + 127) << 23);
    S.h *= sc; S.l *= sc;
    return S;
}
__device__ __forceinline__ DF df_sigmoid(DF x) {
    DF E = df_exp({-x.h, -x.l});
    return df_recip(df_add_f(E, 1.0f));
}
__device__ __forceinline__ DF df_tanh(DF x) {
    const float sgn = (x.h < 0.f) ? -1.f : 1.f;
    DF a = {sgn * x.h, sgn * x.l};
    DF E = df_exp({2.f * a.h, 2.f * a.l});
    DF r = df_recip(df_add_f(E, 1.0f));
    DF res = tsum(1.0f, -2.f * r.h);
    DF o = qts(res.h, res.l - 2.f * r.l);
    return {sgn * o.h, sgn * o.l};
}
__device__ __forceinline__ DF df_red(DF a, unsigned off) {
    float oh = __shfl_down_sync(0xffffffffu, a.h, off);
    float ol = __shfl_down_sync(0xffffffffu, a.l, off);
    return df_add(a, {oh, ol});
}

// Cluster helpers
__device__ __forceinline__ uint32_t smem_u32(const void* p) {
    uint32_t a;
    asm("{ .reg .u64 t; cvta.to.shared.u64 t, %1; cvt.u32.u64 %0, t; }" : "=r"(a) : "l"(p));
    return a;
}
__device__ __forceinline__ uint32_t my_rank() {
    uint32_t r; asm("mov.u32 %0, %%cluster_ctarank;" : "=r"(r)); return r;
}
__device__ __forceinline__ void st_cluster_b64(uint32_t saddr, uint32_t rank, uint64_t v) {
    uint32_t ra;
    asm volatile("mapa.shared::cluster.u32 %0, %1, %2;" : "=r"(ra) : "r"(saddr), "r"(rank));
    asm volatile("st.shared::cluster.b64 [%0], %1;" :: "r"(ra), "l"(v) : "memory");
}
#define CLUSTER_BAR() do { \
    asm volatile("barrier.cluster.arrive.aligned;" ::: "memory"); \
    asm volatile("barrier.cluster.wait.aligned;"   ::: "memory"); } while (0)

// ---------------------------------------------------------------------------
// Kernel 1: modality projections (unchanged from passing R4)
// ---------------------------------------------------------------------------
__global__ void __launch_bounds__(768) proj_kernel(
    const float* __restrict__ bert,
    const int*   __restrict__ umls_idx,
    const int*   __restrict__ pos_idx,
    const float* __restrict__ disg,
    const float* __restrict__ udisg,
    const float* __restrict__ umls_table,
    const float* __restrict__ pos_table,
    const float* __restrict__ Wk0, const float* __restrict__ Wv0,
    const float* __restrict__ Wk1, const float* __restrict__ Wv1,
    const float* __restrict__ Wk2, const float* __restrict__ Wv2,
    const float* __restrict__ Wk3, const float* __restrict__ Wv3,
    const float* __restrict__ Wk4, const float* __restrict__ Wv4)
{
    __shared__ float x[768 + 50 + 20 + 2 + 2];
    const int t = blockIdx.x;
    const int tid = threadIdx.x;

    x[tid] = bert[t * 768 + tid];
    {
        const long ui = (long)umls_idx[t];
        const int  pi = pos_idx[t];
        if (tid < 50) x[768 + tid] = umls_table[ui * 50 + tid];
        else if (tid < 70) x[818 + (tid - 50)] = pos_table[pi * 20 + (tid - 50)];
        else if (tid < 72) x[838 + (tid - 70)] = disg[t * 2 + (tid - 70)];
        else if (tid < 74) x[840 + (tid - 72)] = udisg[t * 2 + (tid - 72)];
    }
    __syncthreads();

    const float* Wks[5] = {Wk0, Wk1, Wk2, Wk3, Wk4};
    const float* Wvs[5] = {Wv0, Wv1, Wv2, Wv3, Wv4};
    const int dims[5] = {768, 50, 20, 2, 2};
    const int offs[5] = {0, 768, 818, 838, 840};

    const int o    = tid;
    const int mod  = o >> 7;
    const int half = (o >> 6) & 1;
    const int dk   = o & 63;
    float acc = 0.f;
    if (mod < 5) {
        const float* W  = half ? Wvs[mod] : Wks[mod];
        const float* xx = x + offs[mod];
        const int d = dims[mod];
        for (int i = 0; i < d; i++) acc += xx[i] * W[i * 64 + dk];
    }
    if (half == 0) g_keys[t * NELEM * DK + mod * DK + dk] = acc;
    else           g_vals[t * NELEM * DV + mod * DV + dk] = acc;
}

// ---------------------------------------------------------------------------
// Kernel 2: MI-RIM scan, 4-CTA cluster, DF arithmetic. 640 thr/CTA.
// CTA `rank` owns hidden slice hh in [rank*32, rank*32+32) for all modules.
// ---------------------------------------------------------------------------
__global__ void __cluster_dims__(NCTA, 1, 1) __launch_bounds__(640, 1) scan_kernel(
    const float* __restrict__ Wq,    // [M,H,DK]
    const float* __restrict__ Wih,   // [M,DV,4H]
    const float* __restrict__ Whh,   // [M,H,4H]
    const float* __restrict__ blstm, // [M,4H]
    const float* __restrict__ Wqc,   // [M,H,DC]
    const float* __restrict__ Wkc,   // [M,H,DC]
    const float* __restrict__ Wvc)   // [M,H,H]
{
    __shared__ float  skt[NELEM * DK], svt[NELEM * DV];
    __shared__ float  sq_h[M * DK], sq_l[M * DK];
    __shared__ float  sat_h[M * 8], sat_l[M * 8];
    __shared__ float  sct_h[M * 8], sct_l[M * 8];
    __shared__ float  sinp_h[M * DV], sinp_l[M * DV];
    __shared__ float  sgate_h[640], sgate_l[640];      // (m,gate,hl) slots, reused in-place for nonlinearity
    __shared__ float  sqc_h[M * DC], sqc_l[M * DC];
    __shared__ float  skc_h[M * DC], skc_l[M * DC];
    __shared__ float  svc_h[M * HSL], svc_l[M * HSL];  // owned slice of vc
    __shared__ float  sc_h[M * HSL], sc_l[M * HSL];    // owned cell state
    __shared__ float2 scomm1[M * H];                   // gathered h1 (x=h, y=l)
    __shared__ float2 scomm2[M * H];                   // gathered h (carry)
    __shared__ float  smask[8];

    const int tid  = threadIdx.x;
    const uint32_t rank = my_rank();
    const int HB = rank * HSL;                          // owned global hh base
    const uint32_t a_comm1 = smem_u32(scomm1);
    const uint32_t a_comm2 = smem_u32(scomm2);

    // init: h(0) = 0, c(0) = 0
    scomm2[tid] = make_float2(0.f, 0.f);
    if (tid < M * HSL) { sc_h[tid] = 0.f; sc_l[tid] = 0.f; }
    __syncthreads();
    CLUSTER_BAR();

    for (int t = 0; t < T; ++t) {
        // ---- interval 1: A (keys/vals) + B (q partial dots, K-split-2) ----
        if (tid < NELEM * DK) {
            skt[tid] = g_keys[t * NELEM * DK + tid];
            svt[tid] = g_vals[t * NELEM * DV + tid];
        }
        {
            const int out = tid >> 1;            // 0..319 = (m,dk)
            const int half = tid & 1;
            const int qm = out >> 6, dk = out & 63;
            const float* w = Wq + qm * H * DK + dk;
            const float2* hc = scomm2 + qm * H;
            float s = 0.f, c = 0.f;
            const int v0 = half * 64;
            #pragma unroll 4
            for (int i = v0; i < v0 + 64; i++) {
                const float2 hv = hc[i];
                cacc(s, c, hv.x, hv.y, w[i * DK]);
            }
            DF r = qts(s, c);
            DF o = df_red(r, 1);                 // lane even: half0 + half1
            if (half == 0) { sq_h[out] = o.h; sq_l[out] = o.l; }
        }
        __syncthreads();

        // ---- interval 2: C attention logits, K-split-8 ----
        {
            const int gout = tid >> 3;           // 0..79
            const int part = tid & 7;
            const int out = gout < 30 ? gout : 29;
            const int am = out / NELEM, j = out - am * NELEM;
            const float* kk = skt + j * DK;
            const float* qh = sq_h + am * DK;
            const float* ql = sq_l + am * DK;
            float s = 0.f, c = 0.f;
            const int i0 = part * 8;
            #pragma unroll
            for (int i = i0; i < i0 + 8; i++) cacc(s, c, qh[i], ql[i], kk[i]);
            DF r = qts(s, c);
            r = df_red(r, 4); r = df_red(r, 2); r = df_red(r, 1);
            if (part == 0 && gout < 30) {
                sat_h[am * 8 + j] = r.h * 0.125f;
                sat_l[am * 8 + j] = r.l * 0.125f;
            }
        }
        __syncthreads();

        // ---- interval 3: D softmax exp (parallel over 30) ----
        if (tid < M * NELEM) {
            const int sm = tid / NELEM, j = tid - sm * NELEM;
            DF v[NELEM];
            for (int k = 0; k < NELEM; k++) v[k] = {sat_h[sm * 8 + k], sat_l[sm * 8 + k]};
            DF mx = v[0];
            for (int k = 1; k < NELEM; k++) if (df_lt(mx, v[k])) mx = v[k];
            DF e = df_exp(df_sub(v[j], mx));
            sat_h[sm * 8 + j] = e.h; sat_l[sm * 8 + j] = e.l;
        }
        __syncthreads();

        // ---- interval 4: D normalize (5 threads) ----
        if (tid < M) {
            DF sum = {0.f, 0.f};
            for (int j = 0; j < NELEM; j++) sum = df_add(sum, {sat_h[tid * 8 + j], sat_l[tid * 8 + j]});
            DF inv = df_recip(sum);
            for (int j = 0; j < NELEM; j++) {
                DF a = df_mul({sat_h[tid * 8 + j], sat_l[tid * 8 + j]}, inv);
                sat_h[tid * 8 + j] = a.h; sat_l[tid * 8 + j] = a.l;
            }
        }
        __syncthreads();

        // ---- interval 5: top-3 mask (tid 0) + E inp (tid<320) ----
        if (tid == 0) {
            DF nl[M]; bool used[M];
            for (int i = 0; i < M; i++) {
                nl[i] = {sat_h[i * 8 + (NELEM - 1)], sat_l[i * 8 + (NELEM - 1)]};
                used[i] = false; smask[i] = 0.f;
            }
            for (int r = 0; r < KTOP; r++) {
                int best = -1; DF bv = {0.f, 0.f};
                for (int i = 0; i < M; i++)
                    if (!used[i] && (best < 0 || df_lt(nl[i], bv))) { bv = nl[i]; best = i; }
                used[best] = true; smask[best] = 1.f;
            }
        }
        if (tid < M * DV) {
            const int em = tid >> 6, dv = tid & 63;
            float s = 0.f, c = 0.f;
            #pragma unroll
            for (int j = 0; j < NELEM; j++)
                cacc(s, c, sat_h[em * 8 + j], sat_l[em * 8 + j], svt[j * DV + dv]);
            DF r = qts(s, c);
            sinp_h[tid] = r.h; sinp_l[tid] = r.l;
        }
        __syncthreads();

        // ---- interval 6: F gates (1 owned column/thread) + in-place nonlinearity ----
        {
            const int m = tid >> 7;              // module
            const int r = tid & 127;             // (gate, hl)
            const int gate = r >> 5;
            const int hl = r & 31;
            const int col = gate * H + HB + hl;  // column in [0,512)
            const float* wih = Wih + m * DV * GH + col;
            const float* whh = Whh + m * H * GH + col;
            float s = blstm[m * GH + col], c = 0.f;
            const float* ih = sinp_h + m * DV;
            const float* il = sinp_l + m * DV;
            #pragma unroll 8
            for (int v = 0; v < DV; v++) cacc(s, c, ih[v], il[v], wih[v * GH]);
            const float2* hc = scomm2 + m * H;
            #pragma unroll 8
            for (int v = 0; v < H; v++) {
                const float2 hv = hc[v];
                cacc(s, c, hv.x, hv.y, whh[v * GH]);
            }
            DF g = qts(s, c);
            DF nlv = (gate == 2) ? df_tanh(g) : df_sigmoid(g);
            sgate_h[tid] = nlv.h; sgate_l[tid] = nlv.l;
        }
        __syncthreads();

        // ---- interval 7: G cell/hidden update on owned slice + broadcast h1 ----
        if (tid < M * HSL) {
            const int m = tid >> 5, hl = tid & 31;
            const int base = m * 128 + hl;
            DF ig = {sgate_h[base],      sgate_l[base]};
            DF fg = {sgate_h[base + 32], sgate_l[base + 32]};
            DF gt = {sgate_h[base + 64], sgate_l[base + 64]};
            DF og = {sgate_h[base + 96], sgate_l[base + 96]};
            DF cold = {sc_h[tid], sc_l[tid]};
            DF cn = df_add(df_mul(fg, cold), df_mul(ig, gt));
            DF hn = df_mul(og, df_tanh(cn));
            const bool on = smask[m] > 0.5f;
            const int hg = m * H + HB + hl;      // global h index
            const float2 hold = scomm2[hg];
            DF h1 = on ? hn : DF{hold.x, hold.y};
            DF c1 = on ? cn : cold;
            sc_h[tid] = c1.h; sc_l[tid] = c1.l;
            const uint64_t pk = ((uint64_t)__float_as_uint(h1.l) << 32) | __float_as_uint(h1.h);
            const uint32_t ad = a_comm1 + hg * 8;
            #pragma unroll
            for (int rk = 0; rk < NCTA; rk++) st_cluster_b64(ad, rk, pk);
        }
        CLUSTER_BAR();

        // ---- interval 8: H1 qc/kc (K-split-2) + H2 vc owned slice (K-split-4) ----
        {
            const int out = tid >> 1;            // 0..319
            const int half = tid & 1;
            const int isK = out >= 160;
            const int o2 = isK ? out - 160 : out;
            const int pm = o2 >> 5, dc = o2 & 31;
            const float* w = (isK ? Wkc : Wqc) + pm * H * DC + dc;
            const float2* hc = scomm1 + pm * H;
            float s = 0.f, c = 0.f;
            const int v0 = half * 64;
            #pragma unroll 4
            for (int i = v0; i < v0 + 64; i++) {
                const float2 hv = hc[i];
                cacc(s, c, hv.x, hv.y, w[i * DC]);
            }
            DF r = qts(s, c);
            DF o = df_red(r, 1);
            if (half == 0) {
                if (isK) { skc_h[o2] = o.h; skc_l[o2] = o.l; }
                else     { sqc_h[o2] = o.h; sqc_l[o2] = o.l; }
            }
        }
        {
            const int out = tid >> 2;            // 0..159 = (j, hl)
            const int qrt = tid & 3;
            const int j = out >> 5, hl = out & 31;
            const float* w = Wvc + j * H * H + HB + hl;
            const float2* hc = scomm1 + j * H;
            float s = 0.f, c = 0.f;
            const int i0 = qrt * 32;
            #pragma unroll 4
            for (int i = i0; i < i0 + 32; i++) {
                const float2 hv = hc[i];
                cacc(s, c, hv.x, hv.y, w[i * H]);
            }
            DF r = qts(s, c);
            r = df_red(r, 2); r = df_red(r, 1);
            if (qrt == 0) { svc_h[out] = r.h; svc_l[out] = r.l; }
        }
        __syncthreads();

        // ---- interval 9: I cattn logits (K-split-8) ----
        {
            const int gout = tid >> 3;           // 0..79
            const int part = tid & 7;
            const int out = gout < 25 ? gout : 24;
            const int im = out / M, j = out - im * M;
            float s = 0.f, c = 0.f;
            const int i0 = part * 4;
            #pragma unroll
            for (int i = i0; i < i0 + 4; i++)
                cacc_df(s, c, {sqc_h[im * DC + i], sqc_l[im * DC + i]},
                              {skc_h[j * DC + i],  skc_l[j * DC + i]});
            DF r = qts(s, c);
            r = df_red(r, 4); r = df_red(r, 2); r = df_red(r, 1);
            if (part == 0 && gout < 25) {
                DF sc = df_mul(r, {0.17677669227123260f, 3.0254043e-9f});
                sct_h[im * 8 + j] = sc.h; sct_l[im * 8 + j] = sc.l;
            }
        }
        __syncthreads();

        // ---- interval 10: I2 exp ----
        if (tid < M * M) {
            const int im = tid / M, j = tid - im * M;
            DF v[M];
            for (int k = 0; k < M; k++) v[k] = {sct_h[im * 8 + k], sct_l[im * 8 + k]};
            DF mx = v[0];
            for (int k = 1; k < M; k++) if (df_lt(mx, v[k])) mx = v[k];
            DF e = df_exp(df_sub(v[j], mx));
            sct_h[im * 8 + j] = e.h; sct_l[im * 8 + j] = e.l;
        }
        __syncthreads();

        // ---- interval 11: I2 normalize ----
        if (tid < M) {
            DF sum = {0.f, 0.f};
            for (int j = 0; j < M; j++) sum = df_add(sum, {sct_h[tid * 8 + j], sct_l[tid * 8 + j]});
            DF inv = df_recip(sum);
            for (int j = 0; j < M; j++) {
                DF a = df_mul({sct_h[tid * 8 + j], sct_l[tid * 8 + j]}, inv);
                sct_h[tid * 8 + j] = a.h; sct_l[tid * 8 + j] = a.l;
            }
        }
        __syncthreads();

        // ---- interval 12: J h2 on owned slice + emit + broadcast ----
        if (tid < M * HSL) {
            const int m = tid >> 5, hl = tid & 31;
            float s = 0.f, c = 0.f;
            #pragma unroll
            for (int j = 0; j < M; j++)
                cacc_df(s, c, {sct_h[m * 8 + j], sct_l[m * 8 + j]},
                              {svc_h[j * HSL + hl], svc_l[j * HSL + hl]});
            DF dot = qts(s, c);
            const int hg = m * H + HB + hl;
            const float2 h1v = scomm1[hg];
            DF h1 = {h1v.x, h1v.y};
            const bool on = smask[m] > 0.5f;
            DF h2 = on ? df_add(h1, dot) : h1;
            g_hidden[t * (M * H) + hg] = h2.h + h2.l;
            const uint64_t pk = ((uint64_t)__float_as_uint(h2.l) << 32) | __float_as_uint(h2.h);
            const uint32_t ad = a_comm2 + hg * 8;
            #pragma unroll
            for (int rk = 0; rk < NCTA; rk++) st_cluster_b64(ad, rk, pk);
        }
        CLUSTER_BAR();
    }
}

// ---------------------------------------------------------------------------
// Kernel 3: classifier (unchanged)
// ---------------------------------------------------------------------------
__global__ void cls_kernel(const float* __restrict__ Wcls,
                           const float* __restrict__ bcls,
                           float* __restrict__ out)
{
    const int warp = (blockIdx.x * blockDim.x + threadIdx.x) >> 5;
    const int lane = threadIdx.x & 31;
    if (warp >= T * 2) return;
    const int t = warp >> 1, c = warp & 1;
    const float* h = g_hidden + t * (M * H);
    float acc = 0.f;
    for (int i = lane; i < M * H; i += 32) acc += h[i] * Wcls[i * 2 + c];
    #pragma unroll
    for (int off = 16; off; off >>= 1) acc += __shfl_down_sync(0xffffffffu, acc, off);
    if (lane == 0) out[t * 2 + c] = acc + bcls[c];
}

// ---------------------------------------------------------------------------
extern "C" void kernel_launch(void* const* d_in, const int* in_sizes, int n_in,
                              void* d_out, int out_size)
{
    const float* bert  = (const float*)d_in[0];
    const int*   ui    = (const int*)  d_in[1];
    const int*   pi    = (const int*)  d_in[2];
    const float* disg  = (const float*)d_in[3];
    const float* udisg = (const float*)d_in[4];
    const float* utab  = (const float*)d_in[5];
    const float* ptab  = (const float*)d_in[6];
    const float* Wk0 = (const float*)d_in[7],  *Wv0 = (const float*)d_in[8];
    const float* Wk1 = (const float*)d_in[9],  *Wv1 = (const float*)d_in[10];
    const float* Wk2 = (const float*)d_in[11], *Wv2 = (const float*)d_in[12];
    const float* Wk3 = (const float*)d_in[13], *Wv3 = (const float*)d_in[14];
    const float* Wk4 = (const float*)d_in[15], *Wv4 = (const float*)d_in[16];
    const float* Wq    = (const float*)d_in[17];
    const float* Wih   = (const float*)d_in[18];
    const float* Whh   = (const float*)d_in[19];
    const float* blstm = (const float*)d_in[20];
    const float* Wqc   = (const float*)d_in[21];
    const float* Wkc   = (const float*)d_in[22];
    const float* Wvc   = (const float*)d_in[23];
    const float* Wcls  = (const float*)d_in[24];
    const float* bcls  = (const float*)d_in[25];

    proj_kernel<<<T, 768>>>(bert, ui, pi, disg, udisg, utab, ptab,
                            Wk0, Wv0, Wk1, Wv1, Wk2, Wv2, Wk3, Wv3, Wk4, Wv4);
    scan_kernel<<<NCTA, 640>>>(Wq, Wih, Whh, blstm, Wqc, Wkc, Wvc);
    cls_kernel<<<32, 1024>>>(Wcls, bcls, (float*)d_out);
}

// round 6
// speedup vs baseline: 16.8792x; 1.1506x over previous
#include <cuda_runtime.h>
#include <math.h>
#include <stdint.h>

#define T 512
#define M 5
#define H 128
#define KTOP 3
#define DK 64
#define DV 64
#define DC 32
#define NELEM 6
#define GH 512
#define NCTA 4
#define HSL 32

typedef unsigned long long u64;

__device__ float g_keys[T * NELEM * DK];
__device__ float g_vals[T * NELEM * DV];
__device__ float g_hidden[T * M * H];
// Packed (even,odd) weight pair scratch
__device__ u64 g_W2[M * 96 * GH];        // fused [Wih;Whh] rows, 1.97MB
__device__ u64 g_Wq2[M * 64 * DK];
__device__ u64 g_Wqkc2[2 * M * 64 * DC];
__device__ u64 g_Wvc2[M * 64 * H];

// ===========================================================================
// Double-float primitives (proven R4/R5)
// ===========================================================================
struct DF { float h, l; };

__device__ __forceinline__ DF qts(float a, float b) {
    float s = a + b; float e = b - (s - a); return {s, e};
}
__device__ __forceinline__ DF tsum(float a, float b) {
    float s = a + b; float bb = s - a;
    float e = (a - (s - bb)) + (b - bb);
    return {s, e};
}
__device__ __forceinline__ DF tprod(float a, float b) {
    float p = a * b; float e = fmaf(a, b, -p); return {p, e};
}
__device__ __forceinline__ DF df_add(DF a, DF b) {
    DF s = tsum(a.h, b.h);
    return qts(s.h, s.l + (a.l + b.l));
}
__device__ __forceinline__ DF df_add_f(DF a, float b) {
    DF s = tsum(a.h, b);
    return qts(s.h, s.l + a.l);
}
__device__ __forceinline__ DF df_sub(DF a, DF b) { return df_add(a, {-b.h, -b.l}); }
__device__ __forceinline__ DF df_mul(DF a, DF b) {
    DF p = tprod(a.h, b.h);
    float l = p.l + (a.h * b.l + a.l * b.h);
    return qts(p.h, l);
}
__device__ __forceinline__ DF df_recip(DF d) {
    float y0 = __frcp_rn(d.h);
    DF p = tprod(d.h, y0);
    float e = (1.0f - p.h) - p.l;
    e = fmaf(-d.l, y0, e);
    return qts(y0, y0 * e);
}
__device__ __forceinline__ bool df_lt(DF a, DF b) {
    return (a.h < b.h) || (a.h == b.h && a.l < b.l);
}
__device__ __forceinline__ void cacc(float& s, float& c, float xh, float xl, float w) {
    float p = xh * w;
    float e = fmaf(xh, w, -p);
    e = fmaf(xl, w, e);
    float t = s + p;
    float bb = t - s;
    c += ((s - (t - bb)) + (p - bb)) + e;
    s = t;
}
__device__ __forceinline__ void cacc_df(float& s, float& c, DF a, DF b) {
    float p = a.h * b.h;
    float e = fmaf(a.h, b.h, -p);
    e = fmaf(a.h, b.l, e);
    e = fmaf(a.l, b.h, e);
    float t = s + p;
    float bb = t - s;
    c += ((s - (t - bb)) + (p - bb)) + e;
    s = t;
}
__device__ __forceinline__ DF df_exp(DF x) {
    if (x.h > 30.f)  { x.h = 30.f;  x.l = 0.f; }
    if (x.h < -30.f) { x.h = -30.f; x.l = 0.f; }
    const float kf = rintf(x.h * 1.4426950408889634f);
    const float th = fmaf(-kf, 0.693145751953125f, x.h);
    const float tl = fmaf(-kf, 1.4286068203094172e-6f, x.l);
    float B = 2.7557319e-6f;
    B = fmaf(B, th, 2.4801587e-5f);
    B = fmaf(B, th, 1.9841270e-4f);
    B = fmaf(B, th, 1.3888889e-3f);
    B = fmaf(B, th, 8.3333333e-3f);
    B = fmaf(B, th, 4.1666667e-2f);
    DF t2 = tprod(th, th);
    DF t3 = tprod(t2.h, th);
    t3.l = fmaf(t2.l, th, t3.l);
    DF q = tprod(t3.h, 0.16666667f);
    q.l = fmaf(t3.h, -4.9670537e-9f, q.l);
    q.l = fmaf(t3.l, 0.16666667f, q.l);
    const float f4 = t2.h * t2.h * B;
    DF S = qts(1.0f, th);
    S = df_add(S, {t2.h * 0.5f, t2.l * 0.5f});
    S = df_add(S, q);
    S.l += f4;
    S.l = fmaf(S.h, tl, S.l);
    S = qts(S.h, S.l);
    const float sc = __int_as_float(((int)kf + 127) << 23);
    S.h *= sc; S.l *= sc;
    return S;
}
__device__ __forceinline__ DF df_sigmoid(DF x) {
    DF E = df_exp({-x.h, -x.l});
    return df_recip(df_add_f(E, 1.0f));
}
__device__ __forceinline__ DF df_tanh(DF x) {
    const float sgn = (x.h < 0.f) ? -1.f : 1.f;
    DF a = {sgn * x.h, sgn * x.l};
    DF E = df_exp({2.f * a.h, 2.f * a.l});
    DF r = df_recip(df_add_f(E, 1.0f));
    DF res = tsum(1.0f, -2.f * r.h);
    DF o = qts(res.h, res.l - 2.f * r.l);
    return {sgn * o.h, sgn * o.l};
}
__device__ __forceinline__ DF df_red(DF a, unsigned off) {
    float oh = __shfl_down_sync(0xffffffffu, a.h, off);
    float ol = __shfl_down_sync(0xffffffffu, a.l, off);
    return df_add(a, {oh, ol});
}

// ===========================================================================
// Packed f32x2 dual compensated chain
// ===========================================================================
__device__ __forceinline__ u64 f2mul(u64 a, u64 b) {
    u64 r; asm("mul.rn.f32x2 %0, %1, %2;" : "=l"(r) : "l"(a), "l"(b)); return r;
}
__device__ __forceinline__ u64 f2add(u64 a, u64 b) {
    u64 r; asm("add.rn.f32x2 %0, %1, %2;" : "=l"(r) : "l"(a), "l"(b)); return r;
}
__device__ __forceinline__ u64 f2fma(u64 a, u64 b, u64 c) {
    u64 r; asm("fma.rn.f32x2 %0, %1, %2, %3;" : "=l"(r) : "l"(a), "l"(b), "l"(c)); return r;
}
__device__ __forceinline__ u64 f2neg(u64 a) { return a ^ 0x8000000080000000ull; }

// (s2,c2) += xh2*w2 + xl2*w2 lane-wise, compensated (2 independent chains)
__device__ __forceinline__ void cacc2(u64& s2, u64& c2, u64 xh2, u64 xl2, u64 w2) {
    u64 p  = f2mul(xh2, w2);
    u64 e  = f2fma(xh2, w2, f2neg(p));
    e      = f2fma(xl2, w2, e);
    u64 t  = f2add(s2, p);
    u64 bb = f2add(t, f2neg(s2));
    u64 z1 = f2add(s2, f2neg(f2add(t, f2neg(bb))));
    u64 z2 = f2add(p, f2neg(bb));
    c2 = f2add(c2, f2add(f2add(z1, z2), e));
    s2 = t;
}
__device__ __forceinline__ DF df_from2(u64 s2, u64 c2) {
    float se = __uint_as_float((unsigned)s2), so = __uint_as_float((unsigned)(s2 >> 32));
    float ce = __uint_as_float((unsigned)c2), co = __uint_as_float((unsigned)(c2 >> 32));
    DF re = tsum(se, ce); re = qts(re.h, re.l);
    DF ro = tsum(so, co); ro = qts(ro.h, ro.l);
    return df_add(re, ro);
}
__device__ __forceinline__ u64 f_to_lo(float a) { return (u64)__float_as_uint(a); }

// Cluster helpers
__device__ __forceinline__ uint32_t smem_u32(const void* p) {
    uint32_t a;
    asm("{ .reg .u64 t; cvta.to.shared.u64 t, %1; cvt.u32.u64 %0, t; }" : "=r"(a) : "l"(p));
    return a;
}
__device__ __forceinline__ uint32_t my_rank() {
    uint32_t r; asm("mov.u32 %0, %%cluster_ctarank;" : "=r"(r)); return r;
}
__device__ __forceinline__ void st_cluster_b32(uint32_t saddr, uint32_t rank, uint32_t v) {
    uint32_t ra;
    asm volatile("mapa.shared::cluster.u32 %0, %1, %2;" : "=r"(ra) : "r"(saddr), "r"(rank));
    asm volatile("st.shared::cluster.b32 [%0], %1;" :: "r"(ra), "r"(v) : "memory");
}
#define CLUSTER_BAR() do { \
    asm volatile("barrier.cluster.arrive.aligned;" ::: "memory"); \
    asm volatile("barrier.cluster.wait.aligned;"   ::: "memory"); } while (0)

// ---------------------------------------------------------------------------
// Kernel 0: pack weights into (even,odd) u64 pair layouts.
// ---------------------------------------------------------------------------
__global__ void pack_kernel(const float* __restrict__ Wq,
                            const float* __restrict__ Wih,
                            const float* __restrict__ Whh,
                            const float* __restrict__ Wqc,
                            const float* __restrict__ Wkc,
                            const float* __restrict__ Wvc)
{
    const int stride = gridDim.x * blockDim.x;
    const int i0 = blockIdx.x * blockDim.x + threadIdx.x;
    for (int idx = i0; idx < M * 96 * GH; idx += stride) {
        const int col = idx % GH;
        const int r = idx / GH;
        const int v2 = r % 96, m = r / 96;
        const int r0 = 2 * v2, r1 = r0 + 1;
        const float e = (r0 < 64) ? Wih[(m * DV + r0) * GH + col] : Whh[(m * H + r0 - 64) * GH + col];
        const float o = (r1 < 64) ? Wih[(m * DV + r1) * GH + col] : Whh[(m * H + r1 - 64) * GH + col];
        g_W2[idx] = ((u64)__float_as_uint(o) << 32) | __float_as_uint(e);
    }
    for (int idx = i0; idx < M * 64 * DK; idx += stride) {
        const int dk = idx % DK;
        const int r = idx / DK;
        const int i2 = r % 64, m = r / 64;
        const float e = Wq[(m * H + 2 * i2) * DK + dk];
        const float o = Wq[(m * H + 2 * i2 + 1) * DK + dk];
        g_Wq2[idx] = ((u64)__float_as_uint(o) << 32) | __float_as_uint(e);
    }
    for (int idx = i0; idx < 2 * M * 64 * DC; idx += stride) {
        const int dc = idx % DC;
        const int r = idx / DC;
        const int k = r % 64;
        const int pm = (r / 64) % M;
        const int sel = r / (64 * M);
        const float* W = sel ? Wkc : Wqc;
        const float e = W[(pm * H + 2 * k) * DC + dc];
        const float o = W[(pm * H + 2 * k + 1) * DC + dc];
        g_Wqkc2[idx] = ((u64)__float_as_uint(o) << 32) | __float_as_uint(e);
    }
    for (int idx = i0; idx < M * 64 * H; idx += stride) {
        const int hv = idx % H;
        const int r = idx / H;
        const int i2 = r % 64, j = r / 64;
        const float e = Wvc[(j * H + 2 * i2) * H + hv];
        const float o = Wvc[(j * H + 2 * i2 + 1) * H + hv];
        g_Wvc2[idx] = ((u64)__float_as_uint(o) << 32) | __float_as_uint(e);
    }
}

// ---------------------------------------------------------------------------
// Kernel 1: modality projections (unchanged)
// ---------------------------------------------------------------------------
__global__ void __launch_bounds__(768) proj_kernel(
    const float* __restrict__ bert,
    const int*   __restrict__ umls_idx,
    const int*   __restrict__ pos_idx,
    const float* __restrict__ disg,
    const float* __restrict__ udisg,
    const float* __restrict__ umls_table,
    const float* __restrict__ pos_table,
    const float* __restrict__ Wk0, const float* __restrict__ Wv0,
    const float* __restrict__ Wk1, const float* __restrict__ Wv1,
    const float* __restrict__ Wk2, const float* __restrict__ Wv2,
    const float* __restrict__ Wk3, const float* __restrict__ Wv3,
    const float* __restrict__ Wk4, const float* __restrict__ Wv4)
{
    __shared__ float x[768 + 50 + 20 + 2 + 2];
    const int t = blockIdx.x;
    const int tid = threadIdx.x;

    x[tid] = bert[t * 768 + tid];
    {
        const long ui = (long)umls_idx[t];
        const int  pi = pos_idx[t];
        if (tid < 50) x[768 + tid] = umls_table[ui * 50 + tid];
        else if (tid < 70) x[818 + (tid - 50)] = pos_table[pi * 20 + (tid - 50)];
        else if (tid < 72) x[838 + (tid - 70)] = disg[t * 2 + (tid - 70)];
        else if (tid < 74) x[840 + (tid - 72)] = udisg[t * 2 + (tid - 72)];
    }
    __syncthreads();

    const float* Wks[5] = {Wk0, Wk1, Wk2, Wk3, Wk4};
    const float* Wvs[5] = {Wv0, Wv1, Wv2, Wv3, Wv4};
    const int dims[5] = {768, 50, 20, 2, 2};
    const int offs[5] = {0, 768, 818, 838, 840};

    const int o    = tid;
    const int mod  = o >> 7;
    const int half = (o >> 6) & 1;
    const int dk   = o & 63;
    float acc = 0.f;
    if (mod < 5) {
        const float* W  = half ? Wvs[mod] : Wks[mod];
        const float* xx = x + offs[mod];
        const int d = dims[mod];
        for (int i = 0; i < d; i++) acc += xx[i] * W[i * 64 + dk];
    }
    if (half == 0) g_keys[t * NELEM * DK + mod * DK + dk] = acc;
    else           g_vals[t * NELEM * DV + mod * DV + dk] = acc;
}

// ---------------------------------------------------------------------------
// Kernel 2: MI-RIM scan, 4-CTA cluster, packed-DF arithmetic. 640 thr/CTA.
// ---------------------------------------------------------------------------
__global__ void __cluster_dims__(NCTA, 1, 1) __launch_bounds__(640, 1) scan_kernel(
    const float* __restrict__ blstm) // [M,4H]; other weights pre-packed
{
    __shared__ float  skt[NELEM * DK], svt[NELEM * DV];
    __shared__ float  sq_h[M * DK], sq_l[M * DK];
    __shared__ float  sat_h[M * 8], sat_l[M * 8];
    __shared__ float  sct_h[M * 8], sct_l[M * 8];
    __shared__ __align__(16) float sinp_h[M * DV];
    __shared__ __align__(16) float sinp_l[M * DV];
    __shared__ float  sgate_h[640], sgate_l[640];
    __shared__ float  sqc_h[M * DC], sqc_l[M * DC];
    __shared__ float  skc_h[M * DC], skc_l[M * DC];
    __shared__ float  svc_h[M * HSL], svc_l[M * HSL];
    __shared__ float  sc_h[M * HSL], sc_l[M * HSL];
    __shared__ __align__(16) float h1_h[M * H];   // gathered h1
    __shared__ __align__(16) float h1_l[M * H];
    __shared__ __align__(16) float hc_h[M * H];   // gathered carry h
    __shared__ __align__(16) float hc_l[M * H];
    __shared__ float  smask[8];

    const int tid  = threadIdx.x;
    const uint32_t rank = my_rank();
    const int HB = rank * HSL;
    const uint32_t a1h = smem_u32(h1_h), a1l = smem_u32(h1_l);
    const uint32_t a2h = smem_u32(hc_h), a2l = smem_u32(hc_l);

    hc_h[tid] = 0.f; hc_l[tid] = 0.f;
    if (tid < M * HSL) { sc_h[tid] = 0.f; sc_l[tid] = 0.f; }
    __syncthreads();
    CLUSTER_BAR();

    for (int t = 0; t < T; ++t) {
        // ---- int1: A keys/vals + B q-proj (packed, K-split-2) ----
        if (tid < NELEM * DK) {
            skt[tid] = g_keys[t * NELEM * DK + tid];
            svt[tid] = g_vals[t * NELEM * DV + tid];
        }
        {
            const int out = tid >> 1;            // (qm,dk)
            const int half = tid & 1;
            const int qm = out >> 6, dk = out & 63;
            const u64* xh2 = (const u64*)(hc_h + qm * H) + half * 32;
            const u64* xl2 = (const u64*)(hc_l + qm * H) + half * 32;
            const u64* w2  = g_Wq2 + (qm * 64 + half * 32) * DK + dk;
            u64 s2 = 0, c2 = 0;
            #pragma unroll 4
            for (int k = 0; k < 32; k++) cacc2(s2, c2, xh2[k], xl2[k], w2[k * DK]);
            DF r = df_from2(s2, c2);
            DF o = df_red(r, 1);
            if (half == 0) { sq_h[out] = o.h; sq_l[out] = o.l; }
        }
        __syncthreads();

        // ---- int2: C attention logits, K-split-8 ----
        {
            const int gout = tid >> 3;
            const int part = tid & 7;
            const int out = gout < 30 ? gout : 29;
            const int am = out / NELEM, j = out - am * NELEM;
            const float* kk = skt + j * DK;
            const float* qh = sq_h + am * DK;
            const float* ql = sq_l + am * DK;
            float s = 0.f, c = 0.f;
            const int i0 = part * 8;
            #pragma unroll
            for (int i = i0; i < i0 + 8; i++) cacc(s, c, qh[i], ql[i], kk[i]);
            DF r = qts(s, c);
            r = df_red(r, 4); r = df_red(r, 2); r = df_red(r, 1);
            if (part == 0 && gout < 30) {
                sat_h[am * 8 + j] = r.h * 0.125f;
                sat_l[am * 8 + j] = r.l * 0.125f;
            }
        }
        __syncthreads();

        // ---- int3: softmax exp ----
        if (tid < M * NELEM) {
            const int sm = tid / NELEM, j = tid - sm * NELEM;
            DF v[NELEM];
            for (int k = 0; k < NELEM; k++) v[k] = {sat_h[sm * 8 + k], sat_l[sm * 8 + k]};
            DF mx = v[0];
            for (int k = 1; k < NELEM; k++) if (df_lt(mx, v[k])) mx = v[k];
            DF e = df_exp(df_sub(v[j], mx));
            sat_h[sm * 8 + j] = e.h; sat_l[sm * 8 + j] = e.l;
        }
        __syncthreads();

        // ---- int4: softmax normalize ----
        if (tid < M) {
            DF sum = {0.f, 0.f};
            for (int j = 0; j < NELEM; j++) sum = df_add(sum, {sat_h[tid * 8 + j], sat_l[tid * 8 + j]});
            DF inv = df_recip(sum);
            for (int j = 0; j < NELEM; j++) {
                DF a = df_mul({sat_h[tid * 8 + j], sat_l[tid * 8 + j]}, inv);
                sat_h[tid * 8 + j] = a.h; sat_l[tid * 8 + j] = a.l;
            }
        }
        __syncthreads();

        // ---- int5: top-3 mask + E inp ----
        if (tid == 0) {
            DF nl[M]; bool used[M];
            for (int i = 0; i < M; i++) {
                nl[i] = {sat_h[i * 8 + (NELEM - 1)], sat_l[i * 8 + (NELEM - 1)]};
                used[i] = false; smask[i] = 0.f;
            }
            for (int r = 0; r < KTOP; r++) {
                int best = -1; DF bv = {0.f, 0.f};
                for (int i = 0; i < M; i++)
                    if (!used[i] && (best < 0 || df_lt(nl[i], bv))) { bv = nl[i]; best = i; }
                used[best] = true; smask[best] = 1.f;
            }
        }
        if (tid < M * DV) {
            const int em = tid >> 6, dv = tid & 63;
            float s = 0.f, c = 0.f;
            #pragma unroll
            for (int j = 0; j < NELEM; j++)
                cacc(s, c, sat_h[em * 8 + j], sat_l[em * 8 + j], svt[j * DV + dv]);
            DF r = qts(s, c);
            sinp_h[tid] = r.h; sinp_l[tid] = r.l;
        }
        __syncthreads();

        // ---- int6: F gates (packed) + nonlinearity ----
        {
            const int m = tid >> 7;
            const int r = tid & 127;
            const int gate = r >> 5;
            const int hl = r & 31;
            const int col = gate * H + HB + hl;
            const u64* w2 = g_W2 + (m * 96) * GH + col;
            u64 s2 = f_to_lo(blstm[m * GH + col]), c2 = 0;
            const u64* ih2 = (const u64*)(sinp_h + m * DV);
            const u64* il2 = (const u64*)(sinp_l + m * DV);
            #pragma unroll 4
            for (int v2 = 0; v2 < 32; v2++)
                cacc2(s2, c2, ih2[v2], il2[v2], w2[v2 * GH]);
            const u64* hh2 = (const u64*)(hc_h + m * H);
            const u64* hl2 = (const u64*)(hc_l + m * H);
            #pragma unroll 4
            for (int v2 = 0; v2 < 64; v2++)
                cacc2(s2, c2, hh2[v2], hl2[v2], w2[(32 + v2) * GH]);
            DF g = df_from2(s2, c2);
            DF nlv = (gate == 2) ? df_tanh(g) : df_sigmoid(g);
            sgate_h[tid] = nlv.h; sgate_l[tid] = nlv.l;
        }
        __syncthreads();

        // ---- int7: LSTM update on owned slice + broadcast h1 ----
        if (tid < M * HSL) {
            const int m = tid >> 5, hl = tid & 31;
            const int base = m * 128 + hl;
            DF ig = {sgate_h[base],      sgate_l[base]};
            DF fg = {sgate_h[base + 32], sgate_l[base + 32]};
            DF gt = {sgate_h[base + 64], sgate_l[base + 64]};
            DF og = {sgate_h[base + 96], sgate_l[base + 96]};
            DF cold = {sc_h[tid], sc_l[tid]};
            DF cn = df_add(df_mul(fg, cold), df_mul(ig, gt));
            DF hn = df_mul(og, df_tanh(cn));
            const bool on = smask[m] > 0.5f;
            const int hg = m * H + HB + hl;
            DF h1 = on ? hn : DF{hc_h[hg], hc_l[hg]};
            DF c1 = on ? cn : cold;
            sc_h[tid] = c1.h; sc_l[tid] = c1.l;
            #pragma unroll
            for (int rk = 0; rk < NCTA; rk++) {
                st_cluster_b32(a1h + hg * 4, rk, __float_as_uint(h1.h));
                st_cluster_b32(a1l + hg * 4, rk, __float_as_uint(h1.l));
            }
        }
        CLUSTER_BAR();

        // ---- int8: warp-split — warps 0-9: qc/kc (packed); warps 10-19: vc ----
        if (tid < 320) {
            const int out = tid;
            const int isK = out >= 160;
            const int o2 = isK ? out - 160 : out;
            const int pm = o2 >> 5, dc = o2 & 31;
            const u64* xh2 = (const u64*)(h1_h + pm * H);
            const u64* xl2 = (const u64*)(h1_l + pm * H);
            const u64* w2  = g_Wqkc2 + ((isK * 5 + pm) * 64) * DC + dc;
            u64 s2 = 0, c2 = 0;
            #pragma unroll 4
            for (int k = 0; k < 64; k++) cacc2(s2, c2, xh2[k], xl2[k], w2[k * DC]);
            DF r = df_from2(s2, c2);
            if (isK) { skc_h[o2] = r.h; skc_l[o2] = r.l; }
            else     { sqc_h[o2] = r.h; sqc_l[o2] = r.l; }
        } else {
            const int tid2 = tid - 320;
            const int out = tid2 >> 1;           // (j, hl)
            const int half = tid2 & 1;
            const int j = out >> 5, hl = out & 31;
            const u64* xh2 = (const u64*)(h1_h + j * H) + half * 32;
            const u64* xl2 = (const u64*)(h1_l + j * H) + half * 32;
            const u64* w2  = g_Wvc2 + (j * 64 + half * 32) * H + HB + hl;
            u64 s2 = 0, c2 = 0;
            #pragma unroll 4
            for (int k = 0; k < 32; k++) cacc2(s2, c2, xh2[k], xl2[k], w2[k * H]);
            DF r = df_from2(s2, c2);
            DF o = df_red(r, 1);
            if (half == 0) { svc_h[out] = o.h; svc_l[out] = o.l; }
        }
        __syncthreads();

        // ---- int9: cattn logits (K-split-8) ----
        {
            const int gout = tid >> 3;
            const int part = tid & 7;
            const int out = gout < 25 ? gout : 24;
            const int im = out / M, j = out - im * M;
            float s = 0.f, c = 0.f;
            const int i0 = part * 4;
            #pragma unroll
            for (int i = i0; i < i0 + 4; i++)
                cacc_df(s, c, {sqc_h[im * DC + i], sqc_l[im * DC + i]},
                              {skc_h[j * DC + i],  skc_l[j * DC + i]});
            DF r = qts(s, c);
            r = df_red(r, 4); r = df_red(r, 2); r = df_red(r, 1);
            if (part == 0 && gout < 25) {
                DF sc = df_mul(r, {0.17677669227123260f, 3.0254043e-9f});
                sct_h[im * 8 + j] = sc.h; sct_l[im * 8 + j] = sc.l;
            }
        }
        __syncthreads();

        // ---- int10: cattn exp ----
        if (tid < M * M) {
            const int im = tid / M, j = tid - im * M;
            DF v[M];
            for (int k = 0; k < M; k++) v[k] = {sct_h[im * 8 + k], sct_l[im * 8 + k]};
            DF mx = v[0];
            for (int k = 1; k < M; k++) if (df_lt(mx, v[k])) mx = v[k];
            DF e = df_exp(df_sub(v[j], mx));
            sct_h[im * 8 + j] = e.h; sct_l[im * 8 + j] = e.l;
        }
        __syncthreads();

        // ---- int11: cattn normalize ----
        if (tid < M) {
            DF sum = {0.f, 0.f};
            for (int j = 0; j < M; j++) sum = df_add(sum, {sct_h[tid * 8 + j], sct_l[tid * 8 + j]});
            DF inv = df_recip(sum);
            for (int j = 0; j < M; j++) {
                DF a = df_mul({sct_h[tid * 8 + j], sct_l[tid * 8 + j]}, inv);
                sct_h[tid * 8 + j] = a.h; sct_l[tid * 8 + j] = a.l;
            }
        }
        __syncthreads();

        // ---- int12: h2 on owned slice + emit + broadcast carry ----
        if (tid < M * HSL) {
            const int m = tid >> 5, hl = tid & 31;
            float s = 0.f, c = 0.f;
            #pragma unroll
            for (int j = 0; j < M; j++)
                cacc_df(s, c, {sct_h[m * 8 + j], sct_l[m * 8 + j]},
                              {svc_h[j * HSL + hl], svc_l[j * HSL + hl]});
            DF dot = qts(s, c);
            const int hg = m * H + HB + hl;
            DF h1 = {h1_h[hg], h1_l[hg]};
            const bool on = smask[m] > 0.5f;
            DF h2 = on ? df_add(h1, dot) : h1;
            g_hidden[t * (M * H) + hg] = h2.h + h2.l;
            #pragma unroll
            for (int rk = 0; rk < NCTA; rk++) {
                st_cluster_b32(a2h + hg * 4, rk, __float_as_uint(h2.h));
                st_cluster_b32(a2l + hg * 4, rk, __float_as_uint(h2.l));
            }
        }
        CLUSTER_BAR();
    }
}

// ---------------------------------------------------------------------------
// Kernel 3: classifier (unchanged)
// ---------------------------------------------------------------------------
__global__ void cls_kernel(const float* __restrict__ Wcls,
                           const float* __restrict__ bcls,
                           float* __restrict__ out)
{
    const int warp = (blockIdx.x * blockDim.x + threadIdx.x) >> 5;
    const int lane = threadIdx.x & 31;
    if (warp >= T * 2) return;
    const int t = warp >> 1, c = warp & 1;
    const float* h = g_hidden + t * (M * H);
    float acc = 0.f;
    for (int i = lane; i < M * H; i += 32) acc += h[i] * Wcls[i * 2 + c];
    #pragma unroll
    for (int off = 16; off; off >>= 1) acc += __shfl_down_sync(0xffffffffu, acc, off);
    if (lane == 0) out[t * 2 + c] = acc + bcls[c];
}

// ---------------------------------------------------------------------------
extern "C" void kernel_launch(void* const* d_in, const int* in_sizes, int n_in,
                              void* d_out, int out_size)
{
    const float* bert  = (const float*)d_in[0];
    const int*   ui    = (const int*)  d_in[1];
    const int*   pi    = (const int*)  d_in[2];
    const float* disg  = (const float*)d_in[3];
    const float* udisg = (const float*)d_in[4];
    const float* utab  = (const float*)d_in[5];
    const float* ptab  = (const float*)d_in[6];
    const float* Wk0 = (const float*)d_in[7],  *Wv0 = (const float*)d_in[8];
    const float* Wk1 = (const float*)d_in[9],  *Wv1 = (const float*)d_in[10];
    const float* Wk2 = (const float*)d_in[11], *Wv2 = (const float*)d_in[12];
    const float* Wk3 = (const float*)d_in[13], *Wv3 = (const float*)d_in[14];
    const float* Wk4 = (const float*)d_in[15], *Wv4 = (const float*)d_in[16];
    const float* Wq    = (const float*)d_in[17];
    const float* Wih   = (const float*)d_in[18];
    const float* Whh   = (const float*)d_in[19];
    const float* blstm = (const float*)d_in[20];
    const float* Wqc   = (const float*)d_in[21];
    const float* Wkc   = (const float*)d_in[22];
    const float* Wvc   = (const float*)d_in[23];
    const float* Wcls  = (const float*)d_in[24];
    const float* bcls  = (const float*)d_in[25];

    pack_kernel<<<256, 256>>>(Wq, Wih, Whh, Wqc, Wkc, Wvc);
    proj_kernel<<<T, 768>>>(bert, ui, pi, disg, udisg, utab, ptab,
                            Wk0, Wv0, Wk1, Wv1, Wk2, Wv2, Wk3, Wv3, Wk4, Wv4);
    scan_kernel<<<NCTA, 640>>>(blstm);
    cls_kernel<<<32, 1024>>>(Wcls, bcls, (float*)d_out);
}

// round 7
// speedup vs baseline: 18.5803x; 1.1008x over previous
#include <cuda_runtime.h>
#include <math.h>
#include <stdint.h>

#define T 512
#define M 5
#define H 128
#define KTOP 3
#define DK 64
#define DV 64
#define DC 32
#define NELEM 6
#define GH 512
#define NCTA 4
#define HSL 32

typedef unsigned long long u64;

__device__ float g_keys[T * NELEM * DK];
__device__ float g_vals[T * NELEM * DV];
__device__ float g_hidden[T * M * H];
// Packed (even,odd) weight pair scratch
__device__ u64 g_W2[M * 96 * GH];
__device__ u64 g_Wq2[M * 64 * DK];
__device__ u64 g_Wqkc2[2 * M * 64 * DC];
__device__ u64 g_Wvc2[M * 64 * H];

// ===========================================================================
// Double-float primitives (proven R4-R6)
// ===========================================================================
struct DF { float h, l; };

__device__ __forceinline__ DF qts(float a, float b) {
    float s = a + b; float e = b - (s - a); return {s, e};
}
__device__ __forceinline__ DF tsum(float a, float b) {
    float s = a + b; float bb = s - a;
    float e = (a - (s - bb)) + (b - bb);
    return {s, e};
}
__device__ __forceinline__ DF tprod(float a, float b) {
    float p = a * b; float e = fmaf(a, b, -p); return {p, e};
}
__device__ __forceinline__ DF df_add(DF a, DF b) {
    DF s = tsum(a.h, b.h);
    return qts(s.h, s.l + (a.l + b.l));
}
__device__ __forceinline__ DF df_add_f(DF a, float b) {
    DF s = tsum(a.h, b);
    return qts(s.h, s.l + a.l);
}
__device__ __forceinline__ DF df_sub(DF a, DF b) { return df_add(a, {-b.h, -b.l}); }
__device__ __forceinline__ DF df_mul(DF a, DF b) {
    DF p = tprod(a.h, b.h);
    float l = p.l + (a.h * b.l + a.l * b.h);
    return qts(p.h, l);
}
__device__ __forceinline__ DF df_recip(DF d) {
    float y0 = __frcp_rn(d.h);
    DF p = tprod(d.h, y0);
    float e = (1.0f - p.h) - p.l;
    e = fmaf(-d.l, y0, e);
    return qts(y0, y0 * e);
}
__device__ __forceinline__ bool df_lt(DF a, DF b) {
    return (a.h < b.h) || (a.h == b.h && a.l < b.l);
}
__device__ __forceinline__ void cacc(float& s, float& c, float xh, float xl, float w) {
    float p = xh * w;
    float e = fmaf(xh, w, -p);
    e = fmaf(xl, w, e);
    float t = s + p;
    float bb = t - s;
    c += ((s - (t - bb)) + (p - bb)) + e;
    s = t;
}
__device__ __forceinline__ void cacc_df(float& s, float& c, DF a, DF b) {
    float p = a.h * b.h;
    float e = fmaf(a.h, b.h, -p);
    e = fmaf(a.h, b.l, e);
    e = fmaf(a.l, b.h, e);
    float t = s + p;
    float bb = t - s;
    c += ((s - (t - bb)) + (p - bb)) + e;
    s = t;
}
__device__ __forceinline__ DF df_exp(DF x) {
    if (x.h > 30.f)  { x.h = 30.f;  x.l = 0.f; }
    if (x.h < -30.f) { x.h = -30.f; x.l = 0.f; }
    const float kf = rintf(x.h * 1.4426950408889634f);
    const float th = fmaf(-kf, 0.693145751953125f, x.h);
    const float tl = fmaf(-kf, 1.4286068203094172e-6f, x.l);
    float B = 2.7557319e-6f;
    B = fmaf(B, th, 2.4801587e-5f);
    B = fmaf(B, th, 1.9841270e-4f);
    B = fmaf(B, th, 1.3888889e-3f);
    B = fmaf(B, th, 8.3333333e-3f);
    B = fmaf(B, th, 4.1666667e-2f);
    DF t2 = tprod(th, th);
    DF t3 = tprod(t2.h, th);
    t3.l = fmaf(t2.l, th, t3.l);
    DF q = tprod(t3.h, 0.16666667f);
    q.l = fmaf(t3.h, -4.9670537e-9f, q.l);
    q.l = fmaf(t3.l, 0.16666667f, q.l);
    const float f4 = t2.h * t2.h * B;
    DF S = qts(1.0f, th);
    S = df_add(S, {t2.h * 0.5f, t2.l * 0.5f});
    S = df_add(S, q);
    S.l += f4;
    S.l = fmaf(S.h, tl, S.l);
    S = qts(S.h, S.l);
    const float sc = __int_as_float(((int)kf + 127) << 23);
    S.h *= sc; S.l *= sc;
    return S;
}
__device__ __forceinline__ DF df_sigmoid(DF x) {
    DF E = df_exp({-x.h, -x.l});
    return df_recip(df_add_f(E, 1.0f));
}
__device__ __forceinline__ DF df_tanh(DF x) {
    const float sgn = (x.h < 0.f) ? -1.f : 1.f;
    DF a = {sgn * x.h, sgn * x.l};
    DF E = df_exp({2.f * a.h, 2.f * a.l});
    DF r = df_recip(df_add_f(E, 1.0f));
    DF res = tsum(1.0f, -2.f * r.h);
    DF o = qts(res.h, res.l - 2.f * r.l);
    return {sgn * o.h, sgn * o.l};
}
__device__ __forceinline__ DF df_red(DF a, unsigned off) {
    float oh = __shfl_down_sync(0xffffffffu, a.h, off);
    float ol = __shfl_down_sync(0xffffffffu, a.l, off);
    return df_add(a, {oh, ol});
}

// ===========================================================================
// Packed Kahan chain: everything expressed as fma.rn.f32x2 (FFMA2).
// Accumulated value = s - c.
// ===========================================================================
#define PK_ONE2  0x3F8000003F800000ull
#define PK_M1_2  0xBF800000BF800000ull
__device__ __forceinline__ u64 f2fma(u64 a, u64 b, u64 c) {
    u64 r; asm("fma.rn.f32x2 %0, %1, %2, %3;" : "=l"(r) : "l"(a), "l"(b), "l"(c)); return r;
}
__device__ __forceinline__ u64 f2neg(u64 a) { return a ^ 0x8000000080000000ull; }

__device__ __forceinline__ void cacc2k(u64& s2, u64& c2, u64 xh2, u64 xl2, u64 w2) {
    u64 p  = f2fma(xh2, w2, 0ull);          // product (exact mul)
    u64 e  = f2fma(xh2, w2, f2neg(p));      // product error
    e      = f2fma(xl2, w2, e);             // + lo-part product
    u64 cm = f2fma(e, PK_M1_2, c2);         // c - e
    u64 y  = f2fma(cm, PK_M1_2, p);         // p - (c - e)
    u64 t  = f2fma(s2, PK_ONE2, y);         // s + y
    u64 d  = f2fma(s2, PK_M1_2, t);         // t - s
    c2     = f2fma(y, PK_M1_2, d);          // (t - s) - y
    s2 = t;
}
__device__ __forceinline__ DF df_from2k(u64 s2, u64 c2) {
    c2 = f2neg(c2);                          // value = s + (-c)
    float se = __uint_as_float((unsigned)s2), so = __uint_as_float((unsigned)(s2 >> 32));
    float ce = __uint_as_float((unsigned)c2), co = __uint_as_float((unsigned)(c2 >> 32));
    DF re = tsum(se, ce); re = qts(re.h, re.l);
    DF ro = tsum(so, co); ro = qts(ro.h, ro.l);
    return df_add(re, ro);
}
__device__ __forceinline__ u64 f_to_lo(float a) { return (u64)__float_as_uint(a); }

// Cluster helpers
__device__ __forceinline__ uint32_t smem_u32(const void* p) {
    uint32_t a;
    asm("{ .reg .u64 t; cvta.to.shared.u64 t, %1; cvt.u32.u64 %0, t; }" : "=r"(a) : "l"(p));
    return a;
}
__device__ __forceinline__ uint32_t my_rank() {
    uint32_t r; asm("mov.u32 %0, %%cluster_ctarank;" : "=r"(r)); return r;
}
__device__ __forceinline__ void st_cluster_b32(uint32_t saddr, uint32_t rank, uint32_t v) {
    uint32_t ra;
    asm volatile("mapa.shared::cluster.u32 %0, %1, %2;" : "=r"(ra) : "r"(saddr), "r"(rank));
    asm volatile("st.shared::cluster.b32 [%0], %1;" :: "r"(ra), "r"(v) : "memory");
}
#define CLUSTER_BAR() do { \
    asm volatile("barrier.cluster.arrive.aligned;" ::: "memory"); \
    asm volatile("barrier.cluster.wait.aligned;"   ::: "memory"); } while (0)

// ---------------------------------------------------------------------------
// Kernel 0: pack weights (unchanged from R6)
// ---------------------------------------------------------------------------
__global__ void pack_kernel(const float* __restrict__ Wq,
                            const float* __restrict__ Wih,
                            const float* __restrict__ Whh,
                            const float* __restrict__ Wqc,
                            const float* __restrict__ Wkc,
                            const float* __restrict__ Wvc)
{
    const int stride = gridDim.x * blockDim.x;
    const int i0 = blockIdx.x * blockDim.x + threadIdx.x;
    for (int idx = i0; idx < M * 96 * GH; idx += stride) {
        const int col = idx % GH;
        const int r = idx / GH;
        const int v2 = r % 96, m = r / 96;
        const int r0 = 2 * v2, r1 = r0 + 1;
        const float e = (r0 < 64) ? Wih[(m * DV + r0) * GH + col] : Whh[(m * H + r0 - 64) * GH + col];
        const float o = (r1 < 64) ? Wih[(m * DV + r1) * GH + col] : Whh[(m * H + r1 - 64) * GH + col];
        g_W2[idx] = ((u64)__float_as_uint(o) << 32) | __float_as_uint(e);
    }
    for (int idx = i0; idx < M * 64 * DK; idx += stride) {
        const int dk = idx % DK;
        const int r = idx / DK;
        const int i2 = r % 64, m = r / 64;
        const float e = Wq[(m * H + 2 * i2) * DK + dk];
        const float o = Wq[(m * H + 2 * i2 + 1) * DK + dk];
        g_Wq2[idx] = ((u64)__float_as_uint(o) << 32) | __float_as_uint(e);
    }
    for (int idx = i0; idx < 2 * M * 64 * DC; idx += stride) {
        const int dc = idx % DC;
        const int r = idx / DC;
        const int k = r % 64;
        const int pm = (r / 64) % M;
        const int sel = r / (64 * M);
        const float* W = sel ? Wkc : Wqc;
        const float e = W[(pm * H + 2 * k) * DC + dc];
        const float o = W[(pm * H + 2 * k + 1) * DC + dc];
        g_Wqkc2[idx] = ((u64)__float_as_uint(o) << 32) | __float_as_uint(e);
    }
    for (int idx = i0; idx < M * 64 * H; idx += stride) {
        const int hv = idx % H;
        const int r = idx / H;
        const int i2 = r % 64, j = r / 64;
        const float e = Wvc[(j * H + 2 * i2) * H + hv];
        const float o = Wvc[(j * H + 2 * i2 + 1) * H + hv];
        g_Wvc2[idx] = ((u64)__float_as_uint(o) << 32) | __float_as_uint(e);
    }
}

// ---------------------------------------------------------------------------
// Kernel 1: modality projections (unchanged)
// ---------------------------------------------------------------------------
__global__ void __launch_bounds__(768) proj_kernel(
    const float* __restrict__ bert,
    const int*   __restrict__ umls_idx,
    const int*   __restrict__ pos_idx,
    const float* __restrict__ disg,
    const float* __restrict__ udisg,
    const float* __restrict__ umls_table,
    const float* __restrict__ pos_table,
    const float* __restrict__ Wk0, const float* __restrict__ Wv0,
    const float* __restrict__ Wk1, const float* __restrict__ Wv1,
    const float* __restrict__ Wk2, const float* __restrict__ Wv2,
    const float* __restrict__ Wk3, const float* __restrict__ Wv3,
    const float* __restrict__ Wk4, const float* __restrict__ Wv4)
{
    __shared__ float x[768 + 50 + 20 + 2 + 2];
    const int t = blockIdx.x;
    const int tid = threadIdx.x;

    x[tid] = bert[t * 768 + tid];
    {
        const long ui = (long)umls_idx[t];
        const int  pi = pos_idx[t];
        if (tid < 50) x[768 + tid] = umls_table[ui * 50 + tid];
        else if (tid < 70) x[818 + (tid - 50)] = pos_table[pi * 20 + (tid - 50)];
        else if (tid < 72) x[838 + (tid - 70)] = disg[t * 2 + (tid - 70)];
        else if (tid < 74) x[840 + (tid - 72)] = udisg[t * 2 + (tid - 72)];
    }
    __syncthreads();

    const float* Wks[5] = {Wk0, Wk1, Wk2, Wk3, Wk4};
    const float* Wvs[5] = {Wv0, Wv1, Wv2, Wv3, Wv4};
    const int dims[5] = {768, 50, 20, 2, 2};
    const int offs[5] = {0, 768, 818, 838, 840};

    const int o    = tid;
    const int mod  = o >> 7;
    const int half = (o >> 6) & 1;
    const int dk   = o & 63;
    float acc = 0.f;
    if (mod < 5) {
        const float* W  = half ? Wvs[mod] : Wks[mod];
        const float* xx = x + offs[mod];
        const int d = dims[mod];
        for (int i = 0; i < d; i++) acc += xx[i] * W[i * 64 + dk];
    }
    if (half == 0) g_keys[t * NELEM * DK + mod * DK + dk] = acc;
    else           g_vals[t * NELEM * DV + mod * DV + dk] = acc;
}

// ---------------------------------------------------------------------------
// Kernel 2: MI-RIM scan. 4-CTA cluster, Kahan-packed DF. 640 thr/CTA.
// ---------------------------------------------------------------------------
__global__ void __cluster_dims__(NCTA, 1, 1) __launch_bounds__(640, 1) scan_kernel(
    const float* __restrict__ blstm)
{
    __shared__ float  skt[NELEM * DK], svt[NELEM * DV];
    __shared__ float  sq_h[M * DK], sq_l[M * DK];
    __shared__ float  sat_h[M * 8], sat_l[M * 8];
    __shared__ float  sct_h[M * 8], sct_l[M * 8];
    __shared__ __align__(16) float sinp_h[M * DV];
    __shared__ __align__(16) float sinp_l[M * DV];
    __shared__ float  sgate_h[640], sgate_l[640];
    __shared__ float  sqc_h[M * DC], sqc_l[M * DC];
    __shared__ float  skc_h[M * DC], skc_l[M * DC];
    __shared__ float  svc_h[M * HSL], svc_l[M * HSL];
    __shared__ float  sc_h[M * HSL], sc_l[M * HSL];
    __shared__ __align__(16) float h1_h[M * H];
    __shared__ __align__(16) float h1_l[M * H];
    __shared__ __align__(16) float hc_h[M * H];
    __shared__ __align__(16) float hc_l[M * H];
    __shared__ float  smask[8];
    __shared__ int    ssel[4];

    const int tid  = threadIdx.x;
    const uint32_t rank = my_rank();
    const int HB = rank * HSL;
    const uint32_t a1h = smem_u32(h1_h), a1l = smem_u32(h1_l);
    const uint32_t a2h = smem_u32(hc_h), a2l = smem_u32(hc_l);
    const uint32_t aqh = smem_u32(sq_h), aql = smem_u32(sq_l);
    const uint32_t aqch = smem_u32(sqc_h), aqcl = smem_u32(sqc_l);
    const uint32_t akch = smem_u32(skc_h), akcl = smem_u32(skc_l);

    hc_h[tid] = 0.f; hc_l[tid] = 0.f;
    if (tid < M * HSL) { sc_h[tid] = 0.f; sc_l[tid] = 0.f; }
    __syncthreads();
    CLUSTER_BAR();

    for (int t = 0; t < T; ++t) {
        // ---- int1: keys/vals load + q-proj PARTITIONED across CTAs ----
        if (tid < NELEM * DK) {
            skt[tid] = g_keys[t * NELEM * DK + tid];
            svt[tid] = g_vals[t * NELEM * DV + tid];
        }
        {
            const int out  = rank * 80 + (tid >> 3);   // global (qm,dk), 80 per CTA
            const int part = tid & 7;                  // K-split-8 over 64 pairs
            const int qm = out >> 6, dk = out & 63;
            const u64* xh2 = (const u64*)(hc_h + qm * H);
            const u64* xl2 = (const u64*)(hc_l + qm * H);
            const u64* w2  = g_Wq2 + qm * 64 * DK + dk;
            u64 s2 = 0, c2 = 0;
            const int k0 = part * 8;
            #pragma unroll
            for (int k = k0; k < k0 + 8; k++) cacc2k(s2, c2, xh2[k], xl2[k], w2[k * DK]);
            DF r = df_from2k(s2, c2);
            r = df_red(r, 4); r = df_red(r, 2); r = df_red(r, 1);
            if (part == 0) {
                #pragma unroll
                for (int rk = 0; rk < NCTA; rk++) {
                    st_cluster_b32(aqh + out * 4, rk, __float_as_uint(r.h));
                    st_cluster_b32(aql + out * 4, rk, __float_as_uint(r.l));
                }
            }
        }
        CLUSTER_BAR();

        // ---- int2: attention logits, K-split-8 ----
        {
            const int gout = tid >> 3;
            const int part = tid & 7;
            const int out = gout < 30 ? gout : 29;
            const int am = out / NELEM, j = out - am * NELEM;
            const float* kk = skt + j * DK;
            const float* qh = sq_h + am * DK;
            const float* ql = sq_l + am * DK;
            float s = 0.f, c = 0.f;
            const int i0 = part * 8;
            #pragma unroll
            for (int i = i0; i < i0 + 8; i++) cacc(s, c, qh[i], ql[i], kk[i]);
            DF r = qts(s, c);
            r = df_red(r, 4); r = df_red(r, 2); r = df_red(r, 1);
            if (part == 0 && gout < 30) {
                sat_h[am * 8 + j] = r.h * 0.125f;
                sat_l[am * 8 + j] = r.l * 0.125f;
            }
        }
        __syncthreads();

        // ---- int3: softmax exp ----
        if (tid < M * NELEM) {
            const int sm = tid / NELEM, j = tid - sm * NELEM;
            DF v[NELEM];
            for (int k = 0; k < NELEM; k++) v[k] = {sat_h[sm * 8 + k], sat_l[sm * 8 + k]};
            DF mx = v[0];
            for (int k = 1; k < NELEM; k++) if (df_lt(mx, v[k])) mx = v[k];
            DF e = df_exp(df_sub(v[j], mx));
            sat_h[sm * 8 + j] = e.h; sat_l[sm * 8 + j] = e.l;
        }
        __syncthreads();

        // ---- int4: softmax normalize ----
        if (tid < M) {
            DF sum = {0.f, 0.f};
            for (int j = 0; j < NELEM; j++) sum = df_add(sum, {sat_h[tid * 8 + j], sat_l[tid * 8 + j]});
            DF inv = df_recip(sum);
            for (int j = 0; j < NELEM; j++) {
                DF a = df_mul({sat_h[tid * 8 + j], sat_l[tid * 8 + j]}, inv);
                sat_h[tid * 8 + j] = a.h; sat_l[tid * 8 + j] = a.l;
            }
        }
        __syncthreads();

        // ---- int5: top-3 mask + compact select list + E inp ----
        if (tid == 0) {
            DF nl[M]; bool used[M];
            for (int i = 0; i < M; i++) {
                nl[i] = {sat_h[i * 8 + (NELEM - 1)], sat_l[i * 8 + (NELEM - 1)]};
                used[i] = false; smask[i] = 0.f;
            }
            for (int r = 0; r < KTOP; r++) {
                int best = -1; DF bv = {0.f, 0.f};
                for (int i = 0; i < M; i++)
                    if (!used[i] && (best < 0 || df_lt(nl[i], bv))) { bv = nl[i]; best = i; }
                used[best] = true; smask[best] = 1.f;
            }
            int k = 0;
            for (int i = 0; i < M; i++) if (used[i]) ssel[k++] = i;
        }
        if (tid < M * DV) {
            const int em = tid >> 6, dv = tid & 63;
            float s = 0.f, c = 0.f;
            #pragma unroll
            for (int j = 0; j < NELEM; j++)
                cacc(s, c, sat_h[em * 8 + j], sat_l[em * 8 + j], svt[j * DV + dv]);
            DF r = qts(s, c);
            sinp_h[tid] = r.h; sinp_l[tid] = r.l;
        }
        __syncthreads();

        // ---- int6: gates — ONLY the 3 selected modules ----
        if (tid < KTOP * 128) {
            const int m = ssel[tid >> 7];
            const int r = tid & 127;
            const int gate = r >> 5;
            const int hl = r & 31;
            const int col = gate * H + HB + hl;
            const u64* w2 = g_W2 + (m * 96) * GH + col;
            u64 s2 = f_to_lo(blstm[m * GH + col]), c2 = 0;
            const u64* ih2 = (const u64*)(sinp_h + m * DV);
            const u64* il2 = (const u64*)(sinp_l + m * DV);
            #pragma unroll 4
            for (int v2 = 0; v2 < 32; v2++)
                cacc2k(s2, c2, ih2[v2], il2[v2], w2[v2 * GH]);
            const u64* hh2 = (const u64*)(hc_h + m * H);
            const u64* hl2 = (const u64*)(hc_l + m * H);
            #pragma unroll 4
            for (int v2 = 0; v2 < 64; v2++)
                cacc2k(s2, c2, hh2[v2], hl2[v2], w2[(32 + v2) * GH]);
            DF g = df_from2k(s2, c2);
            DF nlv = (gate == 2) ? df_tanh(g) : df_sigmoid(g);
            sgate_h[m * 128 + r] = nlv.h; sgate_l[m * 128 + r] = nlv.l;
        }
        __syncthreads();

        // ---- int7: LSTM update on owned slice + broadcast h1 ----
        if (tid < M * HSL) {
            const int m = tid >> 5, hl = tid & 31;
            const bool on = smask[m] > 0.5f;
            const int hg = m * H + HB + hl;
            DF h1, c1;
            if (on) {
                const int base = m * 128 + hl;
                DF ig = {sgate_h[base],      sgate_l[base]};
                DF fg = {sgate_h[base + 32], sgate_l[base + 32]};
                DF gt = {sgate_h[base + 64], sgate_l[base + 64]};
                DF og = {sgate_h[base + 96], sgate_l[base + 96]};
                DF cold = {sc_h[tid], sc_l[tid]};
                c1 = df_add(df_mul(fg, cold), df_mul(ig, gt));
                h1 = df_mul(og, df_tanh(c1));
            } else {
                h1 = {hc_h[hg], hc_l[hg]};
                c1 = {sc_h[tid], sc_l[tid]};
            }
            sc_h[tid] = c1.h; sc_l[tid] = c1.l;
            #pragma unroll
            for (int rk = 0; rk < NCTA; rk++) {
                st_cluster_b32(a1h + hg * 4, rk, __float_as_uint(h1.h));
                st_cluster_b32(a1l + hg * 4, rk, __float_as_uint(h1.l));
            }
        }
        CLUSTER_BAR();

        // ---- int8a: qc/kc PARTITIONED across CTAs (80 outputs, K-split-8) ----
        {
            const int out  = rank * 80 + (tid >> 3);    // 0..319 over cluster
            const int part = tid & 7;
            const int isK = out >= 160;
            const int o2 = isK ? out - 160 : out;
            const int pm = o2 >> 5, dc = o2 & 31;
            const u64* xh2 = (const u64*)(h1_h + pm * H);
            const u64* xl2 = (const u64*)(h1_l + pm * H);
            const u64* w2  = g_Wqkc2 + ((isK * 5 + pm) * 64) * DC + dc;
            u64 s2 = 0, c2 = 0;
            const int k0 = part * 8;
            #pragma unroll
            for (int k = k0; k < k0 + 8; k++) cacc2k(s2, c2, xh2[k], xl2[k], w2[k * DC]);
            DF r = df_from2k(s2, c2);
            r = df_red(r, 4); r = df_red(r, 2); r = df_red(r, 1);
            if (part == 0) {
                const uint32_t ah = (isK ? akch : aqch) + o2 * 4;
                const uint32_t al = (isK ? akcl : aqcl) + o2 * 4;
                #pragma unroll
                for (int rk = 0; rk < NCTA; rk++) {
                    st_cluster_b32(ah, rk, __float_as_uint(r.h));
                    st_cluster_b32(al, rk, __float_as_uint(r.l));
                }
            }
        }
        // ---- int8b: vc owned slice (160 outputs, K-split-4) ----
        {
            const int out = tid >> 2;                  // (j, hl)
            const int qrt = tid & 3;
            const int j = out >> 5, hl = out & 31;
            const u64* xh2 = (const u64*)(h1_h + j * H);
            const u64* xl2 = (const u64*)(h1_l + j * H);
            const u64* w2  = g_Wvc2 + j * 64 * H + HB + hl;
            u64 s2 = 0, c2 = 0;
            const int k0 = qrt * 16;
            #pragma unroll 4
            for (int k = k0; k < k0 + 16; k++) cacc2k(s2, c2, xh2[k], xl2[k], w2[k * H]);
            DF r = df_from2k(s2, c2);
            r = df_red(r, 2); r = df_red(r, 1);
            if (qrt == 0) { svc_h[out] = r.h; svc_l[out] = r.l; }
        }
        CLUSTER_BAR();

        // ---- int9: cattn logits (K-split-8) ----
        {
            const int gout = tid >> 3;
            const int part = tid & 7;
            const int out = gout < 25 ? gout : 24;
            const int im = out / M, j = out - im * M;
            float s = 0.f, c = 0.f;
            const int i0 = part * 4;
            #pragma unroll
            for (int i = i0; i < i0 + 4; i++)
                cacc_df(s, c, {sqc_h[im * DC + i], sqc_l[im * DC + i]},
                              {skc_h[j * DC + i],  skc_l[j * DC + i]});
            DF r = qts(s, c);
            r = df_red(r, 4); r = df_red(r, 2); r = df_red(r, 1);
            if (part == 0 && gout < 25) {
                DF sc = df_mul(r, {0.17677669227123260f, 3.0254043e-9f});
                sct_h[im * 8 + j] = sc.h; sct_l[im * 8 + j] = sc.l;
            }
        }
        __syncthreads();

        // ---- int10: cattn exp ----
        if (tid < M * M) {
            const int im = tid / M, j = tid - im * M;
            DF v[M];
            for (int k = 0; k < M; k++) v[k] = {sct_h[im * 8 + k], sct_l[im * 8 + k]};
            DF mx = v[0];
            for (int k = 1; k < M; k++) if (df_lt(mx, v[k])) mx = v[k];
            DF e = df_exp(df_sub(v[j], mx));
            sct_h[im * 8 + j] = e.h; sct_l[im * 8 + j] = e.l;
        }
        __syncthreads();

        // ---- int11: cattn normalize ----
        if (tid < M) {
            DF sum = {0.f, 0.f};
            for (int j = 0; j < M; j++) sum = df_add(sum, {sct_h[tid * 8 + j], sct_l[tid * 8 + j]});
            DF inv = df_recip(sum);
            for (int j = 0; j < M; j++) {
                DF a = df_mul({sct_h[tid * 8 + j], sct_l[tid * 8 + j]}, inv);
                sct_h[tid * 8 + j] = a.h; sct_l[tid * 8 + j] = a.l;
            }
        }
        __syncthreads();

        // ---- int12: h2 on owned slice + emit + broadcast carry ----
        if (tid < M * HSL) {
            const int m = tid >> 5, hl = tid & 31;
            float s = 0.f, c = 0.f;
            #pragma unroll
            for (int j = 0; j < M; j++)
                cacc_df(s, c, {sct_h[m * 8 + j], sct_l[m * 8 + j]},
                              {svc_h[j * HSL + hl], svc_l[j * HSL + hl]});
            DF dot = qts(s, c);
            const int hg = m * H + HB + hl;
            DF h1 = {h1_h[hg], h1_l[hg]};
            const bool on = smask[m] > 0.5f;
            DF h2 = on ? df_add(h1, dot) : h1;
            g_hidden[t * (M * H) + hg] = h2.h + h2.l;
            #pragma unroll
            for (int rk = 0; rk < NCTA; rk++) {
                st_cluster_b32(a2h + hg * 4, rk, __float_as_uint(h2.h));
                st_cluster_b32(a2l + hg * 4, rk, __float_as_uint(h2.l));
            }
        }
        CLUSTER_BAR();
    }
}

// ---------------------------------------------------------------------------
// Kernel 3: classifier (unchanged)
// ---------------------------------------------------------------------------
__global__ void cls_kernel(const float* __restrict__ Wcls,
                           const float* __restrict__ bcls,
                           float* __restrict__ out)
{
    const int warp = (blockIdx.x * blockDim.x + threadIdx.x) >> 5;
    const int lane = threadIdx.x & 31;
    if (warp >= T * 2) return;
    const int t = warp >> 1, c = warp & 1;
    const float* h = g_hidden + t * (M * H);
    float acc = 0.f;
    for (int i = lane; i < M * H; i += 32) acc += h[i] * Wcls[i * 2 + c];
    #pragma unroll
    for (int off = 16; off; off >>= 1) acc += __shfl_down_sync(0xffffffffu, acc, off);
    if (lane == 0) out[t * 2 + c] = acc + bcls[c];
}

// ---------------------------------------------------------------------------
extern "C" void kernel_launch(void* const* d_in, const int* in_sizes, int n_in,
                              void* d_out, int out_size)
{
    const float* bert  = (const float*)d_in[0];
    const int*   ui    = (const int*)  d_in[1];
    const int*   pi    = (const int*)  d_in[2];
    const float* disg  = (const float*)d_in[3];
    const float* udisg = (const float*)d_in[4];
    const float* utab  = (const float*)d_in[5];
    const float* ptab  = (const float*)d_in[6];
    const float* Wk0 = (const float*)d_in[7],  *Wv0 = (const float*)d_in[8];
    const float* Wk1 = (const float*)d_in[9],  *Wv1 = (const float*)d_in[10];
    const float* Wk2 = (const float*)d_in[11], *Wv2 = (const float*)d_in[12];
    const float* Wk3 = (const float*)d_in[13], *Wv3 = (const float*)d_in[14];
    const float* Wk4 = (const float*)d_in[15], *Wv4 = (const float*)d_in[16];
    const float* Wq    = (const float*)d_in[17];
    const float* Wih   = (const float*)d_in[18];
    const float* Whh   = (const float*)d_in[19];
    const float* blstm = (const float*)d_in[20];
    const float* Wqc   = (const float*)d_in[21];
    const float* Wkc   = (const float*)d_in[22];
    const float* Wvc   = (const float*)d_in[23];
    const float* Wcls  = (const float*)d_in[24];
    const float* bcls  = (const float*)d_in[25];

    pack_kernel<<<256, 256>>>(Wq, Wih, Whh, Wqc, Wkc, Wvc);
    proj_kernel<<<T, 768>>>(bert, ui, pi, disg, udisg, utab, ptab,
                            Wk0, Wv0, Wk1, Wv1, Wk2, Wv2, Wk3, Wv3, Wk4, Wv4);
    scan_kernel<<<NCTA, 640>>>(blstm);
    cls_kernel<<<32, 1024>>>(Wcls, bcls, (float*)d_out);
}

// round 8
// speedup vs baseline: 21.6990x; 1.1678x over previous
#include <cuda_runtime.h>
#include <math.h>
#include <stdint.h>

#define T 512
#define M 5
#define H 128
#define KTOP 3
#define DK 64
#define DV 64
#define DC 32
#define NELEM 6
#define GH 512
#define NCTA 4
#define HSL 32

typedef unsigned long long u64;

__device__ float g_keys[T * NELEM * DK];
__device__ float g_vals[T * NELEM * DV];
__device__ float g_hidden[T * M * H];
__device__ u64 g_W2[M * 96 * GH];
__device__ u64 g_Wq2[M * 64 * DK];
__device__ u64 g_Wqkc2[2 * M * 64 * DC];
__device__ u64 g_Wvc2[M * 64 * H];

// ===========================================================================
// Double-float primitives (proven R4-R7)
// ===========================================================================
struct DF { float h, l; };

__device__ __forceinline__ DF qts(float a, float b) {
    float s = a + b; float e = b - (s - a); return {s, e};
}
__device__ __forceinline__ DF tsum(float a, float b) {
    float s = a + b; float bb = s - a;
    float e = (a - (s - bb)) + (b - bb);
    return {s, e};
}
__device__ __forceinline__ DF tprod(float a, float b) {
    float p = a * b; float e = fmaf(a, b, -p); return {p, e};
}
__device__ __forceinline__ DF df_add(DF a, DF b) {
    DF s = tsum(a.h, b.h);
    return qts(s.h, s.l + (a.l + b.l));
}
__device__ __forceinline__ DF df_add_f(DF a, float b) {
    DF s = tsum(a.h, b);
    return qts(s.h, s.l + a.l);
}
__device__ __forceinline__ DF df_sub(DF a, DF b) { return df_add(a, {-b.h, -b.l}); }
__device__ __forceinline__ DF df_mul(DF a, DF b) {
    DF p = tprod(a.h, b.h);
    float l = p.l + (a.h * b.l + a.l * b.h);
    return qts(p.h, l);
}
__device__ __forceinline__ DF df_recip(DF d) {
    float y0 = __frcp_rn(d.h);
    DF p = tprod(d.h, y0);
    float e = (1.0f - p.h) - p.l;
    e = fmaf(-d.l, y0, e);
    return qts(y0, y0 * e);
}
__device__ __forceinline__ bool df_lt(DF a, DF b) {
    return (a.h < b.h) || (a.h == b.h && a.l < b.l);
}
__device__ __forceinline__ void cacc(float& s, float& c, float xh, float xl, float w) {
    float p = xh * w;
    float e = fmaf(xh, w, -p);
    e = fmaf(xl, w, e);
    float t = s + p;
    float bb = t - s;
    c += ((s - (t - bb)) + (p - bb)) + e;
    s = t;
}
__device__ __forceinline__ void cacc_df(float& s, float& c, DF a, DF b) {
    float p = a.h * b.h;
    float e = fmaf(a.h, b.h, -p);
    e = fmaf(a.h, b.l, e);
    e = fmaf(a.l, b.h, e);
    float t = s + p;
    float bb = t - s;
    c += ((s - (t - bb)) + (p - bb)) + e;
    s = t;
}
__device__ __forceinline__ DF df_exp(DF x) {
    if (x.h > 30.f)  { x.h = 30.f;  x.l = 0.f; }
    if (x.h < -30.f) { x.h = -30.f; x.l = 0.f; }
    const float kf = rintf(x.h * 1.4426950408889634f);
    const float th = fmaf(-kf, 0.693145751953125f, x.h);
    const float tl = fmaf(-kf, 1.4286068203094172e-6f, x.l);
    float B = 2.7557319e-6f;
    B = fmaf(B, th, 2.4801587e-5f);
    B = fmaf(B, th, 1.9841270e-4f);
    B = fmaf(B, th, 1.3888889e-3f);
    B = fmaf(B, th, 8.3333333e-3f);
    B = fmaf(B, th, 4.1666667e-2f);
    DF t2 = tprod(th, th);
    DF t3 = tprod(t2.h, th);
    t3.l = fmaf(t2.l, th, t3.l);
    DF q = tprod(t3.h, 0.16666667f);
    q.l = fmaf(t3.h, -4.9670537e-9f, q.l);
    q.l = fmaf(t3.l, 0.16666667f, q.l);
    const float f4 = t2.h * t2.h * B;
    DF S = qts(1.0f, th);
    S = df_add(S, {t2.h * 0.5f, t2.l * 0.5f});
    S = df_add(S, q);
    S.l += f4;
    S.l = fmaf(S.h, tl, S.l);
    S = qts(S.h, S.l);
    const float sc = __int_as_float(((int)kf + 127) << 23);
    S.h *= sc; S.l *= sc;
    return S;
}
__device__ __forceinline__ DF df_sigmoid(DF x) {
    DF E = df_exp({-x.h, -x.l});
    return df_recip(df_add_f(E, 1.0f));
}
__device__ __forceinline__ DF df_tanh(DF x) {
    const float sgn = (x.h < 0.f) ? -1.f : 1.f;
    DF a = {sgn * x.h, sgn * x.l};
    DF E = df_exp({2.f * a.h, 2.f * a.l});
    DF r = df_recip(df_add_f(E, 1.0f));
    DF res = tsum(1.0f, -2.f * r.h);
    DF o = qts(res.h, res.l - 2.f * r.l);
    return {sgn * o.h, sgn * o.l};
}
__device__ __forceinline__ DF df_red(DF a, unsigned off) {
    float oh = __shfl_down_sync(0xffffffffu, a.h, off);
    float ol = __shfl_down_sync(0xffffffffu, a.l, off);
    return df_add(a, {oh, ol});
}

// ===========================================================================
// Packed Kahan chain (all fma.rn.f32x2). Value = s - c.
// ===========================================================================
#define PK_ONE2  0x3F8000003F800000ull
#define PK_M1_2  0xBF800000BF800000ull
__device__ __forceinline__ u64 f2fma(u64 a, u64 b, u64 c) {
    u64 r; asm("fma.rn.f32x2 %0, %1, %2, %3;" : "=l"(r) : "l"(a), "l"(b), "l"(c)); return r;
}
__device__ __forceinline__ u64 f2neg(u64 a) { return a ^ 0x8000000080000000ull; }

__device__ __forceinline__ void cacc2k(u64& s2, u64& c2, u64 xh2, u64 xl2, u64 w2) {
    u64 p  = f2fma(xh2, w2, 0ull);
    u64 e  = f2fma(xh2, w2, f2neg(p));
    e      = f2fma(xl2, w2, e);
    u64 cm = f2fma(e, PK_M1_2, c2);
    u64 y  = f2fma(cm, PK_M1_2, p);
    u64 t  = f2fma(s2, PK_ONE2, y);
    u64 d  = f2fma(s2, PK_M1_2, t);
    c2     = f2fma(y, PK_M1_2, d);
    s2 = t;
}
__device__ __forceinline__ DF df_from2k(u64 s2, u64 c2) {
    c2 = f2neg(c2);
    float se = __uint_as_float((unsigned)s2), so = __uint_as_float((unsigned)(s2 >> 32));
    float ce = __uint_as_float((unsigned)c2), co = __uint_as_float((unsigned)(c2 >> 32));
    DF re = tsum(se, ce); re = qts(re.h, re.l);
    DF ro = tsum(so, co); ro = qts(ro.h, ro.l);
    return df_add(re, ro);
}
__device__ __forceinline__ u64 f_to_lo(float a) { return (u64)__float_as_uint(a); }

// Cluster helpers
__device__ __forceinline__ uint32_t smem_u32(const void* p) {
    uint32_t a;
    asm("{ .reg .u64 t; cvta.to.shared.u64 t, %1; cvt.u32.u64 %0, t; }" : "=r"(a) : "l"(p));
    return a;
}
__device__ __forceinline__ uint32_t my_rank() {
    uint32_t r; asm("mov.u32 %0, %%cluster_ctarank;" : "=r"(r)); return r;
}
__device__ __forceinline__ void st_cluster_b32(uint32_t saddr, uint32_t rank, uint32_t v) {
    uint32_t ra;
    asm volatile("mapa.shared::cluster.u32 %0, %1, %2;" : "=r"(ra) : "r"(saddr), "r"(rank));
    asm volatile("st.shared::cluster.b32 [%0], %1;" :: "r"(ra), "r"(v) : "memory");
}
#define CLUSTER_BAR() do { \
    asm volatile("barrier.cluster.arrive.aligned;" ::: "memory"); \
    asm volatile("barrier.cluster.wait.aligned;"   ::: "memory"); } while (0)

// ---------------------------------------------------------------------------
// Kernel 0: pack weights (unchanged)
// ---------------------------------------------------------------------------
__global__ void pack_kernel(const float* __restrict__ Wq,
                            const float* __restrict__ Wih,
                            const float* __restrict__ Whh,
                            const float* __restrict__ Wqc,
                            const float* __restrict__ Wkc,
                            const float* __restrict__ Wvc)
{
    const int stride = gridDim.x * blockDim.x;
    const int i0 = blockIdx.x * blockDim.x + threadIdx.x;
    for (int idx = i0; idx < M * 96 * GH; idx += stride) {
        const int col = idx % GH;
        const int r = idx / GH;
        const int v2 = r % 96, m = r / 96;
        const int r0 = 2 * v2, r1 = r0 + 1;
        const float e = (r0 < 64) ? Wih[(m * DV + r0) * GH + col] : Whh[(m * H + r0 - 64) * GH + col];
        const float o = (r1 < 64) ? Wih[(m * DV + r1) * GH + col] : Whh[(m * H + r1 - 64) * GH + col];
        g_W2[idx] = ((u64)__float_as_uint(o) << 32) | __float_as_uint(e);
    }
    for (int idx = i0; idx < M * 64 * DK; idx += stride) {
        const int dk = idx % DK;
        const int r = idx / DK;
        const int i2 = r % 64, m = r / 64;
        const float e = Wq[(m * H + 2 * i2) * DK + dk];
        const float o = Wq[(m * H + 2 * i2 + 1) * DK + dk];
        g_Wq2[idx] = ((u64)__float_as_uint(o) << 32) | __float_as_uint(e);
    }
    for (int idx = i0; idx < 2 * M * 64 * DC; idx += stride) {
        const int dc = idx % DC;
        const int r = idx / DC;
        const int k = r % 64;
        const int pm = (r / 64) % M;
        const int sel = r / (64 * M);
        const float* W = sel ? Wkc : Wqc;
        const float e = W[(pm * H + 2 * k) * DC + dc];
        const float o = W[(pm * H + 2 * k + 1) * DC + dc];
        g_Wqkc2[idx] = ((u64)__float_as_uint(o) << 32) | __float_as_uint(e);
    }
    for (int idx = i0; idx < M * 64 * H; idx += stride) {
        const int hv = idx % H;
        const int r = idx / H;
        const int i2 = r % 64, j = r / 64;
        const float e = Wvc[(j * H + 2 * i2) * H + hv];
        const float o = Wvc[(j * H + 2 * i2 + 1) * H + hv];
        g_Wvc2[idx] = ((u64)__float_as_uint(o) << 32) | __float_as_uint(e);
    }
}

// ---------------------------------------------------------------------------
// Kernel 1: modality projections (unchanged)
// ---------------------------------------------------------------------------
__global__ void __launch_bounds__(768) proj_kernel(
    const float* __restrict__ bert,
    const int*   __restrict__ umls_idx,
    const int*   __restrict__ pos_idx,
    const float* __restrict__ disg,
    const float* __restrict__ udisg,
    const float* __restrict__ umls_table,
    const float* __restrict__ pos_table,
    const float* __restrict__ Wk0, const float* __restrict__ Wv0,
    const float* __restrict__ Wk1, const float* __restrict__ Wv1,
    const float* __restrict__ Wk2, const float* __restrict__ Wv2,
    const float* __restrict__ Wk3, const float* __restrict__ Wv3,
    const float* __restrict__ Wk4, const float* __restrict__ Wv4)
{
    __shared__ float x[768 + 50 + 20 + 2 + 2];
    const int t = blockIdx.x;
    const int tid = threadIdx.x;

    x[tid] = bert[t * 768 + tid];
    {
        const long ui = (long)umls_idx[t];
        const int  pi = pos_idx[t];
        if (tid < 50) x[768 + tid] = umls_table[ui * 50 + tid];
        else if (tid < 70) x[818 + (tid - 50)] = pos_table[pi * 20 + (tid - 50)];
        else if (tid < 72) x[838 + (tid - 70)] = disg[t * 2 + (tid - 70)];
        else if (tid < 74) x[840 + (tid - 72)] = udisg[t * 2 + (tid - 72)];
    }
    __syncthreads();

    const float* Wks[5] = {Wk0, Wk1, Wk2, Wk3, Wk4};
    const float* Wvs[5] = {Wv0, Wv1, Wv2, Wv3, Wv4};
    const int dims[5] = {768, 50, 20, 2, 2};
    const int offs[5] = {0, 768, 818, 838, 840};

    const int o    = tid;
    const int mod  = o >> 7;
    const int half = (o >> 6) & 1;
    const int dk   = o & 63;
    float acc = 0.f;
    if (mod < 5) {
        const float* W  = half ? Wvs[mod] : Wks[mod];
        const float* xx = x + offs[mod];
        const int d = dims[mod];
        for (int i = 0; i < d; i++) acc += xx[i] * W[i * 64 + dk];
    }
    if (half == 0) g_keys[t * NELEM * DK + mod * DK + dk] = acc;
    else           g_vals[t * NELEM * DV + mod * DV + dk] = acc;
}

// ---------------------------------------------------------------------------
// Kernel 2: MI-RIM scan. 4-CTA cluster, fused-softmax, chunked loads.
// ---------------------------------------------------------------------------
__global__ void __cluster_dims__(NCTA, 1, 1) __launch_bounds__(640, 1) scan_kernel(
    const float* __restrict__ blstm)
{
    __shared__ float  skt[NELEM * DK], svt[NELEM * DV];
    __shared__ float  sq_h[M * DK], sq_l[M * DK];
    __shared__ float  sat_h[M * 8], sat_l[M * 8];      // exp(logit), unnormalized
    __shared__ float  sct_h[M * 8], sct_l[M * 8];      // exp(cattn logit), unnormalized
    __shared__ float  sinv_h[8], sinv_l[8];            // 1/sum per module (attn)
    __shared__ __align__(16) float sinp_h[M * DV];
    __shared__ __align__(16) float sinp_l[M * DV];
    __shared__ float  sgate_h[640], sgate_l[640];
    __shared__ float  sqc_h[M * DC], sqc_l[M * DC];
    __shared__ float  skc_h[M * DC], skc_l[M * DC];
    __shared__ float  svc_h[M * HSL], svc_l[M * HSL];
    __shared__ float  sc_h[M * HSL], sc_l[M * HSL];
    __shared__ __align__(16) float h1_h[M * H];
    __shared__ __align__(16) float h1_l[M * H];
    __shared__ __align__(16) float hc_h[M * H];
    __shared__ __align__(16) float hc_l[M * H];
    __shared__ float  smask[8];
    __shared__ int    ssel[4];

    const int tid  = threadIdx.x;
    const uint32_t rank = my_rank();
    const int HB = rank * HSL;
    const uint32_t a1h = smem_u32(h1_h), a1l = smem_u32(h1_l);
    const uint32_t a2h = smem_u32(hc_h), a2l = smem_u32(hc_l);
    const uint32_t aqh = smem_u32(sq_h), aql = smem_u32(sq_l);
    const uint32_t aqch = smem_u32(sqc_h), aqcl = smem_u32(sqc_l);
    const uint32_t akch = smem_u32(skc_h), akcl = smem_u32(skc_l);

    hc_h[tid] = 0.f; hc_l[tid] = 0.f;
    if (tid < M * HSL) { sc_h[tid] = 0.f; sc_l[tid] = 0.f; }
    __syncthreads();
    CLUSTER_BAR();

    for (int t = 0; t < T; ++t) {
        // ---- int1: keys/vals load + q-proj PARTITIONED across CTAs ----
        if (tid < NELEM * DK) {
            skt[tid] = g_keys[t * NELEM * DK + tid];
            svt[tid] = g_vals[t * NELEM * DV + tid];
        }
        {
            const int out  = rank * 80 + (tid >> 3);
            const int part = tid & 7;
            const int qm = out >> 6, dk = out & 63;
            const u64* xh2 = (const u64*)(hc_h + qm * H);
            const u64* xl2 = (const u64*)(hc_l + qm * H);
            const u64* w2  = g_Wq2 + qm * 64 * DK + dk;
            const int k0 = part * 8;
            u64 wb[8];
            #pragma unroll
            for (int k = 0; k < 8; k++) wb[k] = w2[(k0 + k) * DK];
            u64 s2 = 0, c2 = 0;
            #pragma unroll
            for (int k = 0; k < 8; k++) cacc2k(s2, c2, xh2[k0 + k], xl2[k0 + k], wb[k]);
            DF r = df_from2k(s2, c2);
            r = df_red(r, 4); r = df_red(r, 2); r = df_red(r, 1);
            if (part == 0) {
                #pragma unroll
                for (int rk = 0; rk < NCTA; rk++) {
                    st_cluster_b32(aqh + out * 4, rk, __float_as_uint(r.h));
                    st_cluster_b32(aql + out * 4, rk, __float_as_uint(r.l));
                }
            }
        }
        CLUSTER_BAR();

        // ---- int2: attention logits + FUSED exp (no max-shift; softmax is
        //      shift-invariant and logits are O(0.1)) ----
        {
            const int gout = tid >> 3;
            const int part = tid & 7;
            const int out = gout < 30 ? gout : 29;
            const int am = out / NELEM, j = out - am * NELEM;
            const float* kk = skt + j * DK;
            const float* qh = sq_h + am * DK;
            const float* ql = sq_l + am * DK;
            float s = 0.f, c = 0.f;
            const int i0 = part * 8;
            #pragma unroll
            for (int i = i0; i < i0 + 8; i++) cacc(s, c, qh[i], ql[i], kk[i]);
            DF r = qts(s, c);
            r = df_red(r, 4); r = df_red(r, 2); r = df_red(r, 1);
            if (part == 0 && gout < 30) {
                DF e = df_exp({r.h * 0.125f, r.l * 0.125f});
                sat_h[am * 8 + j] = e.h; sat_l[am * 8 + j] = e.l;
            }
        }
        __syncthreads();

        // ---- int3a: per-module inv-sum (5 thr) + unnormalized inp dots ----
        if (tid >= 512 && tid < 512 + M) {
            const int m = tid - 512;
            DF sum = {sat_h[m * 8], sat_l[m * 8]};
            for (int j = 1; j < NELEM; j++) sum = df_add(sum, {sat_h[m * 8 + j], sat_l[m * 8 + j]});
            DF inv = df_recip(sum);
            sinv_h[m] = inv.h; sinv_l[m] = inv.l;
        }
        if (tid < M * DV) {
            const int em = tid >> 6, dv = tid & 63;
            float s = 0.f, c = 0.f;
            #pragma unroll
            for (int j = 0; j < NELEM; j++)
                cacc(s, c, sat_h[em * 8 + j], sat_l[em * 8 + j], svt[j * DV + dv]);
            DF r = qts(s, c);
            sinp_h[tid] = r.h; sinp_l[tid] = r.l;
        }
        __syncthreads();

        // ---- int3b: topk (tid 512) + normalize inp by inv-sum ----
        if (tid == 512) {
            DF nl[M]; bool used[M];
            for (int i = 0; i < M; i++) {
                nl[i] = df_mul({sat_h[i * 8 + (NELEM - 1)], sat_l[i * 8 + (NELEM - 1)]},
                               {sinv_h[i], sinv_l[i]});
                used[i] = false; smask[i] = 0.f;
            }
            for (int r = 0; r < KTOP; r++) {
                int best = -1; DF bv = {0.f, 0.f};
                for (int i = 0; i < M; i++)
                    if (!used[i] && (best < 0 || df_lt(nl[i], bv))) { bv = nl[i]; best = i; }
                used[best] = true; smask[best] = 1.f;
            }
            int k = 0;
            for (int i = 0; i < M; i++) if (used[i]) ssel[k++] = i;
        }
        if (tid < M * DV) {
            const int em = tid >> 6;
            DF r = df_mul({sinp_h[tid], sinp_l[tid]}, {sinv_h[em], sinv_l[em]});
            sinp_h[tid] = r.h; sinp_l[tid] = r.l;
        }
        __syncthreads();

        // ---- int6: gates (3 selected modules), chunked weight prefetch ----
        if (tid < KTOP * 128) {
            const int m = ssel[tid >> 7];
            const int r = tid & 127;
            const int gate = r >> 5;
            const int hl = r & 31;
            const int col = gate * H + HB + hl;
            const u64* w2 = g_W2 + (m * 96) * GH + col;
            u64 s2 = f_to_lo(blstm[m * GH + col]), c2 = 0;
            const u64* ih2 = (const u64*)(sinp_h + m * DV);
            const u64* il2 = (const u64*)(sinp_l + m * DV);
            const u64* hh2 = (const u64*)(hc_h + m * H);
            const u64* hl2 = (const u64*)(hc_l + m * H);
            #pragma unroll
            for (int ch = 0; ch < 6; ch++) {
                u64 wb[16];
                #pragma unroll
                for (int k = 0; k < 16; k++) wb[k] = w2[(ch * 16 + k) * GH];
                #pragma unroll
                for (int k = 0; k < 16; k++) {
                    const int row = ch * 16 + k;
                    u64 xh, xl;
                    if (row < 32) { xh = ih2[row]; xl = il2[row]; }
                    else          { xh = hh2[row - 32]; xl = hl2[row - 32]; }
                    cacc2k(s2, c2, xh, xl, wb[k]);
                }
            }
            DF g = df_from2k(s2, c2);
            DF nlv = (gate == 2) ? df_tanh(g) : df_sigmoid(g);
            sgate_h[m * 128 + r] = nlv.h; sgate_l[m * 128 + r] = nlv.l;
        }
        __syncthreads();

        // ---- int7: LSTM update on owned slice + broadcast h1 ----
        if (tid < M * HSL) {
            const int m = tid >> 5, hl = tid & 31;
            const bool on = smask[m] > 0.5f;
            const int hg = m * H + HB + hl;
            DF h1, c1;
            if (on) {
                const int base = m * 128 + hl;
                DF ig = {sgate_h[base],      sgate_l[base]};
                DF fg = {sgate_h[base + 32], sgate_l[base + 32]};
                DF gt = {sgate_h[base + 64], sgate_l[base + 64]};
                DF og = {sgate_h[base + 96], sgate_l[base + 96]};
                DF cold = {sc_h[tid], sc_l[tid]};
                c1 = df_add(df_mul(fg, cold), df_mul(ig, gt));
                h1 = df_mul(og, df_tanh(c1));
            } else {
                h1 = {hc_h[hg], hc_l[hg]};
                c1 = {sc_h[tid], sc_l[tid]};
            }
            sc_h[tid] = c1.h; sc_l[tid] = c1.l;
            #pragma unroll
            for (int rk = 0; rk < NCTA; rk++) {
                st_cluster_b32(a1h + hg * 4, rk, __float_as_uint(h1.h));
                st_cluster_b32(a1l + hg * 4, rk, __float_as_uint(h1.l));
            }
        }
        CLUSTER_BAR();

        // ---- int8a: qc/kc PARTITIONED (80 outs, K-split-8, batched loads) ----
        {
            const int out  = rank * 80 + (tid >> 3);
            const int part = tid & 7;
            const int isK = out >= 160;
            const int o2 = isK ? out - 160 : out;
            const int pm = o2 >> 5, dc = o2 & 31;
            const u64* xh2 = (const u64*)(h1_h + pm * H);
            const u64* xl2 = (const u64*)(h1_l + pm * H);
            const u64* w2  = g_Wqkc2 + ((isK * 5 + pm) * 64) * DC + dc;
            const int k0 = part * 8;
            u64 wb[8];
            #pragma unroll
            for (int k = 0; k < 8; k++) wb[k] = w2[(k0 + k) * DC];
            u64 s2 = 0, c2 = 0;
            #pragma unroll
            for (int k = 0; k < 8; k++) cacc2k(s2, c2, xh2[k0 + k], xl2[k0 + k], wb[k]);
            DF r = df_from2k(s2, c2);
            r = df_red(r, 4); r = df_red(r, 2); r = df_red(r, 1);
            if (part == 0) {
                const uint32_t ah = (isK ? akch : aqch) + o2 * 4;
                const uint32_t al = (isK ? akcl : aqcl) + o2 * 4;
                #pragma unroll
                for (int rk = 0; rk < NCTA; rk++) {
                    st_cluster_b32(ah, rk, __float_as_uint(r.h));
                    st_cluster_b32(al, rk, __float_as_uint(r.l));
                }
            }
        }
        // ---- int8b: vc owned slice (160 outs, K-split-4, batched loads) ----
        {
            const int out = tid >> 2;
            const int qrt = tid & 3;
            const int j = out >> 5, hl = out & 31;
            const u64* xh2 = (const u64*)(h1_h + j * H);
            const u64* xl2 = (const u64*)(h1_l + j * H);
            const u64* w2  = g_Wvc2 + j * 64 * H + HB + hl;
            const int k0 = qrt * 16;
            u64 wb[16];
            #pragma unroll
            for (int k = 0; k < 16; k++) wb[k] = w2[(k0 + k) * H];
            u64 s2 = 0, c2 = 0;
            #pragma unroll
            for (int k = 0; k < 16; k++) cacc2k(s2, c2, xh2[k0 + k], xl2[k0 + k], wb[k]);
            DF r = df_from2k(s2, c2);
            r = df_red(r, 2); r = df_red(r, 1);
            if (qrt == 0) { svc_h[out] = r.h; svc_l[out] = r.l; }
        }
        CLUSTER_BAR();

        // ---- int9: cattn logits + FUSED exp ----
        {
            const int gout = tid >> 3;
            const int part = tid & 7;
            const int out = gout < 25 ? gout : 24;
            const int im = out / M, j = out - im * M;
            float s = 0.f, c = 0.f;
            const int i0 = part * 4;
            #pragma unroll
            for (int i = i0; i < i0 + 4; i++)
                cacc_df(s, c, {sqc_h[im * DC + i], sqc_l[im * DC + i]},
                              {skc_h[j * DC + i],  skc_l[j * DC + i]});
            DF r = qts(s, c);
            r = df_red(r, 4); r = df_red(r, 2); r = df_red(r, 1);
            if (part == 0 && gout < 25) {
                DF sc = df_mul(r, {0.17677669227123260f, 3.0254043e-9f});
                DF e = df_exp(sc);
                sct_h[im * 8 + j] = e.h; sct_l[im * 8 + j] = e.l;
            }
        }
        __syncthreads();

        // ---- int12: fused normalize + h2 + emit + broadcast ----
        if (tid < M * HSL) {
            const int m = tid >> 5, hl = tid & 31;
            DF sum = {sct_h[m * 8], sct_l[m * 8]};
            #pragma unroll
            for (int j = 1; j < M; j++) sum = df_add(sum, {sct_h[m * 8 + j], sct_l[m * 8 + j]});
            DF inv = df_recip(sum);
            float s = 0.f, c = 0.f;
            #pragma unroll
            for (int j = 0; j < M; j++)
                cacc_df(s, c, {sct_h[m * 8 + j], sct_l[m * 8 + j]},
                              {svc_h[j * HSL + hl], svc_l[j * HSL + hl]});
            DF dot = df_mul(qts(s, c), inv);
            const int hg = m * H + HB + hl;
            DF h1 = {h1_h[hg], h1_l[hg]};
            const bool on = smask[m] > 0.5f;
            DF h2 = on ? df_add(h1, dot) : h1;
            g_hidden[t * (M * H) + hg] = h2.h + h2.l;
            #pragma unroll
            for (int rk = 0; rk < NCTA; rk++) {
                st_cluster_b32(a2h + hg * 4, rk, __float_as_uint(h2.h));
                st_cluster_b32(a2l + hg * 4, rk, __float_as_uint(h2.l));
            }
        }
        CLUSTER_BAR();
    }
}

// ---------------------------------------------------------------------------
// Kernel 3: classifier (unchanged)
// ---------------------------------------------------------------------------
__global__ void cls_kernel(const float* __restrict__ Wcls,
                           const float* __restrict__ bcls,
                           float* __restrict__ out)
{
    const int warp = (blockIdx.x * blockDim.x + threadIdx.x) >> 5;
    const int lane = threadIdx.x & 31;
    if (warp >= T * 2) return;
    const int t = warp >> 1, c = warp & 1;
    const float* h = g_hidden + t * (M * H);
    float acc = 0.f;
    for (int i = lane; i < M * H; i += 32) acc += h[i] * Wcls[i * 2 + c];
    #pragma unroll
    for (int off = 16; off; off >>= 1) acc += __shfl_down_sync(0xffffffffu, acc, off);
    if (lane == 0) out[t * 2 + c] = acc + bcls[c];
}

// ---------------------------------------------------------------------------
extern "C" void kernel_launch(void* const* d_in, const int* in_sizes, int n_in,
                              void* d_out, int out_size)
{
    const float* bert  = (const float*)d_in[0];
    const int*   ui    = (const int*)  d_in[1];
    const int*   pi    = (const int*)  d_in[2];
    const float* disg  = (const float*)d_in[3];
    const float* udisg = (const float*)d_in[4];
    const float* utab  = (const float*)d_in[5];
    const float* ptab  = (const float*)d_in[6];
    const float* Wk0 = (const float*)d_in[7],  *Wv0 = (const float*)d_in[8];
    const float* Wk1 = (const float*)d_in[9],  *Wv1 = (const float*)d_in[10];
    const float* Wk2 = (const float*)d_in[11], *Wv2 = (const float*)d_in[12];
    const float* Wk3 = (const float*)d_in[13], *Wv3 = (const float*)d_in[14];
    const float* Wk4 = (const float*)d_in[15], *Wv4 = (const float*)d_in[16];
    const float* Wq    = (const float*)d_in[17];
    const float* Wih   = (const float*)d_in[18];
    const float* Whh   = (const float*)d_in[19];
    const float* blstm = (const float*)d_in[20];
    const float* Wqc   = (const float*)d_in[21];
    const float* Wkc   = (const float*)d_in[22];
    const float* Wvc   = (const float*)d_in[23];
    const float* Wcls  = (const float*)d_in[24];
    const float* bcls  = (const float*)d_in[25];

    pack_kernel<<<256, 256>>>(Wq, Wih, Whh, Wqc, Wkc, Wvc);
    proj_kernel<<<T, 768>>>(bert, ui, pi, disg, udisg, utab, ptab,
                            Wk0, Wv0, Wk1, Wv1, Wk2, Wv2, Wk3, Wv3, Wk4, Wv4);
    scan_kernel<<<NCTA, 640>>>(blstm);
    cls_kernel<<<32, 1024>>>(Wcls, bcls, (float*)d_out);
}

// round 9
// speedup vs baseline: 25.3127x; 1.1665x over previous
#include <cuda_runtime.h>
#include <math.h>
#include <stdint.h>

#define T 512
#define M 5
#define H 128
#define KTOP 3
#define DK 64
#define DV 64
#define DC 32
#define NELEM 6
#define GH 512
#define NCTA 8
#define HSL 16

typedef unsigned long long u64;

__device__ float g_keys[T * NELEM * DK];
__device__ float g_vals[T * NELEM * DV];
__device__ float g_hidden[T * M * H];
__device__ u64 g_W2[M * 96 * GH];
__device__ u64 g_Wq2[M * 64 * DK];
__device__ u64 g_Wqkc2[2 * M * 64 * DC];
__device__ u64 g_Wvc2[M * 64 * H];

// ===========================================================================
// Double-float primitives (proven R4-R8)
// ===========================================================================
struct DF { float h, l; };

__device__ __forceinline__ DF qts(float a, float b) {
    float s = a + b; float e = b - (s - a); return {s, e};
}
__device__ __forceinline__ DF tsum(float a, float b) {
    float s = a + b; float bb = s - a;
    float e = (a - (s - bb)) + (b - bb);
    return {s, e};
}
__device__ __forceinline__ DF tprod(float a, float b) {
    float p = a * b; float e = fmaf(a, b, -p); return {p, e};
}
__device__ __forceinline__ DF df_add(DF a, DF b) {
    DF s = tsum(a.h, b.h);
    return qts(s.h, s.l + (a.l + b.l));
}
__device__ __forceinline__ DF df_add_f(DF a, float b) {
    DF s = tsum(a.h, b);
    return qts(s.h, s.l + a.l);
}
__device__ __forceinline__ DF df_sub(DF a, DF b) { return df_add(a, {-b.h, -b.l}); }
__device__ __forceinline__ DF df_mul(DF a, DF b) {
    DF p = tprod(a.h, b.h);
    float l = p.l + (a.h * b.l + a.l * b.h);
    return qts(p.h, l);
}
__device__ __forceinline__ DF df_recip(DF d) {
    float y0 = __frcp_rn(d.h);
    DF p = tprod(d.h, y0);
    float e = (1.0f - p.h) - p.l;
    e = fmaf(-d.l, y0, e);
    return qts(y0, y0 * e);
}
__device__ __forceinline__ bool df_lt(DF a, DF b) {
    return (a.h < b.h) || (a.h == b.h && a.l < b.l);
}
__device__ __forceinline__ void cacc(float& s, float& c, float xh, float xl, float w) {
    float p = xh * w;
    float e = fmaf(xh, w, -p);
    e = fmaf(xl, w, e);
    float t = s + p;
    float bb = t - s;
    c += ((s - (t - bb)) + (p - bb)) + e;
    s = t;
}
__device__ __forceinline__ void cacc_df(float& s, float& c, DF a, DF b) {
    float p = a.h * b.h;
    float e = fmaf(a.h, b.h, -p);
    e = fmaf(a.h, b.l, e);
    e = fmaf(a.l, b.h, e);
    float t = s + p;
    float bb = t - s;
    c += ((s - (t - bb)) + (p - bb)) + e;
    s = t;
}
__device__ __forceinline__ DF df_exp(DF x) {
    if (x.h > 30.f)  { x.h = 30.f;  x.l = 0.f; }
    if (x.h < -30.f) { x.h = -30.f; x.l = 0.f; }
    const float kf = rintf(x.h * 1.4426950408889634f);
    const float th = fmaf(-kf, 0.693145751953125f, x.h);
    const float tl = fmaf(-kf, 1.4286068203094172e-6f, x.l);
    float B = 2.7557319e-6f;
    B = fmaf(B, th, 2.4801587e-5f);
    B = fmaf(B, th, 1.9841270e-4f);
    B = fmaf(B, th, 1.3888889e-3f);
    B = fmaf(B, th, 8.3333333e-3f);
    B = fmaf(B, th, 4.1666667e-2f);
    DF t2 = tprod(th, th);
    DF t3 = tprod(t2.h, th);
    t3.l = fmaf(t2.l, th, t3.l);
    DF q = tprod(t3.h, 0.16666667f);
    q.l = fmaf(t3.h, -4.9670537e-9f, q.l);
    q.l = fmaf(t3.l, 0.16666667f, q.l);
    const float f4 = t2.h * t2.h * B;
    DF S = qts(1.0f, th);
    S = df_add(S, {t2.h * 0.5f, t2.l * 0.5f});
    S = df_add(S, q);
    S.l += f4;
    S.l = fmaf(S.h, tl, S.l);
    S = qts(S.h, S.l);
    const float sc = __int_as_float(((int)kf + 127) << 23);
    S.h *= sc; S.l *= sc;
    return S;
}
__device__ __forceinline__ DF df_sigmoid(DF x) {
    DF E = df_exp({-x.h, -x.l});
    return df_recip(df_add_f(E, 1.0f));
}
__device__ __forceinline__ DF df_tanh(DF x) {
    const float sgn = (x.h < 0.f) ? -1.f : 1.f;
    DF a = {sgn * x.h, sgn * x.l};
    DF E = df_exp({2.f * a.h, 2.f * a.l});
    DF r = df_recip(df_add_f(E, 1.0f));
    DF res = tsum(1.0f, -2.f * r.h);
    DF o = qts(res.h, res.l - 2.f * r.l);
    return {sgn * o.h, sgn * o.l};
}
__device__ __forceinline__ DF df_red(DF a, unsigned off) {
    float oh = __shfl_down_sync(0xffffffffu, a.h, off);
    float ol = __shfl_down_sync(0xffffffffu, a.l, off);
    return df_add(a, {oh, ol});
}

// ===========================================================================
// Packed Kahan chain (all fma.rn.f32x2). Value = s - c.
// ===========================================================================
#define PK_ONE2  0x3F8000003F800000ull
#define PK_M1_2  0xBF800000BF800000ull
__device__ __forceinline__ u64 f2fma(u64 a, u64 b, u64 c) {
    u64 r; asm("fma.rn.f32x2 %0, %1, %2, %3;" : "=l"(r) : "l"(a), "l"(b), "l"(c)); return r;
}
__device__ __forceinline__ u64 f2neg(u64 a) { return a ^ 0x8000000080000000ull; }

__device__ __forceinline__ void cacc2k(u64& s2, u64& c2, u64 xh2, u64 xl2, u64 w2) {
    u64 p  = f2fma(xh2, w2, 0ull);
    u64 e  = f2fma(xh2, w2, f2neg(p));
    e      = f2fma(xl2, w2, e);
    u64 cm = f2fma(e, PK_M1_2, c2);
    u64 y  = f2fma(cm, PK_M1_2, p);
    u64 t  = f2fma(s2, PK_ONE2, y);
    u64 d  = f2fma(s2, PK_M1_2, t);
    c2     = f2fma(y, PK_M1_2, d);
    s2 = t;
}
__device__ __forceinline__ DF df_from2k(u64 s2, u64 c2) {
    c2 = f2neg(c2);
    float se = __uint_as_float((unsigned)s2), so = __uint_as_float((unsigned)(s2 >> 32));
    float ce = __uint_as_float((unsigned)c2), co = __uint_as_float((unsigned)(c2 >> 32));
    DF re = tsum(se, ce); re = qts(re.h, re.l);
    DF ro = tsum(so, co); ro = qts(ro.h, ro.l);
    return df_add(re, ro);
}
__device__ __forceinline__ u64 f_to_lo(float a) { return (u64)__float_as_uint(a); }

// Cluster helpers
__device__ __forceinline__ uint32_t smem_u32(const void* p) {
    uint32_t a;
    asm("{ .reg .u64 t; cvta.to.shared.u64 t, %1; cvt.u32.u64 %0, t; }" : "=r"(a) : "l"(p));
    return a;
}
__device__ __forceinline__ uint32_t my_rank() {
    uint32_t r; asm("mov.u32 %0, %%cluster_ctarank;" : "=r"(r)); return r;
}
__device__ __forceinline__ void st_cluster_b32(uint32_t saddr, uint32_t rank, uint32_t v) {
    uint32_t ra;
    asm volatile("mapa.shared::cluster.u32 %0, %1, %2;" : "=r"(ra) : "r"(saddr), "r"(rank));
    asm volatile("st.shared::cluster.b32 [%0], %1;" :: "r"(ra), "r"(v) : "memory");
}
#define CLUSTER_BAR() do { \
    asm volatile("barrier.cluster.arrive.aligned;" ::: "memory"); \
    asm volatile("barrier.cluster.wait.aligned;"   ::: "memory"); } while (0)

// ---------------------------------------------------------------------------
// Kernel 0: pack weights (unchanged)
// ---------------------------------------------------------------------------
__global__ void pack_kernel(const float* __restrict__ Wq,
                            const float* __restrict__ Wih,
                            const float* __restrict__ Whh,
                            const float* __restrict__ Wqc,
                            const float* __restrict__ Wkc,
                            const float* __restrict__ Wvc)
{
    const int stride = gridDim.x * blockDim.x;
    const int i0 = blockIdx.x * blockDim.x + threadIdx.x;
    for (int idx = i0; idx < M * 96 * GH; idx += stride) {
        const int col = idx % GH;
        const int r = idx / GH;
        const int v2 = r % 96, m = r / 96;
        const int r0 = 2 * v2, r1 = r0 + 1;
        const float e = (r0 < 64) ? Wih[(m * DV + r0) * GH + col] : Whh[(m * H + r0 - 64) * GH + col];
        const float o = (r1 < 64) ? Wih[(m * DV + r1) * GH + col] : Whh[(m * H + r1 - 64) * GH + col];
        g_W2[idx] = ((u64)__float_as_uint(o) << 32) | __float_as_uint(e);
    }
    for (int idx = i0; idx < M * 64 * DK; idx += stride) {
        const int dk = idx % DK;
        const int r = idx / DK;
        const int i2 = r % 64, m = r / 64;
        const float e = Wq[(m * H + 2 * i2) * DK + dk];
        const float o = Wq[(m * H + 2 * i2 + 1) * DK + dk];
        g_Wq2[idx] = ((u64)__float_as_uint(o) << 32) | __float_as_uint(e);
    }
    for (int idx = i0; idx < 2 * M * 64 * DC; idx += stride) {
        const int dc = idx % DC;
        const int r = idx / DC;
        const int k = r % 64;
        const int pm = (r / 64) % M;
        const int sel = r / (64 * M);
        const float* W = sel ? Wkc : Wqc;
        const float e = W[(pm * H + 2 * k) * DC + dc];
        const float o = W[(pm * H + 2 * k + 1) * DC + dc];
        g_Wqkc2[idx] = ((u64)__float_as_uint(o) << 32) | __float_as_uint(e);
    }
    for (int idx = i0; idx < M * 64 * H; idx += stride) {
        const int hv = idx % H;
        const int r = idx / H;
        const int i2 = r % 64, j = r / 64;
        const float e = Wvc[(j * H + 2 * i2) * H + hv];
        const float o = Wvc[(j * H + 2 * i2 + 1) * H + hv];
        g_Wvc2[idx] = ((u64)__float_as_uint(o) << 32) | __float_as_uint(e);
    }
}

// ---------------------------------------------------------------------------
// Kernel 1: modality projections (unchanged)
// ---------------------------------------------------------------------------
__global__ void __launch_bounds__(768) proj_kernel(
    const float* __restrict__ bert,
    const int*   __restrict__ umls_idx,
    const int*   __restrict__ pos_idx,
    const float* __restrict__ disg,
    const float* __restrict__ udisg,
    const float* __restrict__ umls_table,
    const float* __restrict__ pos_table,
    const float* __restrict__ Wk0, const float* __restrict__ Wv0,
    const float* __restrict__ Wk1, const float* __restrict__ Wv1,
    const float* __restrict__ Wk2, const float* __restrict__ Wv2,
    const float* __restrict__ Wk3, const float* __restrict__ Wv3,
    const float* __restrict__ Wk4, const float* __restrict__ Wv4)
{
    __shared__ float x[768 + 50 + 20 + 2 + 2];
    const int t = blockIdx.x;
    const int tid = threadIdx.x;

    x[tid] = bert[t * 768 + tid];
    {
        const long ui = (long)umls_idx[t];
        const int  pi = pos_idx[t];
        if (tid < 50) x[768 + tid] = umls_table[ui * 50 + tid];
        else if (tid < 70) x[818 + (tid - 50)] = pos_table[pi * 20 + (tid - 50)];
        else if (tid < 72) x[838 + (tid - 70)] = disg[t * 2 + (tid - 70)];
        else if (tid < 74) x[840 + (tid - 72)] = udisg[t * 2 + (tid - 72)];
    }
    __syncthreads();

    const float* Wks[5] = {Wk0, Wk1, Wk2, Wk3, Wk4};
    const float* Wvs[5] = {Wv0, Wv1, Wv2, Wv3, Wv4};
    const int dims[5] = {768, 50, 20, 2, 2};
    const int offs[5] = {0, 768, 818, 838, 840};

    const int o    = tid;
    const int mod  = o >> 7;
    const int half = (o >> 6) & 1;
    const int dk   = o & 63;
    float acc = 0.f;
    if (mod < 5) {
        const float* W  = half ? Wvs[mod] : Wks[mod];
        const float* xx = x + offs[mod];
        const int d = dims[mod];
        for (int i = 0; i < d; i++) acc += xx[i] * W[i * 64 + dk];
    }
    if (half == 0) g_keys[t * NELEM * DK + mod * DK + dk] = acc;
    else           g_vals[t * NELEM * DV + mod * DV + dk] = acc;
}

// ---------------------------------------------------------------------------
// Kernel 2: MI-RIM scan. 8-CTA cluster, deep K-split. 640 thr/CTA.
// CTA `rank` owns hidden slice [rank*16, rank*16+16) per module.
// ---------------------------------------------------------------------------
__global__ void __cluster_dims__(NCTA, 1, 1) __launch_bounds__(640, 1) scan_kernel(
    const float* __restrict__ blstm)
{
    __shared__ float  skt[NELEM * DK], svt[NELEM * DV];
    __shared__ float  sq_h[M * DK], sq_l[M * DK];
    __shared__ float  sat_h[M * 8], sat_l[M * 8];
    __shared__ float  sct_h[M * 8], sct_l[M * 8];
    __shared__ float  sinv_h[8], sinv_l[8];
    __shared__ __align__(16) float sinp_h[M * DV];
    __shared__ __align__(16) float sinp_l[M * DV];
    __shared__ float  sgate_h[KTOP * 64], sgate_l[KTOP * 64];  // 3 sel-modules x (4g x 16hh)
    __shared__ float  sqc_h[M * DC], sqc_l[M * DC];
    __shared__ float  skc_h[M * DC], skc_l[M * DC];
    __shared__ float  svc_h[M * HSL], svc_l[M * HSL];
    __shared__ float  sc_h[M * HSL], sc_l[M * HSL];
    __shared__ __align__(16) float h1_h[M * H];
    __shared__ __align__(16) float h1_l[M * H];
    __shared__ __align__(16) float hc_h[M * H];
    __shared__ __align__(16) float hc_l[M * H];
    __shared__ float  smask[8];
    __shared__ int    ssel[4];

    const int tid  = threadIdx.x;
    const uint32_t rank = my_rank();
    const int HB = rank * HSL;
    const uint32_t a1h = smem_u32(h1_h), a1l = smem_u32(h1_l);
    const uint32_t a2h = smem_u32(hc_h), a2l = smem_u32(hc_l);
    const uint32_t aqh = smem_u32(sq_h), aql = smem_u32(sq_l);
    const uint32_t aqch = smem_u32(sqc_h), aqcl = smem_u32(sqc_l);
    const uint32_t akch = smem_u32(skc_h), akcl = smem_u32(skc_l);

    hc_h[tid] = 0.f; hc_l[tid] = 0.f;
    if (tid < M * HSL) { sc_h[tid] = 0.f; sc_l[tid] = 0.f; }
    __syncthreads();
    CLUSTER_BAR();

    for (int t = 0; t < T; ++t) {
        // ---- int1: keys/vals load + q-proj PARTITIONED (40 outs/CTA, K16) ----
        if (tid < NELEM * DK) {
            skt[tid] = g_keys[t * NELEM * DK + tid];
            svt[tid] = g_vals[t * NELEM * DV + tid];
        }
        {
            const int out  = rank * 40 + (tid >> 4);   // global (qm,dk)
            const int part = tid & 15;                 // K-split-16 over 64 pairs
            const int qm = out >> 6, dk = out & 63;
            const u64* xh2 = (const u64*)(hc_h + qm * H);
            const u64* xl2 = (const u64*)(hc_l + qm * H);
            const u64* w2  = g_Wq2 + qm * 64 * DK + dk;
            const int k0 = part * 4;
            u64 wb[4];
            #pragma unroll
            for (int k = 0; k < 4; k++) wb[k] = w2[(k0 + k) * DK];
            u64 s2 = 0, c2 = 0;
            #pragma unroll
            for (int k = 0; k < 4; k++) cacc2k(s2, c2, xh2[k0 + k], xl2[k0 + k], wb[k]);
            DF r = df_from2k(s2, c2);
            r = df_red(r, 8); r = df_red(r, 4); r = df_red(r, 2); r = df_red(r, 1);
            if (part == 0) {
                #pragma unroll
                for (int rk = 0; rk < NCTA; rk++) {
                    st_cluster_b32(aqh + out * 4, rk, __float_as_uint(r.h));
                    st_cluster_b32(aql + out * 4, rk, __float_as_uint(r.l));
                }
            }
        }
        CLUSTER_BAR();

        // ---- int2: attention logits + FUSED exp ----
        {
            const int gout = tid >> 3;
            const int part = tid & 7;
            const int out = gout < 30 ? gout : 29;
            const int am = out / NELEM, j = out - am * NELEM;
            const float* kk = skt + j * DK;
            const float* qh = sq_h + am * DK;
            const float* ql = sq_l + am * DK;
            float s = 0.f, c = 0.f;
            const int i0 = part * 8;
            #pragma unroll
            for (int i = i0; i < i0 + 8; i++) cacc(s, c, qh[i], ql[i], kk[i]);
            DF r = qts(s, c);
            r = df_red(r, 4); r = df_red(r, 2); r = df_red(r, 1);
            if (part == 0 && gout < 30) {
                DF e = df_exp({r.h * 0.125f, r.l * 0.125f});
                sat_h[am * 8 + j] = e.h; sat_l[am * 8 + j] = e.l;
            }
        }
        __syncthreads();

        // ---- int3a: inv-sum (5 thr) + unnormalized inp dots ----
        if (tid >= 512 && tid < 512 + M) {
            const int m = tid - 512;
            DF sum = {sat_h[m * 8], sat_l[m * 8]};
            for (int j = 1; j < NELEM; j++) sum = df_add(sum, {sat_h[m * 8 + j], sat_l[m * 8 + j]});
            DF inv = df_recip(sum);
            sinv_h[m] = inv.h; sinv_l[m] = inv.l;
        }
        if (tid < M * DV) {
            const int em = tid >> 6, dv = tid & 63;
            float s = 0.f, c = 0.f;
            #pragma unroll
            for (int j = 0; j < NELEM; j++)
                cacc(s, c, sat_h[em * 8 + j], sat_l[em * 8 + j], svt[j * DV + dv]);
            DF r = qts(s, c);
            sinp_h[tid] = r.h; sinp_l[tid] = r.l;
        }
        __syncthreads();

        // ---- int3b: topk + normalize inp ----
        if (tid == 512) {
            DF nl[M]; bool used[M];
            for (int i = 0; i < M; i++) {
                nl[i] = df_mul({sat_h[i * 8 + (NELEM - 1)], sat_l[i * 8 + (NELEM - 1)]},
                               {sinv_h[i], sinv_l[i]});
                used[i] = false; smask[i] = 0.f;
            }
            for (int r = 0; r < KTOP; r++) {
                int best = -1; DF bv = {0.f, 0.f};
                for (int i = 0; i < M; i++)
                    if (!used[i] && (best < 0 || df_lt(nl[i], bv))) { bv = nl[i]; best = i; }
                used[best] = true; smask[best] = 1.f;
            }
            int k = 0;
            for (int i = 0; i < M; i++) if (used[i]) ssel[k++] = i;
        }
        if (tid < M * DV) {
            const int em = tid >> 6;
            DF r = df_mul({sinp_h[tid], sinp_l[tid]}, {sinv_h[em], sinv_l[em]});
            sinp_h[tid] = r.h; sinp_l[tid] = r.l;
        }
        __syncthreads();

        // ---- int6: gates (3 sel modules, 192 outs, K-split-2, chunked) ----
        if (tid < KTOP * 128) {
            const int out = tid >> 1;            // 0..191
            const int part = tid & 1;
            const int si = out >> 6;             // sel index 0..2
            const int r = out & 63;              // (gate, hl)
            const int gate = r >> 4;
            const int hl = r & 15;
            const int m = ssel[si];
            const int col = gate * H + HB + hl;
            const u64* w2 = g_W2 + (m * 96) * GH + col;
            u64 s2 = part ? 0ull : f_to_lo(blstm[m * GH + col]);
            u64 c2 = 0;
            const u64* ih2 = (const u64*)(sinp_h + m * DV);
            const u64* il2 = (const u64*)(sinp_l + m * DV);
            const u64* hh2 = (const u64*)(hc_h + m * H);
            const u64* hl2 = (const u64*)(hc_l + m * H);
            const int r0 = part * 48;            // 48 pairs per part
            #pragma unroll
            for (int ch = 0; ch < 3; ch++) {
                u64 wb[16];
                #pragma unroll
                for (int k = 0; k < 16; k++) wb[k] = w2[(r0 + ch * 16 + k) * GH];
                #pragma unroll
                for (int k = 0; k < 16; k++) {
                    const int row = r0 + ch * 16 + k;
                    u64 xh, xl;
                    if (row < 32) { xh = ih2[row]; xl = il2[row]; }
                    else          { xh = hh2[row - 32]; xl = hl2[row - 32]; }
                    cacc2k(s2, c2, xh, xl, wb[k]);
                }
            }
            DF g = df_from2k(s2, c2);
            g = df_red(g, 1);
            if (part == 0) {
                DF nlv = (gate == 2) ? df_tanh(g) : df_sigmoid(g);
                sgate_h[si * 64 + r] = nlv.h; sgate_l[si * 64 + r] = nlv.l;
            }
        }
        __syncthreads();

        // ---- int7: LSTM update on owned slice + broadcast h1 ----
        if (tid < M * HSL) {
            const int m = tid >> 4, hl = tid & 15;
            const bool on = smask[m] > 0.5f;
            const int hg = m * H + HB + hl;
            DF h1, c1;
            if (on) {
                int si = 0;
                #pragma unroll
                for (int k = 0; k < KTOP; k++) if (ssel[k] == m) si = k;
                const int base = si * 64 + hl;
                DF ig = {sgate_h[base],      sgate_l[base]};
                DF fg = {sgate_h[base + 16], sgate_l[base + 16]};
                DF gt = {sgate_h[base + 32], sgate_l[base + 32]};
                DF og = {sgate_h[base + 48], sgate_l[base + 48]};
                DF cold = {sc_h[tid], sc_l[tid]};
                c1 = df_add(df_mul(fg, cold), df_mul(ig, gt));
                h1 = df_mul(og, df_tanh(c1));
            } else {
                h1 = {hc_h[hg], hc_l[hg]};
                c1 = {sc_h[tid], sc_l[tid]};
            }
            sc_h[tid] = c1.h; sc_l[tid] = c1.l;
            #pragma unroll
            for (int rk = 0; rk < NCTA; rk++) {
                st_cluster_b32(a1h + hg * 4, rk, __float_as_uint(h1.h));
                st_cluster_b32(a1l + hg * 4, rk, __float_as_uint(h1.l));
            }
        }
        CLUSTER_BAR();

        // ---- int8a: qc/kc PARTITIONED (40 outs/CTA, K-split-16) ----
        {
            const int out  = rank * 40 + (tid >> 4);
            const int part = tid & 15;
            const int isK = out >= 160;
            const int o2 = isK ? out - 160 : out;
            const int pm = o2 >> 5, dc = o2 & 31;
            const u64* xh2 = (const u64*)(h1_h + pm * H);
            const u64* xl2 = (const u64*)(h1_l + pm * H);
            const u64* w2  = g_Wqkc2 + ((isK * 5 + pm) * 64) * DC + dc;
            const int k0 = part * 4;
            u64 wb[4];
            #pragma unroll
            for (int k = 0; k < 4; k++) wb[k] = w2[(k0 + k) * DC];
            u64 s2 = 0, c2 = 0;
            #pragma unroll
            for (int k = 0; k < 4; k++) cacc2k(s2, c2, xh2[k0 + k], xl2[k0 + k], wb[k]);
            DF r = df_from2k(s2, c2);
            r = df_red(r, 8); r = df_red(r, 4); r = df_red(r, 2); r = df_red(r, 1);
            if (part == 0) {
                const uint32_t ah = (isK ? akch : aqch) + o2 * 4;
                const uint32_t al = (isK ? akcl : aqcl) + o2 * 4;
                #pragma unroll
                for (int rk = 0; rk < NCTA; rk++) {
                    st_cluster_b32(ah, rk, __float_as_uint(r.h));
                    st_cluster_b32(al, rk, __float_as_uint(r.l));
                }
            }
        }
        // ---- int8b: vc owned slice (80 outs, K-split-8) ----
        {
            const int out = tid >> 3;                  // (j, hl), 0..79
            const int part = tid & 7;
            const int j = out >> 4, hl = out & 15;
            const u64* xh2 = (const u64*)(h1_h + j * H);
            const u64* xl2 = (const u64*)(h1_l + j * H);
            const u64* w2  = g_Wvc2 + j * 64 * H + HB + hl;
            const int k0 = part * 8;
            u64 wb[8];
            #pragma unroll
            for (int k = 0; k < 8; k++) wb[k] = w2[(k0 + k) * H];
            u64 s2 = 0, c2 = 0;
            #pragma unroll
            for (int k = 0; k < 8; k++) cacc2k(s2, c2, xh2[k0 + k], xl2[k0 + k], wb[k]);
            DF r = df_from2k(s2, c2);
            r = df_red(r, 4); r = df_red(r, 2); r = df_red(r, 1);
            if (part == 0) { svc_h[out] = r.h; svc_l[out] = r.l; }
        }
        CLUSTER_BAR();

        // ---- int9: cattn logits + FUSED exp ----
        {
            const int gout = tid >> 3;
            const int part = tid & 7;
            const int out = gout < 25 ? gout : 24;
            const int im = out / M, j = out - im * M;
            float s = 0.f, c = 0.f;
            const int i0 = part * 4;
            #pragma unroll
            for (int i = i0; i < i0 + 4; i++)
                cacc_df(s, c, {sqc_h[im * DC + i], sqc_l[im * DC + i]},
                              {skc_h[j * DC + i],  skc_l[j * DC + i]});
            DF r = qts(s, c);
            r = df_red(r, 4); r = df_red(r, 2); r = df_red(r, 1);
            if (part == 0 && gout < 25) {
                DF sc = df_mul(r, {0.17677669227123260f, 3.0254043e-9f});
                DF e = df_exp(sc);
                sct_h[im * 8 + j] = e.h; sct_l[im * 8 + j] = e.l;
            }
        }
        __syncthreads();

        // ---- int12: fused normalize + h2 + emit + broadcast ----
        if (tid < M * HSL) {
            const int m = tid >> 4, hl = tid & 15;
            DF sum = {sct_h[m * 8], sct_l[m * 8]};
            #pragma unroll
            for (int j = 1; j < M; j++) sum = df_add(sum, {sct_h[m * 8 + j], sct_l[m * 8 + j]});
            DF inv = df_recip(sum);
            float s = 0.f, c = 0.f;
            #pragma unroll
            for (int j = 0; j < M; j++)
                cacc_df(s, c, {sct_h[m * 8 + j], sct_l[m * 8 + j]},
                              {svc_h[j * HSL + hl], svc_l[j * HSL + hl]});
            DF dot = df_mul(qts(s, c), inv);
            const int hg = m * H + HB + hl;
            DF h1 = {h1_h[hg], h1_l[hg]};
            const bool on = smask[m] > 0.5f;
            DF h2 = on ? df_add(h1, dot) : h1;
            g_hidden[t * (M * H) + hg] = h2.h + h2.l;
            #pragma unroll
            for (int rk = 0; rk < NCTA; rk++) {
                st_cluster_b32(a2h + hg * 4, rk, __float_as_uint(h2.h));
                st_cluster_b32(a2l + hg * 4, rk, __float_as_uint(h2.l));
            }
        }
        CLUSTER_BAR();
    }
}

// ---------------------------------------------------------------------------
// Kernel 3: classifier (unchanged)
// ---------------------------------------------------------------------------
__global__ void cls_kernel(const float* __restrict__ Wcls,
                           const float* __restrict__ bcls,
                           float* __restrict__ out)
{
    const int warp = (blockIdx.x * blockDim.x + threadIdx.x) >> 5;
    const int lane = threadIdx.x & 31;
    if (warp >= T * 2) return;
    const int t = warp >> 1, c = warp & 1;
    const float* h = g_hidden + t * (M * H);
    float acc = 0.f;
    for (int i = lane; i < M * H; i += 32) acc += h[i] * Wcls[i * 2 + c];
    #pragma unroll
    for (int off = 16; off; off >>= 1) acc += __shfl_down_sync(0xffffffffu, acc, off);
    if (lane == 0) out[t * 2 + c] = acc + bcls[c];
}

// ---------------------------------------------------------------------------
extern "C" void kernel_launch(void* const* d_in, const int* in_sizes, int n_in,
                              void* d_out, int out_size)
{
    const float* bert  = (const float*)d_in[0];
    const int*   ui    = (const int*)  d_in[1];
    const int*   pi    = (const int*)  d_in[2];
    const float* disg  = (const float*)d_in[3];
    const float* udisg = (const float*)d_in[4];
    const float* utab  = (const float*)d_in[5];
    const float* ptab  = (const float*)d_in[6];
    const float* Wk0 = (const float*)d_in[7],  *Wv0 = (const float*)d_in[8];
    const float* Wk1 = (const float*)d_in[9],  *Wv1 = (const float*)d_in[10];
    const float* Wk2 = (const float*)d_in[11], *Wv2 = (const float*)d_in[12];
    const float* Wk3 = (const float*)d_in[13], *Wv3 = (const float*)d_in[14];
    const float* Wk4 = (const float*)d_in[15], *Wv4 = (const float*)d_in[16];
    const float* Wq    = (const float*)d_in[17];
    const float* Wih   = (const float*)d_in[18];
    const float* Whh   = (const float*)d_in[19];
    const float* blstm = (const float*)d_in[20];
    const float* Wqc   = (const float*)d_in[21];
    const float* Wkc   = (const float*)d_in[22];
    const float* Wvc   = (const float*)d_in[23];
    const float* Wcls  = (const float*)d_in[24];
    const float* bcls  = (const float*)d_in[25];

    pack_kernel<<<256, 256>>>(Wq, Wih, Whh, Wqc, Wkc, Wvc);
    proj_kernel<<<T, 768>>>(bert, ui, pi, disg, udisg, utab, ptab,
                            Wk0, Wv0, Wk1, Wv1, Wk2, Wv2, Wk3, Wv3, Wk4, Wv4);
    scan_kernel<<<NCTA, 640>>>(blstm);
    cls_kernel<<<32, 1024>>>(Wcls, bcls, (float*)d_out);
}

// round 10
// speedup vs baseline: 25.4511x; 1.0055x over previous
#include <cuda_runtime.h>
#include <math.h>
#include <stdint.h>

#define T 512
#define M 5
#define H 128
#define KTOP 3
#define DK 64
#define DV 64
#define DC 32
#define NELEM 6
#define GH 512
#define NCTA 8
#define HSL 16

typedef unsigned long long u64;

__device__ float g_keys[T * NELEM * DK];
__device__ float g_vals[T * NELEM * DV];
__device__ float g_hidden[T * M * H];
__device__ u64 g_W2[M * 96 * GH];
__device__ u64 g_Wq2[M * 64 * DK];
__device__ u64 g_Wqkc2[2 * M * 64 * DC];
__device__ u64 g_Wvc2[M * 64 * H];

// ===========================================================================
// Double-float primitives (proven R4-R9)
// ===========================================================================
struct DF { float h, l; };

__device__ __forceinline__ DF qts(float a, float b) {
    float s = a + b; float e = b - (s - a); return {s, e};
}
__device__ __forceinline__ DF tsum(float a, float b) {
    float s = a + b; float bb = s - a;
    float e = (a - (s - bb)) + (b - bb);
    return {s, e};
}
__device__ __forceinline__ DF tprod(float a, float b) {
    float p = a * b; float e = fmaf(a, b, -p); return {p, e};
}
__device__ __forceinline__ DF df_add(DF a, DF b) {
    DF s = tsum(a.h, b.h);
    return qts(s.h, s.l + (a.l + b.l));
}
__device__ __forceinline__ DF df_add_f(DF a, float b) {
    DF s = tsum(a.h, b);
    return qts(s.h, s.l + a.l);
}
__device__ __forceinline__ DF df_sub(DF a, DF b) { return df_add(a, {-b.h, -b.l}); }
__device__ __forceinline__ DF df_mul(DF a, DF b) {
    DF p = tprod(a.h, b.h);
    float l = p.l + (a.h * b.l + a.l * b.h);
    return qts(p.h, l);
}
__device__ __forceinline__ DF df_recip(DF d) {
    float y0 = __frcp_rn(d.h);
    DF p = tprod(d.h, y0);
    float e = (1.0f - p.h) - p.l;
    e = fmaf(-d.l, y0, e);
    return qts(y0, y0 * e);
}
__device__ __forceinline__ bool df_lt(DF a, DF b) {
    return (a.h < b.h) || (a.h == b.h && a.l < b.l);
}
__device__ __forceinline__ bool df_gt(DF a, DF b) { return df_lt(b, a); }
__device__ __forceinline__ void cacc(float& s, float& c, float xh, float xl, float w) {
    float p = xh * w;
    float e = fmaf(xh, w, -p);
    e = fmaf(xl, w, e);
    float t = s + p;
    float bb = t - s;
    c += ((s - (t - bb)) + (p - bb)) + e;
    s = t;
}
__device__ __forceinline__ void cacc_df(float& s, float& c, DF a, DF b) {
    float p = a.h * b.h;
    float e = fmaf(a.h, b.h, -p);
    e = fmaf(a.h, b.l, e);
    e = fmaf(a.l, b.h, e);
    float t = s + p;
    float bb = t - s;
    c += ((s - (t - bb)) + (p - bb)) + e;
    s = t;
}
__device__ __forceinline__ DF df_exp(DF x) {
    if (x.h > 30.f)  { x.h = 30.f;  x.l = 0.f; }
    if (x.h < -30.f) { x.h = -30.f; x.l = 0.f; }
    const float kf = rintf(x.h * 1.4426950408889634f);
    const float th = fmaf(-kf, 0.693145751953125f, x.h);
    const float tl = fmaf(-kf, 1.4286068203094172e-6f, x.l);
    float B = 2.7557319e-6f;
    B = fmaf(B, th, 2.4801587e-5f);
    B = fmaf(B, th, 1.9841270e-4f);
    B = fmaf(B, th, 1.3888889e-3f);
    B = fmaf(B, th, 8.3333333e-3f);
    B = fmaf(B, th, 4.1666667e-2f);
    DF t2 = tprod(th, th);
    DF t3 = tprod(t2.h, th);
    t3.l = fmaf(t2.l, th, t3.l);
    DF q = tprod(t3.h, 0.16666667f);
    q.l = fmaf(t3.h, -4.9670537e-9f, q.l);
    q.l = fmaf(t3.l, 0.16666667f, q.l);
    const float f4 = t2.h * t2.h * B;
    DF S = qts(1.0f, th);
    S = df_add(S, {t2.h * 0.5f, t2.l * 0.5f});
    S = df_add(S, q);
    S.l += f4;
    S.l = fmaf(S.h, tl, S.l);
    S = qts(S.h, S.l);
    const float sc = __int_as_float(((int)kf + 127) << 23);
    S.h *= sc; S.l *= sc;
    return S;
}
__device__ __forceinline__ DF df_sigmoid(DF x) {
    DF E = df_exp({-x.h, -x.l});
    return df_recip(df_add_f(E, 1.0f));
}
__device__ __forceinline__ DF df_tanh(DF x) {
    const float sgn = (x.h < 0.f) ? -1.f : 1.f;
    DF a = {sgn * x.h, sgn * x.l};
    DF E = df_exp({2.f * a.h, 2.f * a.l});
    DF r = df_recip(df_add_f(E, 1.0f));
    DF res = tsum(1.0f, -2.f * r.h);
    DF o = qts(res.h, res.l - 2.f * r.l);
    return {sgn * o.h, sgn * o.l};
}
__device__ __forceinline__ DF df_red(DF a, unsigned off) {
    float oh = __shfl_down_sync(0xffffffffu, a.h, off);
    float ol = __shfl_down_sync(0xffffffffu, a.l, off);
    return df_add(a, {oh, ol});
}

// ===========================================================================
// Packed Kahan chain (all fma.rn.f32x2). Value = s - c.
// ===========================================================================
#define PK_ONE2  0x3F8000003F800000ull
#define PK_M1_2  0xBF800000BF800000ull
__device__ __forceinline__ u64 f2fma(u64 a, u64 b, u64 c) {
    u64 r; asm("fma.rn.f32x2 %0, %1, %2, %3;" : "=l"(r) : "l"(a), "l"(b), "l"(c)); return r;
}
__device__ __forceinline__ u64 f2neg(u64 a) { return a ^ 0x8000000080000000ull; }

__device__ __forceinline__ void cacc2k(u64& s2, u64& c2, u64 xh2, u64 xl2, u64 w2) {
    u64 p  = f2fma(xh2, w2, 0ull);
    u64 e  = f2fma(xh2, w2, f2neg(p));
    e      = f2fma(xl2, w2, e);
    u64 cm = f2fma(e, PK_M1_2, c2);
    u64 y  = f2fma(cm, PK_M1_2, p);
    u64 t  = f2fma(s2, PK_ONE2, y);
    u64 d  = f2fma(s2, PK_M1_2, t);
    c2     = f2fma(y, PK_M1_2, d);
    s2 = t;
}
__device__ __forceinline__ DF df_from2k(u64 s2, u64 c2) {
    c2 = f2neg(c2);
    float se = __uint_as_float((unsigned)s2), so = __uint_as_float((unsigned)(s2 >> 32));
    float ce = __uint_as_float((unsigned)c2), co = __uint_as_float((unsigned)(c2 >> 32));
    DF re = tsum(se, ce); re = qts(re.h, re.l);
    DF ro = tsum(so, co); ro = qts(ro.h, ro.l);
    return df_add(re, ro);
}
__device__ __forceinline__ u64 f_to_lo(float a) { return (u64)__float_as_uint(a); }

// Cluster helpers
__device__ __forceinline__ uint32_t smem_u32(const void* p) {
    uint32_t a;
    asm("{ .reg .u64 t; cvta.to.shared.u64 t, %1; cvt.u32.u64 %0, t; }" : "=r"(a) : "l"(p));
    return a;
}
__device__ __forceinline__ uint32_t my_rank() {
    uint32_t r; asm("mov.u32 %0, %%cluster_ctarank;" : "=r"(r)); return r;
}
__device__ __forceinline__ void st_cluster_b32(uint32_t saddr, uint32_t rank, uint32_t v) {
    uint32_t ra;
    asm volatile("mapa.shared::cluster.u32 %0, %1, %2;" : "=r"(ra) : "r"(saddr), "r"(rank));
    asm volatile("st.shared::cluster.b32 [%0], %1;" :: "r"(ra), "r"(v) : "memory");
}
#define CLUSTER_BAR() do { \
    asm volatile("barrier.cluster.arrive.aligned;" ::: "memory"); \
    asm volatile("barrier.cluster.wait.aligned;"   ::: "memory"); } while (0)

// ---------------------------------------------------------------------------
// Kernel 0: pack weights (unchanged)
// ---------------------------------------------------------------------------
__global__ void pack_kernel(const float* __restrict__ Wq,
                            const float* __restrict__ Wih,
                            const float* __restrict__ Whh,
                            const float* __restrict__ Wqc,
                            const float* __restrict__ Wkc,
                            const float* __restrict__ Wvc)
{
    const int stride = gridDim.x * blockDim.x;
    const int i0 = blockIdx.x * blockDim.x + threadIdx.x;
    for (int idx = i0; idx < M * 96 * GH; idx += stride) {
        const int col = idx % GH;
        const int r = idx / GH;
        const int v2 = r % 96, m = r / 96;
        const int r0 = 2 * v2, r1 = r0 + 1;
        const float e = (r0 < 64) ? Wih[(m * DV + r0) * GH + col] : Whh[(m * H + r0 - 64) * GH + col];
        const float o = (r1 < 64) ? Wih[(m * DV + r1) * GH + col] : Whh[(m * H + r1 - 64) * GH + col];
        g_W2[idx] = ((u64)__float_as_uint(o) << 32) | __float_as_uint(e);
    }
    for (int idx = i0; idx < M * 64 * DK; idx += stride) {
        const int dk = idx % DK;
        const int r = idx / DK;
        const int i2 = r % 64, m = r / 64;
        const float e = Wq[(m * H + 2 * i2) * DK + dk];
        const float o = Wq[(m * H + 2 * i2 + 1) * DK + dk];
        g_Wq2[idx] = ((u64)__float_as_uint(o) << 32) | __float_as_uint(e);
    }
    for (int idx = i0; idx < 2 * M * 64 * DC; idx += stride) {
        const int dc = idx % DC;
        const int r = idx / DC;
        const int k = r % 64;
        const int pm = (r / 64) % M;
        const int sel = r / (64 * M);
        const float* W = sel ? Wkc : Wqc;
        const float e = W[(pm * H + 2 * k) * DC + dc];
        const float o = W[(pm * H + 2 * k + 1) * DC + dc];
        g_Wqkc2[idx] = ((u64)__float_as_uint(o) << 32) | __float_as_uint(e);
    }
    for (int idx = i0; idx < M * 64 * H; idx += stride) {
        const int hv = idx % H;
        const int r = idx / H;
        const int i2 = r % 64, j = r / 64;
        const float e = Wvc[(j * H + 2 * i2) * H + hv];
        const float o = Wvc[(j * H + 2 * i2 + 1) * H + hv];
        g_Wvc2[idx] = ((u64)__float_as_uint(o) << 32) | __float_as_uint(e);
    }
}

// ---------------------------------------------------------------------------
// Kernel 1: modality projections (unchanged)
// ---------------------------------------------------------------------------
__global__ void __launch_bounds__(768) proj_kernel(
    const float* __restrict__ bert,
    const int*   __restrict__ umls_idx,
    const int*   __restrict__ pos_idx,
    const float* __restrict__ disg,
    const float* __restrict__ udisg,
    const float* __restrict__ umls_table,
    const float* __restrict__ pos_table,
    const float* __restrict__ Wk0, const float* __restrict__ Wv0,
    const float* __restrict__ Wk1, const float* __restrict__ Wv1,
    const float* __restrict__ Wk2, const float* __restrict__ Wv2,
    const float* __restrict__ Wk3, const float* __restrict__ Wv3,
    const float* __restrict__ Wk4, const float* __restrict__ Wv4)
{
    __shared__ float x[768 + 50 + 20 + 2 + 2];
    const int t = blockIdx.x;
    const int tid = threadIdx.x;

    x[tid] = bert[t * 768 + tid];
    {
        const long ui = (long)umls_idx[t];
        const int  pi = pos_idx[t];
        if (tid < 50) x[768 + tid] = umls_table[ui * 50 + tid];
        else if (tid < 70) x[818 + (tid - 50)] = pos_table[pi * 20 + (tid - 50)];
        else if (tid < 72) x[838 + (tid - 70)] = disg[t * 2 + (tid - 70)];
        else if (tid < 74) x[840 + (tid - 72)] = udisg[t * 2 + (tid - 72)];
    }
    __syncthreads();

    const float* Wks[5] = {Wk0, Wk1, Wk2, Wk3, Wk4};
    const float* Wvs[5] = {Wv0, Wv1, Wv2, Wv3, Wv4};
    const int dims[5] = {768, 50, 20, 2, 2};
    const int offs[5] = {0, 768, 818, 838, 840};

    const int o    = tid;
    const int mod  = o >> 7;
    const int half = (o >> 6) & 1;
    const int dk   = o & 63;
    float acc = 0.f;
    if (mod < 5) {
        const float* W  = half ? Wvs[mod] : Wks[mod];
        const float* xx = x + offs[mod];
        const int d = dims[mod];
        for (int i = 0; i < d; i++) acc += xx[i] * W[i * 64 + dk];
    }
    if (half == 0) g_keys[t * NELEM * DK + mod * DK + dk] = acc;
    else           g_vals[t * NELEM * DV + mod * DV + dk] = acc;
}

// ---------------------------------------------------------------------------
// Kernel 2: MI-RIM scan. 8-CTA cluster, 2 cluster-bars/step. 640 thr/CTA.
// ---------------------------------------------------------------------------
__global__ void __cluster_dims__(NCTA, 1, 1) __launch_bounds__(640, 1) scan_kernel(
    const float* __restrict__ blstm)
{
    __shared__ float  skt[NELEM * DK], svt[NELEM * DV];
    __shared__ float  sq_h[M * DK], sq_l[M * DK];
    __shared__ float  sat_h[M * 8], sat_l[M * 8];
    __shared__ float  sct_h[M * 8], sct_l[M * 8];
    __shared__ __align__(16) float sinp_h[M * DV];
    __shared__ __align__(16) float sinp_l[M * DV];
    __shared__ float  sgate_h[KTOP * 64], sgate_l[KTOP * 64];
    __shared__ float  sqc_h[M * DC], sqc_l[M * DC];
    __shared__ float  skc_h[M * DC], skc_l[M * DC];
    __shared__ float  svc_h[M * HSL], svc_l[M * HSL];
    __shared__ float  sc_h[M * HSL], sc_l[M * HSL];
    __shared__ __align__(16) float h1_h[M * H];
    __shared__ __align__(16) float h1_l[M * H];
    __shared__ __align__(16) float hc_h[M * H];
    __shared__ __align__(16) float hc_l[M * H];
    __shared__ float  smask[8];
    __shared__ int    ssel[4];

    const int tid  = threadIdx.x;
    const uint32_t rank = my_rank();
    const int HB = rank * HSL;
    const uint32_t a1h = smem_u32(h1_h), a1l = smem_u32(h1_l);
    const uint32_t a2h = smem_u32(hc_h), a2l = smem_u32(hc_l);

    hc_h[tid] = 0.f; hc_l[tid] = 0.f;
    if (tid < M * HSL) { sc_h[tid] = 0.f; sc_l[tid] = 0.f; }
    __syncthreads();
    CLUSTER_BAR();

    for (int t = 0; t < T; ++t) {
        // ---- int1: kv load + q computed LOCALLY (redundant, K-split-2) ----
        if (tid < NELEM * DK) {
            skt[tid] = g_keys[t * NELEM * DK + tid];
            svt[tid] = g_vals[t * NELEM * DV + tid];
        }
        {
            const int out  = tid >> 1;            // 0..319 = (qm,dk)
            const int part = tid & 1;
            const int qm = out >> 6, dk = out & 63;
            const u64* xh2 = (const u64*)(hc_h + qm * H);
            const u64* xl2 = (const u64*)(hc_l + qm * H);
            const u64* w2  = g_Wq2 + qm * 64 * DK + dk;
            const int k0 = part * 32;
            u64 s2 = 0, c2 = 0;
            #pragma unroll 4
            for (int kk2 = 0; kk2 < 32; kk2 += 8) {
                u64 wb[8];
                #pragma unroll
                for (int k = 0; k < 8; k++) wb[k] = w2[(k0 + kk2 + k) * DK];
                #pragma unroll
                for (int k = 0; k < 8; k++)
                    cacc2k(s2, c2, xh2[k0 + kk2 + k], xl2[k0 + kk2 + k], wb[k]);
            }
            DF r = df_from2k(s2, c2);
            DF o = df_red(r, 1);
            if (part == 0) { sq_h[out] = o.h; sq_l[out] = o.l; }
        }
        __syncthreads();

        // ---- int2: attention logits + FUSED exp (shift-free softmax) ----
        {
            const int gout = tid >> 3;
            const int part = tid & 7;
            const int out = gout < 30 ? gout : 29;
            const int am = out / NELEM, j = out - am * NELEM;
            const float* kk = skt + j * DK;
            const float* qh = sq_h + am * DK;
            const float* ql = sq_l + am * DK;
            float s = 0.f, c = 0.f;
            const int i0 = part * 8;
            #pragma unroll
            for (int i = i0; i < i0 + 8; i++) cacc(s, c, qh[i], ql[i], kk[i]);
            DF r = qts(s, c);
            r = df_red(r, 4); r = df_red(r, 2); r = df_red(r, 1);
            if (part == 0 && gout < 30) {
                DF e = df_exp({r.h * 0.125f, r.l * 0.125f});
                sat_h[am * 8 + j] = e.h; sat_l[am * 8 + j] = e.l;
            }
        }
        __syncthreads();

        // ---- int3: inp dots + per-thread normalize  ||  warp16: topk ----
        // null logit == 0 exactly -> e_null == 1 -> null_attn[m] = 1/sum[m],
        // so top-3-smallest-null == top-3-LARGEST-sum (exact ordering, no div).
        if (tid < M * DV) {
            const int em = tid >> 6, dv = tid & 63;
            float s = 0.f, c = 0.f;
            #pragma unroll
            for (int j = 0; j < NELEM; j++)
                cacc(s, c, sat_h[em * 8 + j], sat_l[em * 8 + j], svt[j * DV + dv]);
            DF sum = {sat_h[em * 8], sat_l[em * 8]};
            #pragma unroll
            for (int j = 1; j < NELEM; j++) sum = df_add(sum, {sat_h[em * 8 + j], sat_l[em * 8 + j]});
            DF inv = df_recip(sum);
            DF r = df_mul(qts(s, c), inv);
            sinp_h[tid] = r.h; sinp_l[tid] = r.l;
        } else if (tid >= 512 && tid < 544) {
            const int lane = tid - 512;
            DF mysum = {0.f, 0.f};
            if (lane < M) {
                mysum = {sat_h[lane * 8], sat_l[lane * 8]};
                #pragma unroll
                for (int j = 1; j < NELEM; j++)
                    mysum = df_add(mysum, {sat_h[lane * 8 + j], sat_l[lane * 8 + j]});
            }
            // gather 5 sums to lane 0
            DF sums[M];
            #pragma unroll
            for (int i = 0; i < M; i++) {
                sums[i].h = __shfl_sync(0xffffffffu, mysum.h, i);
                sums[i].l = __shfl_sync(0xffffffffu, mysum.l, i);
            }
            if (lane == 0) {
                bool used[M];
                #pragma unroll
                for (int i = 0; i < M; i++) { used[i] = false; smask[i] = 0.f; }
                for (int r = 0; r < KTOP; r++) {
                    int best = -1; DF bv = {0.f, 0.f};
                    for (int i = 0; i < M; i++)
                        if (!used[i] && (best < 0 || df_gt(sums[i], bv))) { bv = sums[i]; best = i; }
                    used[best] = true; smask[best] = 1.f;
                }
                int k = 0;
                for (int i = 0; i < M; i++) if (used[i]) ssel[k++] = i;
            }
        }
        __syncthreads();

        // ---- int6: gates (3 sel modules, 192 outs, K-split-2, chunked) ----
        if (tid < KTOP * 128) {
            const int out = tid >> 1;
            const int part = tid & 1;
            const int si = out >> 6;
            const int r = out & 63;
            const int gate = r >> 4;
            const int hl = r & 15;
            const int m = ssel[si];
            const int col = gate * H + HB + hl;
            const u64* w2 = g_W2 + (m * 96) * GH + col;
            u64 s2 = part ? 0ull : f_to_lo(blstm[m * GH + col]);
            u64 c2 = 0;
            const u64* ih2 = (const u64*)(sinp_h + m * DV);
            const u64* il2 = (const u64*)(sinp_l + m * DV);
            const u64* hh2 = (const u64*)(hc_h + m * H);
            const u64* hl2 = (const u64*)(hc_l + m * H);
            const int r0 = part * 48;
            #pragma unroll
            for (int ch = 0; ch < 3; ch++) {
                u64 wb[16];
                #pragma unroll
                for (int k = 0; k < 16; k++) wb[k] = w2[(r0 + ch * 16 + k) * GH];
                #pragma unroll
                for (int k = 0; k < 16; k++) {
                    const int row = r0 + ch * 16 + k;
                    u64 xh, xl;
                    if (row < 32) { xh = ih2[row]; xl = il2[row]; }
                    else          { xh = hh2[row - 32]; xl = hl2[row - 32]; }
                    cacc2k(s2, c2, xh, xl, wb[k]);
                }
            }
            DF g = df_from2k(s2, c2);
            g = df_red(g, 1);
            if (part == 0) {
                DF nlv = (gate == 2) ? df_tanh(g) : df_sigmoid(g);
                sgate_h[si * 64 + r] = nlv.h; sgate_l[si * 64 + r] = nlv.l;
            }
        }
        __syncthreads();

        // ---- int7: LSTM update on owned slice + broadcast h1 ----
        if (tid < M * HSL) {
            const int m = tid >> 4, hl = tid & 15;
            const bool on = smask[m] > 0.5f;
            const int hg = m * H + HB + hl;
            DF h1, c1;
            if (on) {
                int si = 0;
                #pragma unroll
                for (int k = 0; k < KTOP; k++) if (ssel[k] == m) si = k;
                const int base = si * 64 + hl;
                DF ig = {sgate_h[base],      sgate_l[base]};
                DF fg = {sgate_h[base + 16], sgate_l[base + 16]};
                DF gt = {sgate_h[base + 32], sgate_l[base + 32]};
                DF og = {sgate_h[base + 48], sgate_l[base + 48]};
                DF cold = {sc_h[tid], sc_l[tid]};
                c1 = df_add(df_mul(fg, cold), df_mul(ig, gt));
                h1 = df_mul(og, df_tanh(c1));
            } else {
                h1 = {hc_h[hg], hc_l[hg]};
                c1 = {sc_h[tid], sc_l[tid]};
            }
            sc_h[tid] = c1.h; sc_l[tid] = c1.l;
            #pragma unroll
            for (int rk = 0; rk < NCTA; rk++) {
                st_cluster_b32(a1h + hg * 4, rk, __float_as_uint(h1.h));
                st_cluster_b32(a1l + hg * 4, rk, __float_as_uint(h1.l));
            }
        }
        CLUSTER_BAR();

        // ---- int8: qc/kc LOCAL (redundant, K-split-2) then vc owned ----
        {
            const int out  = tid >> 1;           // 0..319
            const int part = tid & 1;
            const int isK = out >= 160;
            const int o2 = isK ? out - 160 : out;
            const int pm = o2 >> 5, dc = o2 & 31;
            const u64* xh2 = (const u64*)(h1_h + pm * H);
            const u64* xl2 = (const u64*)(h1_l + pm * H);
            const u64* w2  = g_Wqkc2 + ((isK * 5 + pm) * 64) * DC + dc;
            const int k0 = part * 32;
            u64 s2 = 0, c2 = 0;
            #pragma unroll 4
            for (int kk2 = 0; kk2 < 32; kk2 += 8) {
                u64 wb[8];
                #pragma unroll
                for (int k = 0; k < 8; k++) wb[k] = w2[(k0 + kk2 + k) * DC];
                #pragma unroll
                for (int k = 0; k < 8; k++)
                    cacc2k(s2, c2, xh2[k0 + kk2 + k], xl2[k0 + kk2 + k], wb[k]);
            }
            DF r = df_from2k(s2, c2);
            DF o = df_red(r, 1);
            if (part == 0) {
                if (isK) { skc_h[o2] = o.h; skc_l[o2] = o.l; }
                else     { sqc_h[o2] = o.h; sqc_l[o2] = o.l; }
            }
        }
        {
            const int out = tid >> 3;            // (j, hl), 0..79
            const int part = tid & 7;
            const int j = out >> 4, hl = out & 15;
            const u64* xh2 = (const u64*)(h1_h + j * H);
            const u64* xl2 = (const u64*)(h1_l + j * H);
            const u64* w2  = g_Wvc2 + j * 64 * H + HB + hl;
            const int k0 = part * 8;
            u64 wb[8];
            #pragma unroll
            for (int k = 0; k < 8; k++) wb[k] = w2[(k0 + k) * H];
            u64 s2 = 0, c2 = 0;
            #pragma unroll
            for (int k = 0; k < 8; k++) cacc2k(s2, c2, xh2[k0 + k], xl2[k0 + k], wb[k]);
            DF r = df_from2k(s2, c2);
            r = df_red(r, 4); r = df_red(r, 2); r = df_red(r, 1);
            if (part == 0) { svc_h[out] = r.h; svc_l[out] = r.l; }
        }
        __syncthreads();

        // ---- int9: cattn logits + FUSED exp ----
        {
            const int gout = tid >> 3;
            const int part = tid & 7;
            const int out = gout < 25 ? gout : 24;
            const int im = out / M, j = out - im * M;
            float s = 0.f, c = 0.f;
            const int i0 = part * 4;
            #pragma unroll
            for (int i = i0; i < i0 + 4; i++)
                cacc_df(s, c, {sqc_h[im * DC + i], sqc_l[im * DC + i]},
                              {skc_h[j * DC + i],  skc_l[j * DC + i]});
            DF r = qts(s, c);
            r = df_red(r, 4); r = df_red(r, 2); r = df_red(r, 1);
            if (part == 0 && gout < 25) {
                DF sc = df_mul(r, {0.17677669227123260f, 3.0254043e-9f});
                DF e = df_exp(sc);
                sct_h[im * 8 + j] = e.h; sct_l[im * 8 + j] = e.l;
            }
        }
        __syncthreads();

        // ---- int12: fused normalize + h2 + emit + broadcast carry ----
        if (tid < M * HSL) {
            const int m = tid >> 4, hl = tid & 15;
            DF sum = {sct_h[m * 8], sct_l[m * 8]};
            #pragma unroll
            for (int j = 1; j < M; j++) sum = df_add(sum, {sct_h[m * 8 + j], sct_l[m * 8 + j]});
            DF inv = df_recip(sum);
            float s = 0.f, c = 0.f;
            #pragma unroll
            for (int j = 0; j < M; j++)
                cacc_df(s, c, {sct_h[m * 8 + j], sct_l[m * 8 + j]},
                              {svc_h[j * HSL + hl], svc_l[j * HSL + hl]});
            DF dot = df_mul(qts(s, c), inv);
            const int hg = m * H + HB + hl;
            DF h1 = {h1_h[hg], h1_l[hg]};
            const bool on = smask[m] > 0.5f;
            DF h2 = on ? df_add(h1, dot) : h1;
            g_hidden[t * (M * H) + hg] = h2.h + h2.l;
            #pragma unroll
            for (int rk = 0; rk < NCTA; rk++) {
                st_cluster_b32(a2h + hg * 4, rk, __float_as_uint(h2.h));
                st_cluster_b32(a2l + hg * 4, rk, __float_as_uint(h2.l));
            }
        }
        CLUSTER_BAR();
    }
}

// ---------------------------------------------------------------------------
// Kernel 3: classifier (unchanged)
// ---------------------------------------------------------------------------
__global__ void cls_kernel(const float* __restrict__ Wcls,
                           const float* __restrict__ bcls,
                           float* __restrict__ out)
{
    const int warp = (blockIdx.x * blockDim.x + threadIdx.x) >> 5;
    const int lane = threadIdx.x & 31;
    if (warp >= T * 2) return;
    const int t = warp >> 1, c = warp & 1;
    const float* h = g_hidden + t * (M * H);
    float acc = 0.f;
    for (int i = lane; i < M * H; i += 32) acc += h[i] * Wcls[i * 2 + c];
    #pragma unroll
    for (int off = 16; off; off >>= 1) acc += __shfl_down_sync(0xffffffffu, acc, off);
    if (lane == 0) out[t * 2 + c] = acc + bcls[c];
}

// ---------------------------------------------------------------------------
extern "C" void kernel_launch(void* const* d_in, const int* in_sizes, int n_in,
                              void* d_out, int out_size)
{
    const float* bert  = (const float*)d_in[0];
    const int*   ui    = (const int*)  d_in[1];
    const int*   pi    = (const int*)  d_in[2];
    const float* disg  = (const float*)d_in[3];
    const float* udisg = (const float*)d_in[4];
    const float* utab  = (const float*)d_in[5];
    const float* ptab  = (const float*)d_in[6];
    const float* Wk0 = (const float*)d_in[7],  *Wv0 = (const float*)d_in[8];
    const float* Wk1 = (const float*)d_in[9],  *Wv1 = (const float*)d_in[10];
    const float* Wk2 = (const float*)d_in[11], *Wv2 = (const float*)d_in[12];
    const float* Wk3 = (const float*)d_in[13], *Wv3 = (const float*)d_in[14];
    const float* Wk4 = (const float*)d_in[15], *Wv4 = (const float*)d_in[16];
    const float* Wq    = (const float*)d_in[17];
    const float* Wih   = (const float*)d_in[18];
    const float* Whh   = (const float*)d_in[19];
    const float* blstm = (const float*)d_in[20];
    const float* Wqc   = (const float*)d_in[21];
    const float* Wkc   = (const float*)d_in[22];
    const float* Wvc   = (const float*)d_in[23];
    const float* Wcls  = (const float*)d_in[24];
    const float* bcls  = (const float*)d_in[25];

    pack_kernel<<<256, 256>>>(Wq, Wih, Whh, Wqc, Wkc, Wvc);
    proj_kernel<<<T, 768>>>(bert, ui, pi, disg, udisg, utab, ptab,
                            Wk0, Wv0, Wk1, Wv1, Wk2, Wv2, Wk3, Wv3, Wk4, Wv4);
    scan_kernel<<<NCTA, 640>>>(blstm);
    cls_kernel<<<32, 1024>>>(Wcls, bcls, (float*)d_out);
}